// round 1
// baseline (speedup 1.0000x reference)
#include <cuda_runtime.h>
#include <cstdint>

#define BB 2
#define LL 2048
#define DD 1024
#define HH 16
#define DKK 64

// Scratch (allowed: __device__ globals, no runtime alloc)
__device__ float g_qh[(size_t)BB * LL * DD];
__device__ float g_kh[(size_t)BB * LL * DD];
__device__ float g_vh[(size_t)BB * LL * DD];
__device__ float g_ctx[(size_t)BB * LL * DD];

// ---------------------------------------------------------------------------
// GEMM: C[M,N] = A[M,K] * W[K,N] + bias[N].  BM=BN=128, BK=8, 256 threads,
// each thread 8x8 micro-tile. M%128==0, N%128==0, K%8==0 assumed.
// ---------------------------------------------------------------------------
__global__ __launch_bounds__(256) void gemm_bias_kernel(
    const float* __restrict__ A, const float* __restrict__ W,
    const float* __restrict__ bias, float* __restrict__ C,
    int M, int N, int K)
{
    __shared__ float As[8][128];
    __shared__ float Bs[8][128];

    int tid = threadIdx.x;
    int tx = tid & 15;        // 0..15 -> 8 cols each
    int ty = tid >> 4;        // 0..15 -> 8 rows each
    int m0 = blockIdx.y * 128;
    int n0 = blockIdx.x * 128;

    int a_row  = tid >> 1;          // 0..127
    int a_col4 = (tid & 1) * 4;     // 0 or 4
    int b_row  = tid >> 5;          // 0..7
    int b_col4 = (tid & 31) * 4;    // 0..124

    const float* Aptr = A + (size_t)(m0 + a_row) * K;

    float acc[8][8];
    #pragma unroll
    for (int i = 0; i < 8; ++i)
        #pragma unroll
        for (int j = 0; j < 8; ++j) acc[i][j] = 0.f;

    for (int k0 = 0; k0 < K; k0 += 8) {
        float4 av = *(const float4*)(Aptr + k0 + a_col4);
        As[a_col4 + 0][a_row] = av.x;
        As[a_col4 + 1][a_row] = av.y;
        As[a_col4 + 2][a_row] = av.z;
        As[a_col4 + 3][a_row] = av.w;
        float4 bv = *(const float4*)(W + (size_t)(k0 + b_row) * N + n0 + b_col4);
        *(float4*)&Bs[b_row][b_col4] = bv;
        __syncthreads();

        #pragma unroll
        for (int kk = 0; kk < 8; ++kk) {
            float a[8], b[8];
            #pragma unroll
            for (int i = 0; i < 8; ++i) a[i] = As[kk][ty * 8 + i];
            #pragma unroll
            for (int j = 0; j < 8; ++j) b[j] = Bs[kk][tx * 8 + j];
            #pragma unroll
            for (int i = 0; i < 8; ++i)
                #pragma unroll
                for (int j = 0; j < 8; ++j)
                    acc[i][j] += a[i] * b[j];
        }
        __syncthreads();
    }

    #pragma unroll
    for (int i = 0; i < 8; ++i) {
        int row = m0 + ty * 8 + i;
        #pragma unroll
        for (int j4 = 0; j4 < 8; j4 += 4) {
            int col = n0 + tx * 8 + j4;
            float4 o;
            o.x = acc[i][j4 + 0] + bias[col + 0];
            o.y = acc[i][j4 + 1] + bias[col + 1];
            o.z = acc[i][j4 + 2] + bias[col + 2];
            o.w = acc[i][j4 + 3] + bias[col + 3];
            *(float4*)&C[(size_t)row * N + col] = o;
        }
    }
}

// ---------------------------------------------------------------------------
// Scores: for pair p=(b,h): S[q,k] = (Qh[q,:]·Kh[k,:]) / D, masked -> attn
// region of d_out, layout [(h*B+b), L, L]. 128x128 tile, K-dim = 64 (BK=8).
// ---------------------------------------------------------------------------
__global__ __launch_bounds__(256) void scores_kernel(
    const float* __restrict__ qh, const float* __restrict__ kh,
    const int* __restrict__ mask, float* __restrict__ attn)
{
    __shared__ float Qs[8][128];
    __shared__ float Ks[8][128];

    int tid = threadIdx.x;
    int tx = tid & 15;
    int ty = tid >> 4;
    int p = blockIdx.z;
    int b = p / HH;
    int h = p % HH;
    int q0 = blockIdx.y * 128;
    int k0 = blockIdx.x * 128;

    const float* Qb = qh + ((size_t)b * LL + q0) * DD + h * DKK;
    const float* Kb = kh + ((size_t)b * LL + k0) * DD + h * DKK;

    int l_row = tid >> 1;
    int l_col = (tid & 1) * 4;

    float acc[8][8];
    #pragma unroll
    for (int i = 0; i < 8; ++i)
        #pragma unroll
        for (int j = 0; j < 8; ++j) acc[i][j] = 0.f;

    for (int d0 = 0; d0 < DKK; d0 += 8) {
        float4 qv = *(const float4*)(Qb + (size_t)l_row * DD + d0 + l_col);
        Qs[l_col + 0][l_row] = qv.x;
        Qs[l_col + 1][l_row] = qv.y;
        Qs[l_col + 2][l_row] = qv.z;
        Qs[l_col + 3][l_row] = qv.w;
        float4 kv = *(const float4*)(Kb + (size_t)l_row * DD + d0 + l_col);
        Ks[l_col + 0][l_row] = kv.x;
        Ks[l_col + 1][l_row] = kv.y;
        Ks[l_col + 2][l_row] = kv.z;
        Ks[l_col + 3][l_row] = kv.w;
        __syncthreads();

        #pragma unroll
        for (int kk = 0; kk < 8; ++kk) {
            float a[8], c[8];
            #pragma unroll
            for (int i = 0; i < 8; ++i) a[i] = Qs[kk][ty * 8 + i];
            #pragma unroll
            for (int j = 0; j < 8; ++j) c[j] = Ks[kk][tx * 8 + j];
            #pragma unroll
            for (int i = 0; i < 8; ++i)
                #pragma unroll
                for (int j = 0; j < 8; ++j)
                    acc[i][j] += a[i] * c[j];
        }
        __syncthreads();
    }

    const float scale = 1.0f / (float)DD;
    size_t obase = (size_t)(h * BB + b) * LL * LL;

    #pragma unroll
    for (int i = 0; i < 8; ++i) {
        int q = q0 + ty * 8 + i;
        const int* mrow = mask + ((size_t)b * LL + q) * LL + k0 + tx * 8;
        float* orow = attn + obase + (size_t)q * LL + k0 + tx * 8;
        #pragma unroll
        for (int j4 = 0; j4 < 8; j4 += 4) {
            int4 m = *(const int4*)(mrow + j4);
            float4 o;
            o.x = m.x ? acc[i][j4 + 0] * scale : -1e9f;
            o.y = m.y ? acc[i][j4 + 1] * scale : -1e9f;
            o.z = m.z ? acc[i][j4 + 2] * scale : -1e9f;
            o.w = m.w ? acc[i][j4 + 3] * scale : -1e9f;
            *(float4*)(orow + j4) = o;
        }
    }
}

// ---------------------------------------------------------------------------
// Row softmax in place. One block (256 threads) per row of 2048.
// ---------------------------------------------------------------------------
__global__ __launch_bounds__(256) void softmax_kernel(float* __restrict__ attn)
{
    __shared__ float red[256];
    float* row = attn + (size_t)blockIdx.x * LL;
    int tid = threadIdx.x;

    float4 v0 = *(float4*)(row + tid * 8);
    float4 v1 = *(float4*)(row + tid * 8 + 4);

    float m = fmaxf(fmaxf(fmaxf(v0.x, v0.y), fmaxf(v0.z, v0.w)),
                    fmaxf(fmaxf(v1.x, v1.y), fmaxf(v1.z, v1.w)));
    red[tid] = m;
    __syncthreads();
    for (int s = 128; s > 0; s >>= 1) {
        if (tid < s) red[tid] = fmaxf(red[tid], red[tid + s]);
        __syncthreads();
    }
    m = red[0];
    __syncthreads();

    v0.x = expf(v0.x - m); v0.y = expf(v0.y - m);
    v0.z = expf(v0.z - m); v0.w = expf(v0.w - m);
    v1.x = expf(v1.x - m); v1.y = expf(v1.y - m);
    v1.z = expf(v1.z - m); v1.w = expf(v1.w - m);

    float s8 = (v0.x + v0.y + v0.z + v0.w) + (v1.x + v1.y + v1.z + v1.w);
    red[tid] = s8;
    __syncthreads();
    for (int s = 128; s > 0; s >>= 1) {
        if (tid < s) red[tid] += red[tid + s];
        __syncthreads();
    }
    float inv = 1.0f / red[0];

    v0.x *= inv; v0.y *= inv; v0.z *= inv; v0.w *= inv;
    v1.x *= inv; v1.y *= inv; v1.z *= inv; v1.w *= inv;
    *(float4*)(row + tid * 8) = v0;
    *(float4*)(row + tid * 8 + 4) = v1;
}

// ---------------------------------------------------------------------------
// AV: per pair p=(b,h): C[2048,64] = P[2048,2048] * Vh[2048,64].
// BM=128, BN=64, BK=16. 256 threads, each 8x4.
// ---------------------------------------------------------------------------
__global__ __launch_bounds__(256) void av_kernel(
    const float* __restrict__ attn, const float* __restrict__ vh,
    float* __restrict__ ctx)
{
    __shared__ float Ps[16][128];
    __shared__ float Vs[16][64];

    int tid = threadIdx.x;
    int tx = tid & 15;   // 4 cols each
    int ty = tid >> 4;   // 8 rows each
    int p = blockIdx.y;
    int b = p / HH;
    int h = p % HH;
    int m0 = blockIdx.x * 128;

    const float* Pb = attn + (size_t)(h * BB + b) * LL * LL + (size_t)m0 * LL;
    const float* Vb = vh + (size_t)b * LL * DD + h * DKK;

    int a_row  = tid >> 1;
    int a_col  = (tid & 1) * 4;
    int b_row  = tid >> 4;         // 0..15
    int b_col4 = (tid & 15) * 4;   // 0..60

    float acc[8][4];
    #pragma unroll
    for (int i = 0; i < 8; ++i)
        #pragma unroll
        for (int j = 0; j < 4; ++j) acc[i][j] = 0.f;

    for (int k0 = 0; k0 < LL; k0 += 16) {
        float4 p0 = *(const float4*)(Pb + (size_t)a_row * LL + k0 + a_col);
        float4 p1 = *(const float4*)(Pb + (size_t)a_row * LL + k0 + a_col + 8);
        Ps[a_col + 0][a_row] = p0.x;
        Ps[a_col + 1][a_row] = p0.y;
        Ps[a_col + 2][a_row] = p0.z;
        Ps[a_col + 3][a_row] = p0.w;
        Ps[a_col + 8][a_row] = p1.x;
        Ps[a_col + 9][a_row] = p1.y;
        Ps[a_col + 10][a_row] = p1.z;
        Ps[a_col + 11][a_row] = p1.w;
        float4 vv = *(const float4*)(Vb + (size_t)(k0 + b_row) * DD + b_col4);
        *(float4*)&Vs[b_row][b_col4] = vv;
        __syncthreads();

        #pragma unroll
        for (int kk = 0; kk < 16; ++kk) {
            float a[8], c[4];
            #pragma unroll
            for (int i = 0; i < 8; ++i) a[i] = Ps[kk][ty * 8 + i];
            #pragma unroll
            for (int j = 0; j < 4; ++j) c[j] = Vs[kk][tx * 4 + j];
            #pragma unroll
            for (int i = 0; i < 8; ++i)
                #pragma unroll
                for (int j = 0; j < 4; ++j)
                    acc[i][j] += a[i] * c[j];
        }
        __syncthreads();
    }

    #pragma unroll
    for (int i = 0; i < 8; ++i) {
        int q = m0 + ty * 8 + i;
        float4 o;
        o.x = acc[i][0]; o.y = acc[i][1]; o.z = acc[i][2]; o.w = acc[i][3];
        *(float4*)&ctx[((size_t)b * LL + q) * DD + h * DKK + tx * 4] = o;
    }
}

// ---------------------------------------------------------------------------
extern "C" void kernel_launch(void* const* d_in, const int* in_sizes, int n_in,
                              void* d_out, int out_size)
{
    const float* q    = (const float*)d_in[0];
    const float* k    = (const float*)d_in[1];
    const float* v    = (const float*)d_in[2];
    const int*   mask = (const int*)d_in[3];
    const float* Wq   = (const float*)d_in[4];
    const float* bq   = (const float*)d_in[5];
    const float* Wk   = (const float*)d_in[6];
    const float* bk   = (const float*)d_in[7];
    const float* Wv   = (const float*)d_in[8];
    const float* bv   = (const float*)d_in[9];
    const float* Wo   = (const float*)d_in[10];
    const float* bo   = (const float*)d_in[11];

    float* out  = (float*)d_out;
    float* attn = out + (size_t)BB * LL * DD;

    float *qh, *kh, *vh, *ctx;
    cudaGetSymbolAddress((void**)&qh, g_qh);
    cudaGetSymbolAddress((void**)&kh, g_kh);
    cudaGetSymbolAddress((void**)&vh, g_vh);
    cudaGetSymbolAddress((void**)&ctx, g_ctx);

    const int M = BB * LL;  // 4096
    dim3 gproj(DD / 128, M / 128);  // (8, 32)

    gemm_bias_kernel<<<gproj, 256>>>(q, Wq, bq, qh, M, DD, DD);
    gemm_bias_kernel<<<gproj, 256>>>(k, Wk, bk, kh, M, DD, DD);
    gemm_bias_kernel<<<gproj, 256>>>(v, Wv, bv, vh, M, DD, DD);

    dim3 gsc(LL / 128, LL / 128, BB * HH);  // (16,16,32)
    scores_kernel<<<gsc, 256>>>(qh, kh, mask, attn);

    softmax_kernel<<<BB * HH * LL, 256>>>(attn);  // 65536 rows

    dim3 gav(LL / 128, BB * HH);  // (16, 32)
    av_kernel<<<gav, 256>>>(attn, vh, ctx);

    gemm_bias_kernel<<<gproj, 256>>>(ctx, Wo, bo, out, M, DD, DD);
}

// round 3
// speedup vs baseline: 1.1637x; 1.1637x over previous
#include <cuda_runtime.h>
#include <cstdint>

#define BB 2
#define LL 2048
#define DD 1024
#define HH 16
#define DKK 64
#define NP (BB*HH)

// Scratch (__device__ globals — no runtime allocation)
__device__ float g_qh[(size_t)BB * LL * DD];
__device__ float g_kh[(size_t)BB * LL * DD];
__device__ float g_vh[(size_t)BB * LL * DD];
__device__ float g_ctx[(size_t)BB * LL * DD];
__device__ float g_rowsum[(size_t)NP * LL];

// ---- packed fp32x2 helpers (Blackwell FFMA2 via PTX) ----------------------
__device__ __forceinline__ unsigned long long pack2(float x, float y) {
    unsigned long long r;
    asm("mov.b64 %0,{%1,%2};" : "=l"(r) : "f"(x), "f"(y));
    return r;
}
__device__ __forceinline__ void unpack2(unsigned long long p, float& x, float& y) {
    asm("mov.b64 {%0,%1},%2;" : "=f"(x), "=f"(y) : "l"(p));
}
__device__ __forceinline__ void ffma2(unsigned long long& d,
                                      unsigned long long a, unsigned long long b) {
    asm("fma.rn.f32x2 %0,%1,%2,%0;" : "+l"(d) : "l"(a), "l"(b));
}

// ---------------------------------------------------------------------------
__global__ void zero_kernel(float* p, int n) {
    int i = blockIdx.x * blockDim.x + threadIdx.x;
    if (i < n) p[i] = 0.f;
}

// ---------------------------------------------------------------------------
// GEMM: C[M,N] = A[M,K]*W[K,N] + bias. BM=BN=128, BK=16, double-buffered,
// 256 threads, 8x8 per thread via FFMA2 (i-packed pairs).
// ---------------------------------------------------------------------------
__global__ __launch_bounds__(256) void gemm_bias_kernel(
    const float* __restrict__ A, const float* __restrict__ W,
    const float* __restrict__ bias, float* __restrict__ C,
    int M, int N, int K)
{
    __shared__ float As[2][16][128];
    __shared__ float Bs[2][16][128];

    int tid = threadIdx.x;
    int tx = tid & 15;
    int ty = tid >> 4;
    int m0 = blockIdx.y * 128;
    int n0 = blockIdx.x * 128;

    int a_row = tid >> 1;
    int a_c8  = (tid & 1) * 8;
    int b_row = tid >> 4;
    int b_c8  = (tid & 15) * 8;

    unsigned long long acc2[4][8];
    #pragma unroll
    for (int i = 0; i < 4; ++i)
        #pragma unroll
        for (int j = 0; j < 8; ++j) acc2[i][j] = 0ull;

    float4 ra0, ra1, rb0, rb1;

    auto load_g = [&](int t) {
        int k0 = t * 16;
        const float* Ap = A + (size_t)(m0 + a_row) * K + k0 + a_c8;
        ra0 = *(const float4*)Ap;
        ra1 = *(const float4*)(Ap + 4);
        const float* Bp = W + (size_t)(k0 + b_row) * N + n0 + b_c8;
        rb0 = *(const float4*)Bp;
        rb1 = *(const float4*)(Bp + 4);
    };
    auto store_s = [&](int buf) {
        As[buf][a_c8 + 0][a_row] = ra0.x;
        As[buf][a_c8 + 1][a_row] = ra0.y;
        As[buf][a_c8 + 2][a_row] = ra0.z;
        As[buf][a_c8 + 3][a_row] = ra0.w;
        As[buf][a_c8 + 4][a_row] = ra1.x;
        As[buf][a_c8 + 5][a_row] = ra1.y;
        As[buf][a_c8 + 6][a_row] = ra1.z;
        As[buf][a_c8 + 7][a_row] = ra1.w;
        *(float4*)&Bs[buf][b_row][b_c8]     = rb0;
        *(float4*)&Bs[buf][b_row][b_c8 + 4] = rb1;
    };

    int NT = K / 16;
    load_g(0);
    store_s(0);

    for (int t = 0; t < NT; ++t) {
        __syncthreads();
        int cur = t & 1;
        if (t + 1 < NT) load_g(t + 1);

        #pragma unroll
        for (int kk = 0; kk < 16; ++kk) {
            const unsigned long long* ap =
                (const unsigned long long*)&As[cur][kk][ty * 8];
            unsigned long long a2[4] = {ap[0], ap[1], ap[2], ap[3]};
            const float4* bp = (const float4*)&Bs[cur][kk][tx * 8];
            float4 bv0 = bp[0], bv1 = bp[1];
            unsigned long long b2[8];
            b2[0] = pack2(bv0.x, bv0.x);
            b2[1] = pack2(bv0.y, bv0.y);
            b2[2] = pack2(bv0.z, bv0.z);
            b2[3] = pack2(bv0.w, bv0.w);
            b2[4] = pack2(bv1.x, bv1.x);
            b2[5] = pack2(bv1.y, bv1.y);
            b2[6] = pack2(bv1.z, bv1.z);
            b2[7] = pack2(bv1.w, bv1.w);
            #pragma unroll
            for (int ip = 0; ip < 4; ++ip)
                #pragma unroll
                for (int j = 0; j < 8; ++j)
                    ffma2(acc2[ip][j], a2[ip], b2[j]);
        }
        if (t + 1 < NT) store_s((t + 1) & 1);
    }

    float bb[8];
    {
        const float4* bp = (const float4*)(bias + n0 + tx * 8);
        float4 v0 = bp[0], v1 = bp[1];
        bb[0] = v0.x; bb[1] = v0.y; bb[2] = v0.z; bb[3] = v0.w;
        bb[4] = v1.x; bb[5] = v1.y; bb[6] = v1.z; bb[7] = v1.w;
    }
    #pragma unroll
    for (int ip = 0; ip < 4; ++ip) {
        float r0[8], r1[8];
        #pragma unroll
        for (int j = 0; j < 8; ++j) unpack2(acc2[ip][j], r0[j], r1[j]);
        int row0 = m0 + ty * 8 + 2 * ip;
        float* c0 = C + (size_t)row0 * N + n0 + tx * 8;
        float* c1 = c0 + N;
        float4 o;
        o.x = r0[0] + bb[0]; o.y = r0[1] + bb[1];
        o.z = r0[2] + bb[2]; o.w = r0[3] + bb[3];
        *(float4*)c0 = o;
        o.x = r0[4] + bb[4]; o.y = r0[5] + bb[5];
        o.z = r0[6] + bb[6]; o.w = r0[7] + bb[7];
        *(float4*)(c0 + 4) = o;
        o.x = r1[0] + bb[0]; o.y = r1[1] + bb[1];
        o.z = r1[2] + bb[2]; o.w = r1[3] + bb[3];
        *(float4*)c1 = o;
        o.x = r1[4] + bb[4]; o.y = r1[5] + bb[5];
        o.z = r1[6] + bb[6]; o.w = r1[7] + bb[7];
        *(float4*)(c1 + 4) = o;
    }
}

// ---------------------------------------------------------------------------
// Scores + exp + partial row sums. Per pair p=(b,h), 128x128 tile of
// e[q,k] = mask ? exp((Qh·Kh)/D) : 0 written to attn (unnormalized);
// per-row partial sums atomically accumulated into g_rowsum.
// ---------------------------------------------------------------------------
__global__ __launch_bounds__(256) void scores_exp_kernel(
    const float* __restrict__ qh, const float* __restrict__ kh,
    const int* __restrict__ mask, float* __restrict__ attn,
    float* __restrict__ rowsum)
{
    __shared__ float Qs[32][128];
    __shared__ float Ks[32][128];

    int tid = threadIdx.x;
    int tx = tid & 15;
    int ty = tid >> 4;
    int p = blockIdx.z;
    int b = p / HH;
    int h = p % HH;
    int q0 = blockIdx.y * 128;
    int k0 = blockIdx.x * 128;

    const float* Qb = qh + ((size_t)b * LL + q0) * DD + h * DKK;
    const float* Kb = kh + ((size_t)b * LL + k0) * DD + h * DKK;

    int l_row = tid >> 1;
    int l_cb  = (tid & 1) * 16;

    unsigned long long acc2[4][8];
    #pragma unroll
    for (int i = 0; i < 4; ++i)
        #pragma unroll
        for (int j = 0; j < 8; ++j) acc2[i][j] = 0ull;

    for (int d0 = 0; d0 < DKK; d0 += 32) {
        const float* Qp = Qb + (size_t)l_row * DD + d0 + l_cb;
        const float* Kp = Kb + (size_t)l_row * DD + d0 + l_cb;
        float4 q0v = *(const float4*)(Qp);
        float4 q1v = *(const float4*)(Qp + 4);
        float4 q2v = *(const float4*)(Qp + 8);
        float4 q3v = *(const float4*)(Qp + 12);
        float4 k0v = *(const float4*)(Kp);
        float4 k1v = *(const float4*)(Kp + 4);
        float4 k2v = *(const float4*)(Kp + 8);
        float4 k3v = *(const float4*)(Kp + 12);
        __syncthreads();
        Qs[l_cb + 0][l_row] = q0v.x;  Qs[l_cb + 1][l_row] = q0v.y;
        Qs[l_cb + 2][l_row] = q0v.z;  Qs[l_cb + 3][l_row] = q0v.w;
        Qs[l_cb + 4][l_row] = q1v.x;  Qs[l_cb + 5][l_row] = q1v.y;
        Qs[l_cb + 6][l_row] = q1v.z;  Qs[l_cb + 7][l_row] = q1v.w;
        Qs[l_cb + 8][l_row] = q2v.x;  Qs[l_cb + 9][l_row] = q2v.y;
        Qs[l_cb + 10][l_row] = q2v.z; Qs[l_cb + 11][l_row] = q2v.w;
        Qs[l_cb + 12][l_row] = q3v.x; Qs[l_cb + 13][l_row] = q3v.y;
        Qs[l_cb + 14][l_row] = q3v.z; Qs[l_cb + 15][l_row] = q3v.w;
        Ks[l_cb + 0][l_row] = k0v.x;  Ks[l_cb + 1][l_row] = k0v.y;
        Ks[l_cb + 2][l_row] = k0v.z;  Ks[l_cb + 3][l_row] = k0v.w;
        Ks[l_cb + 4][l_row] = k1v.x;  Ks[l_cb + 5][l_row] = k1v.y;
        Ks[l_cb + 6][l_row] = k1v.z;  Ks[l_cb + 7][l_row] = k1v.w;
        Ks[l_cb + 8][l_row] = k2v.x;  Ks[l_cb + 9][l_row] = k2v.y;
        Ks[l_cb + 10][l_row] = k2v.z; Ks[l_cb + 11][l_row] = k2v.w;
        Ks[l_cb + 12][l_row] = k3v.x; Ks[l_cb + 13][l_row] = k3v.y;
        Ks[l_cb + 14][l_row] = k3v.z; Ks[l_cb + 15][l_row] = k3v.w;
        __syncthreads();

        #pragma unroll
        for (int kk = 0; kk < 32; ++kk) {
            const unsigned long long* ap =
                (const unsigned long long*)&Qs[kk][ty * 8];
            unsigned long long a2[4] = {ap[0], ap[1], ap[2], ap[3]};
            const float4* bp = (const float4*)&Ks[kk][tx * 8];
            float4 bv0 = bp[0], bv1 = bp[1];
            unsigned long long b2[8];
            b2[0] = pack2(bv0.x, bv0.x);
            b2[1] = pack2(bv0.y, bv0.y);
            b2[2] = pack2(bv0.z, bv0.z);
            b2[3] = pack2(bv0.w, bv0.w);
            b2[4] = pack2(bv1.x, bv1.x);
            b2[5] = pack2(bv1.y, bv1.y);
            b2[6] = pack2(bv1.z, bv1.z);
            b2[7] = pack2(bv1.w, bv1.w);
            #pragma unroll
            for (int ip = 0; ip < 4; ++ip)
                #pragma unroll
                for (int j = 0; j < 8; ++j)
                    ffma2(acc2[ip][j], a2[ip], b2[j]);
        }
    }

    const float scale = 1.0f / (float)DD;
    size_t obase = (size_t)(h * BB + b) * LL * LL;
    float* rs = rowsum + (size_t)p * LL;

    #pragma unroll
    for (int ip = 0; ip < 4; ++ip) {
        float r0[8], r1[8];
        #pragma unroll
        for (int j = 0; j < 8; ++j) unpack2(acc2[ip][j], r0[j], r1[j]);
        #pragma unroll
        for (int r = 0; r < 2; ++r) {
            float* s = r ? r1 : r0;
            int q = q0 + ty * 8 + 2 * ip + r;
            const int* mrow = mask + ((size_t)b * LL + q) * LL + k0 + tx * 8;
            int4 m0v = *(const int4*)(mrow);
            int4 m1v = *(const int4*)(mrow + 4);
            float e[8];
            e[0] = m0v.x ? __expf(s[0] * scale) : 0.f;
            e[1] = m0v.y ? __expf(s[1] * scale) : 0.f;
            e[2] = m0v.z ? __expf(s[2] * scale) : 0.f;
            e[3] = m0v.w ? __expf(s[3] * scale) : 0.f;
            e[4] = m1v.x ? __expf(s[4] * scale) : 0.f;
            e[5] = m1v.y ? __expf(s[5] * scale) : 0.f;
            e[6] = m1v.z ? __expf(s[6] * scale) : 0.f;
            e[7] = m1v.w ? __expf(s[7] * scale) : 0.f;
            float* orow = attn + obase + (size_t)q * LL + k0 + tx * 8;
            float4 o;
            o.x = e[0]; o.y = e[1]; o.z = e[2]; o.w = e[3];
            *(float4*)orow = o;
            o.x = e[4]; o.y = e[5]; o.z = e[6]; o.w = e[7];
            *(float4*)(orow + 4) = o;
            float part = ((e[0] + e[1]) + (e[2] + e[3])) +
                         ((e[4] + e[5]) + (e[6] + e[7]));
            part += __shfl_xor_sync(0xffffffffu, part, 8);
            part += __shfl_xor_sync(0xffffffffu, part, 4);
            part += __shfl_xor_sync(0xffffffffu, part, 2);
            part += __shfl_xor_sync(0xffffffffu, part, 1);
            if (tx == 0) atomicAdd(rs + q, part);
        }
    }
}

// ---------------------------------------------------------------------------
// AV + normalization: ctx = (attn/rowsum) @ Vh; also writes normalized attn
// back in place during its streaming read.
// ---------------------------------------------------------------------------
__global__ __launch_bounds__(256) void av_norm_kernel(
    float* __restrict__ attn, const float* __restrict__ vh,
    const float* __restrict__ rowsum, float* __restrict__ ctx)
{
    __shared__ float Ps[16][128];
    __shared__ float Vs[16][64];

    int tid = threadIdx.x;
    int tx = tid & 15;
    int ty = tid >> 4;
    int p = blockIdx.y;
    int b = p / HH;
    int h = p % HH;
    int m0 = blockIdx.x * 128;

    float* Pb = attn + (size_t)(h * BB + b) * LL * LL + (size_t)m0 * LL;
    const float* Vb = vh + (size_t)b * LL * DD + h * DKK;
    const float* rs = rowsum + (size_t)p * LL + m0;

    int ar = tid >> 1;
    int ac = (tid & 1) * 4;
    int vr = tid >> 4;
    int vc = (tid & 15) * 4;

    float inv_ar = 1.0f / rs[ar];

    unsigned long long acc2[4][4];
    #pragma unroll
    for (int i = 0; i < 4; ++i)
        #pragma unroll
        for (int j = 0; j < 4; ++j) acc2[i][j] = 0ull;

    for (int k0 = 0; k0 < LL; k0 += 16) {
        float* Pr = Pb + (size_t)ar * LL + k0 + ac;
        float4 p0 = *(const float4*)(Pr);
        float4 p1 = *(const float4*)(Pr + 8);
        float4 vv = *(const float4*)(Vb + (size_t)(k0 + vr) * DD + vc);
        __syncthreads();
        Ps[ac + 0][ar] = p0.x;  Ps[ac + 1][ar] = p0.y;
        Ps[ac + 2][ar] = p0.z;  Ps[ac + 3][ar] = p0.w;
        Ps[ac + 8][ar] = p1.x;  Ps[ac + 9][ar] = p1.y;
        Ps[ac + 10][ar] = p1.z; Ps[ac + 11][ar] = p1.w;
        *(float4*)&Vs[vr][vc] = vv;
        __syncthreads();

        // write back normalized attention (overlaps with compute below)
        float4 w;
        w.x = p0.x * inv_ar; w.y = p0.y * inv_ar;
        w.z = p0.z * inv_ar; w.w = p0.w * inv_ar;
        *(float4*)(Pr) = w;
        w.x = p1.x * inv_ar; w.y = p1.y * inv_ar;
        w.z = p1.z * inv_ar; w.w = p1.w * inv_ar;
        *(float4*)(Pr + 8) = w;

        #pragma unroll
        for (int kk = 0; kk < 16; ++kk) {
            const unsigned long long* ap =
                (const unsigned long long*)&Ps[kk][ty * 8];
            unsigned long long a2[4] = {ap[0], ap[1], ap[2], ap[3]};
            float bv0 = Vs[kk][tx * 4 + 0];
            float bv1 = Vs[kk][tx * 4 + 1];
            float bv2 = Vs[kk][tx * 4 + 2];
            float bv3 = Vs[kk][tx * 4 + 3];
            unsigned long long b2[4];
            b2[0] = pack2(bv0, bv0);
            b2[1] = pack2(bv1, bv1);
            b2[2] = pack2(bv2, bv2);
            b2[3] = pack2(bv3, bv3);
            #pragma unroll
            for (int ip = 0; ip < 4; ++ip)
                #pragma unroll
                for (int j = 0; j < 4; ++j)
                    ffma2(acc2[ip][j], a2[ip], b2[j]);
        }
    }

    #pragma unroll
    for (int ip = 0; ip < 4; ++ip) {
        float r0[4], r1[4];
        #pragma unroll
        for (int j = 0; j < 4; ++j) unpack2(acc2[ip][j], r0[j], r1[j]);
        int row0 = m0 + ty * 8 + 2 * ip;
        float i0 = 1.0f / rowsum[(size_t)p * LL + row0];
        float i1 = 1.0f / rowsum[(size_t)p * LL + row0 + 1];
        float4 o;
        o.x = r0[0] * i0; o.y = r0[1] * i0; o.z = r0[2] * i0; o.w = r0[3] * i0;
        *(float4*)&ctx[((size_t)b * LL + row0) * DD + h * DKK + tx * 4] = o;
        o.x = r1[0] * i1; o.y = r1[1] * i1; o.z = r1[2] * i1; o.w = r1[3] * i1;
        *(float4*)&ctx[((size_t)b * LL + row0 + 1) * DD + h * DKK + tx * 4] = o;
    }
}

// ---------------------------------------------------------------------------
extern "C" void kernel_launch(void* const* d_in, const int* in_sizes, int n_in,
                              void* d_out, int out_size)
{
    const float* q    = (const float*)d_in[0];
    const float* k    = (const float*)d_in[1];
    const float* v    = (const float*)d_in[2];
    const int*   mask = (const int*)d_in[3];
    const float* Wq   = (const float*)d_in[4];
    const float* bq   = (const float*)d_in[5];
    const float* Wk   = (const float*)d_in[6];
    const float* bk   = (const float*)d_in[7];
    const float* Wv   = (const float*)d_in[8];
    const float* bv   = (const float*)d_in[9];
    const float* Wo   = (const float*)d_in[10];
    const float* bo   = (const float*)d_in[11];

    float* out  = (float*)d_out;
    float* attn = out + (size_t)BB * LL * DD;

    float *qh, *kh, *vh, *ctx, *rowsum;
    cudaGetSymbolAddress((void**)&qh, g_qh);
    cudaGetSymbolAddress((void**)&kh, g_kh);
    cudaGetSymbolAddress((void**)&vh, g_vh);
    cudaGetSymbolAddress((void**)&ctx, g_ctx);
    cudaGetSymbolAddress((void**)&rowsum, g_rowsum);

    const int M = BB * LL;  // 4096

    zero_kernel<<<(NP * LL + 255) / 256, 256>>>(rowsum, NP * LL);

    dim3 gproj(DD / 128, M / 128);  // (8, 32)
    gemm_bias_kernel<<<gproj, 256>>>(q, Wq, bq, qh, M, DD, DD);
    gemm_bias_kernel<<<gproj, 256>>>(k, Wk, bk, kh, M, DD, DD);
    gemm_bias_kernel<<<gproj, 256>>>(v, Wv, bv, vh, M, DD, DD);

    dim3 gsc(LL / 128, LL / 128, NP);  // (16,16,32)
    scores_exp_kernel<<<gsc, 256>>>(qh, kh, mask, attn, rowsum);

    dim3 gav(LL / 128, NP);  // (16, 32)
    av_norm_kernel<<<gav, 256>>>(attn, vh, rowsum, ctx);

    gemm_bias_kernel<<<gproj, 256>>>(ctx, Wo, bo, out, M, DD, DD);
}

// round 6
// speedup vs baseline: 1.3023x; 1.1192x over previous
#include <cuda_runtime.h>
#include <cuda_bf16.h>
#include <cstdint>

#define BB 2
#define LL 2048
#define DD 1024
#define HH 16
#define DKK 64
#define NP (BB*HH)

// Scratch (__device__ globals — no runtime allocation)
__device__ float g_qh[(size_t)BB * LL * DD];
__device__ float g_kh[(size_t)BB * LL * DD];
__device__ float g_vh[(size_t)BB * LL * DD];
__device__ float g_ctx[(size_t)BB * LL * DD];
__device__ float g_rowsum[(size_t)NP * LL];

// ---- packed fp32x2 helpers (FFMA2 via PTX) --------------------------------
__device__ __forceinline__ unsigned long long pack2(float x, float y) {
    unsigned long long r;
    asm("mov.b64 %0,{%1,%2};" : "=l"(r) : "f"(x), "f"(y));
    return r;
}
__device__ __forceinline__ void unpack2(unsigned long long p, float& x, float& y) {
    asm("mov.b64 {%0,%1},%2;" : "=f"(x), "=f"(y) : "l"(p));
}
__device__ __forceinline__ void ffma2(unsigned long long& d,
                                      unsigned long long a, unsigned long long b) {
    asm("fma.rn.f32x2 %0,%1,%2,%0;" : "+l"(d) : "l"(a), "l"(b));
}

// ---- warp-MMA helpers (base-target instructions; no tcgen05) --------------
__device__ __forceinline__ uint32_t smem_u32(const void* p) {
    uint32_t a;
    asm("{ .reg .u64 t; cvta.to.shared.u64 t, %1; cvt.u32.u64 %0, t; }"
        : "=r"(a) : "l"(p));
    return a;
}
__device__ __forceinline__ void ldm_x4(uint32_t* r, uint32_t addr) {
    asm volatile("ldmatrix.sync.aligned.m8n8.x4.shared.b16 {%0,%1,%2,%3}, [%4];"
                 : "=r"(r[0]), "=r"(r[1]), "=r"(r[2]), "=r"(r[3]) : "r"(addr));
}
__device__ __forceinline__ void mma_bf16(float* c, const uint32_t* a,
                                         const uint32_t* b) {
    asm volatile(
        "mma.sync.aligned.m16n8k16.row.col.f32.bf16.bf16.f32 "
        "{%0,%1,%2,%3}, {%4,%5,%6,%7}, {%8,%9}, {%0,%1,%2,%3};"
        : "+f"(c[0]), "+f"(c[1]), "+f"(c[2]), "+f"(c[3])
        : "r"(a[0]), "r"(a[1]), "r"(a[2]), "r"(a[3]), "r"(b[0]), "r"(b[1]));
}

// ---------------------------------------------------------------------------
__global__ void zero_kernel(float* p, int n) {
    int i = blockIdx.x * blockDim.x + threadIdx.x;
    if (i < n) p[i] = 0.f;
}

// ---------------------------------------------------------------------------
// HMMA GEMM: C[M,N] = A[M,K]*W[K,N] + bias, fp32 in/out via bf16 hi/lo split
// (3 MMAs: Ah*Bh + Ah*Bl + Al*Bh). Tile 128x128, BK=32, 8 warps (2x4),
// each warp 64x32 via m16n8k16. Smem rows padded to 80B => conflict-free
// ldmatrix. Double-buffered, one __syncthreads per K-chunk.
// ---------------------------------------------------------------------------
#define ROWB 80            // bytes per smem row (32 bf16 data + 16B pad)
#define OFF_AH 0
#define OFF_AL 10240       // 128*80
#define OFF_BH 20480
#define OFF_BL 30720
#define BUFB   40960
#define GEMM_SMEM (2*BUFB)

__global__ __launch_bounds__(256) void gemm_mma_kernel(
    const float* __restrict__ A, const float* __restrict__ W,
    const float* __restrict__ bias, float* __restrict__ C,
    int M, int N, int K)
{
    extern __shared__ char smem[];
    const uint32_t sbase = smem_u32(smem);
    const int tid  = threadIdx.x;
    const int wid  = tid >> 5;
    const int lane = tid & 31;
    const int m0 = blockIdx.y * 128;
    const int n0 = blockIdx.x * 128;
    const int wm = (wid & 1) * 64;     // warp m-offset in tile
    const int wn = (wid >> 1) * 32;    // warp n-offset in tile

    float c[4][4][4];
    #pragma unroll
    for (int mt = 0; mt < 4; ++mt)
        #pragma unroll
        for (int no = 0; no < 4; ++no)
            #pragma unroll
            for (int e = 0; e < 4; ++e) c[mt][no][e] = 0.f;

    // staged global loads
    float ra[16], rw[16];
    const int a_row = tid >> 1;          // 0..127
    const int a_c16 = (tid & 1) * 16;    // 0 or 16
    const int w_k   = tid >> 3;          // 0..31
    const int w_n16 = (tid & 7) * 16;    // 0..112

    auto g_load = [&](int t) {
        const float* Ap = A + (size_t)(m0 + a_row) * K + t * 32 + a_c16;
        #pragma unroll
        for (int i = 0; i < 4; ++i)
            *(float4*)(ra + 4 * i) = *(const float4*)(Ap + 4 * i);
        const float* Wp = W + (size_t)(t * 32 + w_k) * N + n0 + w_n16;
        #pragma unroll
        for (int i = 0; i < 4; ++i)
            *(float4*)(rw + 4 * i) = *(const float4*)(Wp + 4 * i);
    };
    auto s_store = [&](int buf) {
        char* base = smem + buf * BUFB;
        // A: row-major [m][k], 16 bf16 contiguous
        uint32_t ao = (uint32_t)a_row * ROWB + (uint32_t)a_c16 * 2;
        #pragma unroll
        for (int i = 0; i < 8; ++i) {
            float x = ra[2 * i], y = ra[2 * i + 1];
            __nv_bfloat16 hx = __float2bfloat16(x);
            __nv_bfloat16 hy = __float2bfloat16(y);
            float lx = x - __bfloat162float(hx);
            float ly = y - __bfloat162float(hy);
            __nv_bfloat162 hp; hp.x = hx; hp.y = hy;
            __nv_bfloat162 lp = __floats2bfloat162_rn(lx, ly);
            *(uint32_t*)(base + OFF_AH + ao + 4 * i) = *(uint32_t*)&hp;
            *(uint32_t*)(base + OFF_AL + ao + 4 * i) = *(uint32_t*)&lp;
        }
        // B: transposed to [n][k]
        #pragma unroll
        for (int i = 0; i < 16; ++i) {
            float x = rw[i];
            __nv_bfloat16 h = __float2bfloat16(x);
            float l = x - __bfloat162float(h);
            __nv_bfloat16 lo = __float2bfloat16(l);
            uint32_t bo = (uint32_t)(w_n16 + i) * ROWB + (uint32_t)w_k * 2;
            *(__nv_bfloat16*)(base + OFF_BH + bo) = h;
            *(__nv_bfloat16*)(base + OFF_BL + bo) = lo;
        }
    };

    const int NT = K / 32;
    g_load(0);
    s_store(0);

    // per-lane ldmatrix address components
    const uint32_t a_lrow = (uint32_t)(lane & 15);
    const uint32_t a_koff = (uint32_t)(lane >> 4) * 8;
    const uint32_t b_lrow = (uint32_t)((lane >> 4) * 8 + (lane & 7));
    const uint32_t b_koff = (uint32_t)((lane >> 3) & 1) * 8;

    for (int t = 0; t < NT; ++t) {
        __syncthreads();
        const uint32_t bb = sbase + (uint32_t)(t & 1) * BUFB;
        if (t + 1 < NT) g_load(t + 1);

        #pragma unroll
        for (int ks = 0; ks < 2; ++ks) {
            const uint32_t kbyte = (uint32_t)(ks * 16 + a_koff) * 2;
            uint32_t af[4][4];
            #pragma unroll
            for (int mt = 0; mt < 4; ++mt)
                ldm_x4(af[mt], bb + OFF_AH +
                       (uint32_t)(wm + mt * 16 + a_lrow) * ROWB + kbyte);

            const uint32_t bkb = (uint32_t)(ks * 16 + b_koff) * 2;
            uint32_t bh[4][2], bl[4][2];
            #pragma unroll
            for (int half = 0; half < 2; ++half) {
                uint32_t r[4];
                uint32_t nrow = (uint32_t)(wn + half * 16) + b_lrow;
                ldm_x4(r, bb + OFF_BH + nrow * ROWB + bkb);
                bh[half * 2][0] = r[0]; bh[half * 2][1] = r[1];
                bh[half * 2 + 1][0] = r[2]; bh[half * 2 + 1][1] = r[3];
                ldm_x4(r, bb + OFF_BL + nrow * ROWB + bkb);
                bl[half * 2][0] = r[0]; bl[half * 2][1] = r[1];
                bl[half * 2 + 1][0] = r[2]; bl[half * 2 + 1][1] = r[3];
            }

            #pragma unroll
            for (int mt = 0; mt < 4; ++mt)
                #pragma unroll
                for (int no = 0; no < 4; ++no)
                    mma_bf16(c[mt][no], af[mt], bh[no]);
            #pragma unroll
            for (int mt = 0; mt < 4; ++mt)
                #pragma unroll
                for (int no = 0; no < 4; ++no)
                    mma_bf16(c[mt][no], af[mt], bl[no]);

            // A-lo fragments (reuse af regs)
            #pragma unroll
            for (int mt = 0; mt < 4; ++mt)
                ldm_x4(af[mt], bb + OFF_AL +
                       (uint32_t)(wm + mt * 16 + a_lrow) * ROWB + kbyte);
            #pragma unroll
            for (int mt = 0; mt < 4; ++mt)
                #pragma unroll
                for (int no = 0; no < 4; ++no)
                    mma_bf16(c[mt][no], af[mt], bh[no]);
        }
        if (t + 1 < NT) s_store((t + 1) & 1);
    }

    // Epilogue
    const int erow = lane >> 2;
    const int ecol = (lane & 3) * 2;
    #pragma unroll
    for (int mt = 0; mt < 4; ++mt) {
        int r0 = m0 + wm + mt * 16 + erow;
        #pragma unroll
        for (int no = 0; no < 4; ++no) {
            int col = n0 + wn + no * 8 + ecol;
            float2 bv = *(const float2*)(bias + col);
            float2 o;
            o.x = c[mt][no][0] + bv.x;
            o.y = c[mt][no][1] + bv.y;
            *(float2*)(C + (size_t)r0 * N + col) = o;
            o.x = c[mt][no][2] + bv.x;
            o.y = c[mt][no][3] + bv.y;
            *(float2*)(C + (size_t)(r0 + 8) * N + col) = o;
        }
    }
}

// ---------------------------------------------------------------------------
// Scores + exp + partial row sums (FFMA2 path)
// ---------------------------------------------------------------------------
__global__ __launch_bounds__(256) void scores_exp_kernel(
    const float* __restrict__ qh, const float* __restrict__ kh,
    const int* __restrict__ mask, float* __restrict__ attn,
    float* __restrict__ rowsum)
{
    __shared__ float Qs[32][128];
    __shared__ float Ks[32][128];

    int tid = threadIdx.x;
    int tx = tid & 15;
    int ty = tid >> 4;
    int p = blockIdx.z;
    int b = p / HH;
    int h = p % HH;
    int q0 = blockIdx.y * 128;
    int k0 = blockIdx.x * 128;

    const float* Qb = qh + ((size_t)b * LL + q0) * DD + h * DKK;
    const float* Kb = kh + ((size_t)b * LL + k0) * DD + h * DKK;

    int l_row = tid >> 1;
    int l_cb  = (tid & 1) * 16;

    unsigned long long acc2[4][8];
    #pragma unroll
    for (int i = 0; i < 4; ++i)
        #pragma unroll
        for (int j = 0; j < 8; ++j) acc2[i][j] = 0ull;

    for (int d0 = 0; d0 < DKK; d0 += 32) {
        const float* Qp = Qb + (size_t)l_row * DD + d0 + l_cb;
        const float* Kp = Kb + (size_t)l_row * DD + d0 + l_cb;
        float4 q0v = *(const float4*)(Qp);
        float4 q1v = *(const float4*)(Qp + 4);
        float4 q2v = *(const float4*)(Qp + 8);
        float4 q3v = *(const float4*)(Qp + 12);
        float4 k0v = *(const float4*)(Kp);
        float4 k1v = *(const float4*)(Kp + 4);
        float4 k2v = *(const float4*)(Kp + 8);
        float4 k3v = *(const float4*)(Kp + 12);
        __syncthreads();
        Qs[l_cb + 0][l_row] = q0v.x;  Qs[l_cb + 1][l_row] = q0v.y;
        Qs[l_cb + 2][l_row] = q0v.z;  Qs[l_cb + 3][l_row] = q0v.w;
        Qs[l_cb + 4][l_row] = q1v.x;  Qs[l_cb + 5][l_row] = q1v.y;
        Qs[l_cb + 6][l_row] = q1v.z;  Qs[l_cb + 7][l_row] = q1v.w;
        Qs[l_cb + 8][l_row] = q2v.x;  Qs[l_cb + 9][l_row] = q2v.y;
        Qs[l_cb + 10][l_row] = q2v.z; Qs[l_cb + 11][l_row] = q2v.w;
        Qs[l_cb + 12][l_row] = q3v.x; Qs[l_cb + 13][l_row] = q3v.y;
        Qs[l_cb + 14][l_row] = q3v.z; Qs[l_cb + 15][l_row] = q3v.w;
        Ks[l_cb + 0][l_row] = k0v.x;  Ks[l_cb + 1][l_row] = k0v.y;
        Ks[l_cb + 2][l_row] = k0v.z;  Ks[l_cb + 3][l_row] = k0v.w;
        Ks[l_cb + 4][l_row] = k1v.x;  Ks[l_cb + 5][l_row] = k1v.y;
        Ks[l_cb + 6][l_row] = k1v.z;  Ks[l_cb + 7][l_row] = k1v.w;
        Ks[l_cb + 8][l_row] = k2v.x;  Ks[l_cb + 9][l_row] = k2v.y;
        Ks[l_cb + 10][l_row] = k2v.z; Ks[l_cb + 11][l_row] = k2v.w;
        Ks[l_cb + 12][l_row] = k3v.x; Ks[l_cb + 13][l_row] = k3v.y;
        Ks[l_cb + 14][l_row] = k3v.z; Ks[l_cb + 15][l_row] = k3v.w;
        __syncthreads();

        #pragma unroll
        for (int kk = 0; kk < 32; ++kk) {
            const unsigned long long* ap =
                (const unsigned long long*)&Qs[kk][ty * 8];
            unsigned long long a2[4] = {ap[0], ap[1], ap[2], ap[3]};
            const float4* bp = (const float4*)&Ks[kk][tx * 8];
            float4 bv0 = bp[0], bv1 = bp[1];
            unsigned long long b2[8];
            b2[0] = pack2(bv0.x, bv0.x);
            b2[1] = pack2(bv0.y, bv0.y);
            b2[2] = pack2(bv0.z, bv0.z);
            b2[3] = pack2(bv0.w, bv0.w);
            b2[4] = pack2(bv1.x, bv1.x);
            b2[5] = pack2(bv1.y, bv1.y);
            b2[6] = pack2(bv1.z, bv1.z);
            b2[7] = pack2(bv1.w, bv1.w);
            #pragma unroll
            for (int ip = 0; ip < 4; ++ip)
                #pragma unroll
                for (int j = 0; j < 8; ++j)
                    ffma2(acc2[ip][j], a2[ip], b2[j]);
        }
    }

    const float scale = 1.0f / (float)DD;
    size_t obase = (size_t)(h * BB + b) * LL * LL;
    float* rs = rowsum + (size_t)p * LL;

    #pragma unroll
    for (int ip = 0; ip < 4; ++ip) {
        float r0[8], r1[8];
        #pragma unroll
        for (int j = 0; j < 8; ++j) unpack2(acc2[ip][j], r0[j], r1[j]);
        #pragma unroll
        for (int r = 0; r < 2; ++r) {
            float* s = r ? r1 : r0;
            int q = q0 + ty * 8 + 2 * ip + r;
            const int* mrow = mask + ((size_t)b * LL + q) * LL + k0 + tx * 8;
            int4 m0v = *(const int4*)(mrow);
            int4 m1v = *(const int4*)(mrow + 4);
            float e[8];
            e[0] = m0v.x ? __expf(s[0] * scale) : 0.f;
            e[1] = m0v.y ? __expf(s[1] * scale) : 0.f;
            e[2] = m0v.z ? __expf(s[2] * scale) : 0.f;
            e[3] = m0v.w ? __expf(s[3] * scale) : 0.f;
            e[4] = m1v.x ? __expf(s[4] * scale) : 0.f;
            e[5] = m1v.y ? __expf(s[5] * scale) : 0.f;
            e[6] = m1v.z ? __expf(s[6] * scale) : 0.f;
            e[7] = m1v.w ? __expf(s[7] * scale) : 0.f;
            float* orow = attn + obase + (size_t)q * LL + k0 + tx * 8;
            float4 o;
            o.x = e[0]; o.y = e[1]; o.z = e[2]; o.w = e[3];
            *(float4*)orow = o;
            o.x = e[4]; o.y = e[5]; o.z = e[6]; o.w = e[7];
            *(float4*)(orow + 4) = o;
            float part = ((e[0] + e[1]) + (e[2] + e[3])) +
                         ((e[4] + e[5]) + (e[6] + e[7]));
            part += __shfl_xor_sync(0xffffffffu, part, 8);
            part += __shfl_xor_sync(0xffffffffu, part, 4);
            part += __shfl_xor_sync(0xffffffffu, part, 2);
            part += __shfl_xor_sync(0xffffffffu, part, 1);
            if (tx == 0) atomicAdd(rs + q, part);
        }
    }
}

// ---------------------------------------------------------------------------
// AV + normalization (FFMA2 path)
// ---------------------------------------------------------------------------
__global__ __launch_bounds__(256) void av_norm_kernel(
    float* __restrict__ attn, const float* __restrict__ vh,
    const float* __restrict__ rowsum, float* __restrict__ ctx)
{
    __shared__ float Ps[16][128];
    __shared__ float Vs[16][64];

    int tid = threadIdx.x;
    int tx = tid & 15;
    int ty = tid >> 4;
    int p = blockIdx.y;
    int b = p / HH;
    int h = p % HH;
    int m0 = blockIdx.x * 128;

    float* Pb = attn + (size_t)(h * BB + b) * LL * LL + (size_t)m0 * LL;
    const float* Vb = vh + (size_t)b * LL * DD + h * DKK;
    const float* rs = rowsum + (size_t)p * LL + m0;

    int ar = tid >> 1;
    int ac = (tid & 1) * 4;
    int vr = tid >> 4;
    int vc = (tid & 15) * 4;

    float inv_ar = 1.0f / rs[ar];

    unsigned long long acc2[4][4];
    #pragma unroll
    for (int i = 0; i < 4; ++i)
        #pragma unroll
        for (int j = 0; j < 4; ++j) acc2[i][j] = 0ull;

    for (int k0 = 0; k0 < LL; k0 += 16) {
        float* Pr = Pb + (size_t)ar * LL + k0 + ac;
        float4 p0 = *(const float4*)(Pr);
        float4 p1 = *(const float4*)(Pr + 8);
        float4 vv = *(const float4*)(Vb + (size_t)(k0 + vr) * DD + vc);
        __syncthreads();
        Ps[ac + 0][ar] = p0.x;  Ps[ac + 1][ar] = p0.y;
        Ps[ac + 2][ar] = p0.z;  Ps[ac + 3][ar] = p0.w;
        Ps[ac + 8][ar] = p1.x;  Ps[ac + 9][ar] = p1.y;
        Ps[ac + 10][ar] = p1.z; Ps[ac + 11][ar] = p1.w;
        *(float4*)&Vs[vr][vc] = vv;
        __syncthreads();

        float4 w;
        w.x = p0.x * inv_ar; w.y = p0.y * inv_ar;
        w.z = p0.z * inv_ar; w.w = p0.w * inv_ar;
        *(float4*)(Pr) = w;
        w.x = p1.x * inv_ar; w.y = p1.y * inv_ar;
        w.z = p1.z * inv_ar; w.w = p1.w * inv_ar;
        *(float4*)(Pr + 8) = w;

        #pragma unroll
        for (int kk = 0; kk < 16; ++kk) {
            const unsigned long long* ap =
                (const unsigned long long*)&Ps[kk][ty * 8];
            unsigned long long a2[4] = {ap[0], ap[1], ap[2], ap[3]};
            float bv0 = Vs[kk][tx * 4 + 0];
            float bv1 = Vs[kk][tx * 4 + 1];
            float bv2 = Vs[kk][tx * 4 + 2];
            float bv3 = Vs[kk][tx * 4 + 3];
            unsigned long long b2[4];
            b2[0] = pack2(bv0, bv0);
            b2[1] = pack2(bv1, bv1);
            b2[2] = pack2(bv2, bv2);
            b2[3] = pack2(bv3, bv3);
            #pragma unroll
            for (int ip = 0; ip < 4; ++ip)
                #pragma unroll
                for (int j = 0; j < 4; ++j)
                    ffma2(acc2[ip][j], a2[ip], b2[j]);
        }
    }

    #pragma unroll
    for (int ip = 0; ip < 4; ++ip) {
        float r0[4], r1[4];
        #pragma unroll
        for (int j = 0; j < 4; ++j) unpack2(acc2[ip][j], r0[j], r1[j]);
        int row0 = m0 + ty * 8 + 2 * ip;
        float i0 = 1.0f / rowsum[(size_t)p * LL + row0];
        float i1 = 1.0f / rowsum[(size_t)p * LL + row0 + 1];
        float4 o;
        o.x = r0[0] * i0; o.y = r0[1] * i0; o.z = r0[2] * i0; o.w = r0[3] * i0;
        *(float4*)&ctx[((size_t)b * LL + row0) * DD + h * DKK + tx * 4] = o;
        o.x = r1[0] * i1; o.y = r1[1] * i1; o.z = r1[2] * i1; o.w = r1[3] * i1;
        *(float4*)&ctx[((size_t)b * LL + row0 + 1) * DD + h * DKK + tx * 4] = o;
    }
}

// ---------------------------------------------------------------------------
extern "C" void kernel_launch(void* const* d_in, const int* in_sizes, int n_in,
                              void* d_out, int out_size)
{
    const float* q    = (const float*)d_in[0];
    const float* k    = (const float*)d_in[1];
    const float* v    = (const float*)d_in[2];
    const int*   mask = (const int*)d_in[3];
    const float* Wq   = (const float*)d_in[4];
    const float* bq   = (const float*)d_in[5];
    const float* Wk   = (const float*)d_in[6];
    const float* bk   = (const float*)d_in[7];
    const float* Wv   = (const float*)d_in[8];
    const float* bv   = (const float*)d_in[9];
    const float* Wo   = (const float*)d_in[10];
    const float* bo   = (const float*)d_in[11];

    float* out  = (float*)d_out;
    float* attn = out + (size_t)BB * LL * DD;

    float *qh, *kh, *vh, *ctx, *rowsum;
    cudaGetSymbolAddress((void**)&qh, g_qh);
    cudaGetSymbolAddress((void**)&kh, g_kh);
    cudaGetSymbolAddress((void**)&vh, g_vh);
    cudaGetSymbolAddress((void**)&ctx, g_ctx);
    cudaGetSymbolAddress((void**)&rowsum, g_rowsum);

    const int M = BB * LL;  // 4096

    static int smem_set = 0;
    if (!smem_set) {
        cudaFuncSetAttribute(gemm_mma_kernel,
                             cudaFuncAttributeMaxDynamicSharedMemorySize,
                             GEMM_SMEM);
        smem_set = 1;
    }

    zero_kernel<<<(NP * LL + 255) / 256, 256>>>(rowsum, NP * LL);

    dim3 gproj(DD / 128, M / 128);  // (8, 32)
    gemm_mma_kernel<<<gproj, 256, GEMM_SMEM>>>(q, Wq, bq, qh, M, DD, DD);
    gemm_mma_kernel<<<gproj, 256, GEMM_SMEM>>>(k, Wk, bk, kh, M, DD, DD);
    gemm_mma_kernel<<<gproj, 256, GEMM_SMEM>>>(v, Wv, bv, vh, M, DD, DD);

    dim3 gsc(LL / 128, LL / 128, NP);  // (16,16,32)
    scores_exp_kernel<<<gsc, 256>>>(qh, kh, mask, attn, rowsum);

    dim3 gav(LL / 128, NP);  // (16, 32)
    av_norm_kernel<<<gav, 256>>>(attn, vh, rowsum, ctx);

    gemm_mma_kernel<<<gproj, 256, GEMM_SMEM>>>(ctx, Wo, bo, out, M, DD, DD);
}

// round 8
// speedup vs baseline: 1.5153x; 1.1636x over previous
#include <cuda_runtime.h>
#include <cuda_bf16.h>
#include <cstdint>

#define BB 2
#define LL 2048
#define DD 1024
#define HH 16
#define DKK 64
#define NP (BB*HH)

// Scratch (__device__ globals — no runtime allocation)
__device__ float g_qh[(size_t)BB * LL * DD];
__device__ float g_kh[(size_t)BB * LL * DD];
__device__ float g_vh[(size_t)BB * LL * DD];
__device__ float g_ctx[(size_t)BB * LL * DD];
__device__ float g_rowsum[(size_t)NP * LL];

// ---- warp-MMA helpers (base-target instructions; no tcgen05) --------------
__device__ __forceinline__ uint32_t smem_u32(const void* p) {
    uint32_t a;
    asm("{ .reg .u64 t; cvta.to.shared.u64 t, %1; cvt.u32.u64 %0, t; }"
        : "=r"(a) : "l"(p));
    return a;
}
__device__ __forceinline__ void ldm_x4(uint32_t* r, uint32_t addr) {
    asm volatile("ldmatrix.sync.aligned.m8n8.x4.shared.b16 {%0,%1,%2,%3}, [%4];"
                 : "=r"(r[0]), "=r"(r[1]), "=r"(r[2]), "=r"(r[3]) : "r"(addr));
}
__device__ __forceinline__ void mma_bf16(float* c, const uint32_t* a,
                                         const uint32_t* b) {
    asm volatile(
        "mma.sync.aligned.m16n8k16.row.col.f32.bf16.bf16.f32 "
        "{%0,%1,%2,%3}, {%4,%5,%6,%7}, {%8,%9}, {%0,%1,%2,%3};"
        : "+f"(c[0]), "+f"(c[1]), "+f"(c[2]), "+f"(c[3])
        : "r"(a[0]), "r"(a[1]), "r"(a[2]), "r"(a[3]), "r"(b[0]), "r"(b[1]));
}
// split a float pair into bf16x2 hi and lo words
__device__ __forceinline__ void split2(float x, float y, uint32_t& hi, uint32_t& lo) {
    __nv_bfloat16 hx = __float2bfloat16(x);
    __nv_bfloat16 hy = __float2bfloat16(y);
    float lx = x - __bfloat162float(hx);
    float ly = y - __bfloat162float(hy);
    __nv_bfloat162 hp; hp.x = hx; hp.y = hy;
    __nv_bfloat162 lp = __floats2bfloat162_rn(lx, ly);
    hi = *(uint32_t*)&hp;
    lo = *(uint32_t*)&lp;
}

// ---------------------------------------------------------------------------
__global__ void zero_kernel(float* p, int n) {
    int i = blockIdx.x * blockDim.x + threadIdx.x;
    if (i < n) p[i] = 0.f;
}

// ---------------------------------------------------------------------------
// HMMA GEMM: C = A*W + bias (fp32 via bf16 hi/lo 3-MMA split). Unchanged R6.
// ---------------------------------------------------------------------------
#define ROWB 80
#define OFF_AH 0
#define OFF_AL 10240
#define OFF_BH 20480
#define OFF_BL 30720
#define BUFB   40960
#define GEMM_SMEM (2*BUFB)

__global__ __launch_bounds__(256) void gemm_mma_kernel(
    const float* __restrict__ A, const float* __restrict__ W,
    const float* __restrict__ bias, float* __restrict__ C,
    int M, int N, int K)
{
    extern __shared__ char smem[];
    const uint32_t sbase = smem_u32(smem);
    const int tid  = threadIdx.x;
    const int wid  = tid >> 5;
    const int lane = tid & 31;
    const int m0 = blockIdx.y * 128;
    const int n0 = blockIdx.x * 128;
    const int wm = (wid & 1) * 64;
    const int wn = (wid >> 1) * 32;

    float c[4][4][4];
    #pragma unroll
    for (int mt = 0; mt < 4; ++mt)
        #pragma unroll
        for (int no = 0; no < 4; ++no)
            #pragma unroll
            for (int e = 0; e < 4; ++e) c[mt][no][e] = 0.f;

    float ra[16], rw[16];
    const int a_row = tid >> 1;
    const int a_c16 = (tid & 1) * 16;
    const int w_k   = tid >> 3;
    const int w_n16 = (tid & 7) * 16;

    auto g_load = [&](int t) {
        const float* Ap = A + (size_t)(m0 + a_row) * K + t * 32 + a_c16;
        #pragma unroll
        for (int i = 0; i < 4; ++i)
            *(float4*)(ra + 4 * i) = *(const float4*)(Ap + 4 * i);
        const float* Wp = W + (size_t)(t * 32 + w_k) * N + n0 + w_n16;
        #pragma unroll
        for (int i = 0; i < 4; ++i)
            *(float4*)(rw + 4 * i) = *(const float4*)(Wp + 4 * i);
    };
    auto s_store = [&](int buf) {
        char* base = smem + buf * BUFB;
        uint32_t ao = (uint32_t)a_row * ROWB + (uint32_t)a_c16 * 2;
        #pragma unroll
        for (int i = 0; i < 8; ++i) {
            uint32_t hi, lo;
            split2(ra[2 * i], ra[2 * i + 1], hi, lo);
            *(uint32_t*)(base + OFF_AH + ao + 4 * i) = hi;
            *(uint32_t*)(base + OFF_AL + ao + 4 * i) = lo;
        }
        #pragma unroll
        for (int i = 0; i < 16; ++i) {
            float x = rw[i];
            __nv_bfloat16 h = __float2bfloat16(x);
            float l = x - __bfloat162float(h);
            __nv_bfloat16 lo = __float2bfloat16(l);
            uint32_t bo = (uint32_t)(w_n16 + i) * ROWB + (uint32_t)w_k * 2;
            *(__nv_bfloat16*)(base + OFF_BH + bo) = h;
            *(__nv_bfloat16*)(base + OFF_BL + bo) = lo;
        }
    };

    const int NT = K / 32;
    g_load(0);
    s_store(0);

    const uint32_t a_lrow = (uint32_t)(lane & 15);
    const uint32_t a_koff = (uint32_t)(lane >> 4) * 8;
    const uint32_t b_lrow = (uint32_t)((lane >> 4) * 8 + (lane & 7));
    const uint32_t b_koff = (uint32_t)((lane >> 3) & 1) * 8;

    for (int t = 0; t < NT; ++t) {
        __syncthreads();
        const uint32_t bb = sbase + (uint32_t)(t & 1) * BUFB;
        if (t + 1 < NT) g_load(t + 1);

        #pragma unroll
        for (int ks = 0; ks < 2; ++ks) {
            const uint32_t kbyte = (uint32_t)(ks * 16 + a_koff) * 2;
            uint32_t af[4][4];
            #pragma unroll
            for (int mt = 0; mt < 4; ++mt)
                ldm_x4(af[mt], bb + OFF_AH +
                       (uint32_t)(wm + mt * 16 + a_lrow) * ROWB + kbyte);

            const uint32_t bkb = (uint32_t)(ks * 16 + b_koff) * 2;
            uint32_t bh[4][2], bl[4][2];
            #pragma unroll
            for (int half = 0; half < 2; ++half) {
                uint32_t r[4];
                uint32_t nrow = (uint32_t)(wn + half * 16) + b_lrow;
                ldm_x4(r, bb + OFF_BH + nrow * ROWB + bkb);
                bh[half * 2][0] = r[0]; bh[half * 2][1] = r[1];
                bh[half * 2 + 1][0] = r[2]; bh[half * 2 + 1][1] = r[3];
                ldm_x4(r, bb + OFF_BL + nrow * ROWB + bkb);
                bl[half * 2][0] = r[0]; bl[half * 2][1] = r[1];
                bl[half * 2 + 1][0] = r[2]; bl[half * 2 + 1][1] = r[3];
            }

            #pragma unroll
            for (int mt = 0; mt < 4; ++mt)
                #pragma unroll
                for (int no = 0; no < 4; ++no)
                    mma_bf16(c[mt][no], af[mt], bh[no]);
            #pragma unroll
            for (int mt = 0; mt < 4; ++mt)
                #pragma unroll
                for (int no = 0; no < 4; ++no)
                    mma_bf16(c[mt][no], af[mt], bl[no]);

            #pragma unroll
            for (int mt = 0; mt < 4; ++mt)
                ldm_x4(af[mt], bb + OFF_AL +
                       (uint32_t)(wm + mt * 16 + a_lrow) * ROWB + kbyte);
            #pragma unroll
            for (int mt = 0; mt < 4; ++mt)
                #pragma unroll
                for (int no = 0; no < 4; ++no)
                    mma_bf16(c[mt][no], af[mt], bh[no]);
        }
        if (t + 1 < NT) s_store((t + 1) & 1);
    }

    const int erow = lane >> 2;
    const int ecol = (lane & 3) * 2;
    #pragma unroll
    for (int mt = 0; mt < 4; ++mt) {
        int r0 = m0 + wm + mt * 16 + erow;
        #pragma unroll
        for (int no = 0; no < 4; ++no) {
            int col = n0 + wn + no * 8 + ecol;
            float2 bv = *(const float2*)(bias + col);
            float2 o;
            o.x = c[mt][no][0] + bv.x;
            o.y = c[mt][no][1] + bv.y;
            *(float2*)(C + (size_t)r0 * N + col) = o;
            o.x = c[mt][no][2] + bv.x;
            o.y = c[mt][no][3] + bv.y;
            *(float2*)(C + (size_t)(r0 + 8) * N + col) = o;
        }
    }
}

// ---------------------------------------------------------------------------
// Scores via HMMA: per (b,h) 128x128 tile of S = Qh @ Kh^T, K-dim=64 loaded
// once. Epilogue: mask + exp + rowsum atomics + store unnormalized e to attn.
// Smem rows padded to 144B (9*16) => conflict-free ldmatrix.
// ---------------------------------------------------------------------------
#define SROWB 144
#define S_QH 0
#define S_QL 18432
#define S_KH 36864
#define S_KL 55296
#define SCORES_SMEM 73728

__global__ __launch_bounds__(256) void scores_mma_kernel(
    const float* __restrict__ qh, const float* __restrict__ kh,
    const int* __restrict__ mask, float* __restrict__ attn,
    float* __restrict__ rowsum)
{
    extern __shared__ char smem[];
    const uint32_t sbase = smem_u32(smem);
    const int tid = threadIdx.x;
    const int wid = tid >> 5;
    const int lane = tid & 31;
    const int p = blockIdx.z;
    const int b = p / HH;
    const int h = p % HH;
    const int q0 = blockIdx.y * 128;
    const int k0 = blockIdx.x * 128;

    // Load + convert Q and K tiles (128 x 64 each)
    {
        int row = tid >> 1;
        int cseg = (tid & 1) * 32;
        const float* Qp = qh + ((size_t)(b * LL + q0 + row)) * DD + h * DKK + cseg;
        const float* Kp = kh + ((size_t)(b * LL + k0 + row)) * DD + h * DKK + cseg;
        char* sm = smem;
        uint32_t ro = (uint32_t)row * SROWB + (uint32_t)cseg * 2;
        #pragma unroll
        for (int i = 0; i < 8; ++i) {
            float4 v = *(const float4*)(Qp + 4 * i);
            uint32_t h01, l01, h23, l23;
            split2(v.x, v.y, h01, l01);
            split2(v.z, v.w, h23, l23);
            *(uint32_t*)(sm + S_QH + ro + 8 * i)     = h01;
            *(uint32_t*)(sm + S_QH + ro + 8 * i + 4) = h23;
            *(uint32_t*)(sm + S_QL + ro + 8 * i)     = l01;
            *(uint32_t*)(sm + S_QL + ro + 8 * i + 4) = l23;
        }
        #pragma unroll
        for (int i = 0; i < 8; ++i) {
            float4 v = *(const float4*)(Kp + 4 * i);
            uint32_t h01, l01, h23, l23;
            split2(v.x, v.y, h01, l01);
            split2(v.z, v.w, h23, l23);
            *(uint32_t*)(sm + S_KH + ro + 8 * i)     = h01;
            *(uint32_t*)(sm + S_KH + ro + 8 * i + 4) = h23;
            *(uint32_t*)(sm + S_KL + ro + 8 * i)     = l01;
            *(uint32_t*)(sm + S_KL + ro + 8 * i + 4) = l23;
        }
    }
    __syncthreads();

    const int wm = (wid & 1) * 64;
    const int wn = (wid >> 1) * 32;

    float c[4][4][4];
    #pragma unroll
    for (int mt = 0; mt < 4; ++mt)
        #pragma unroll
        for (int no = 0; no < 4; ++no)
            #pragma unroll
            for (int e = 0; e < 4; ++e) c[mt][no][e] = 0.f;

    const uint32_t a_lrow = (uint32_t)(lane & 15);
    const uint32_t a_koff = (uint32_t)(lane >> 4) * 8;
    const uint32_t b_lrow = (uint32_t)((lane >> 4) * 8 + (lane & 7));
    const uint32_t b_koff = (uint32_t)((lane >> 3) & 1) * 8;

    #pragma unroll
    for (int ks = 0; ks < 4; ++ks) {
        const uint32_t kbyte = (uint32_t)(ks * 16 + a_koff) * 2;
        uint32_t af[4][4];
        #pragma unroll
        for (int mt = 0; mt < 4; ++mt)
            ldm_x4(af[mt], sbase + S_QH +
                   (uint32_t)(wm + mt * 16 + a_lrow) * SROWB + kbyte);

        const uint32_t bkb = (uint32_t)(ks * 16 + b_koff) * 2;
        uint32_t bh[4][2], bl[4][2];
        #pragma unroll
        for (int half = 0; half < 2; ++half) {
            uint32_t r[4];
            uint32_t nrow = (uint32_t)(wn + half * 16) + b_lrow;
            ldm_x4(r, sbase + S_KH + nrow * SROWB + bkb);
            bh[half * 2][0] = r[0]; bh[half * 2][1] = r[1];
            bh[half * 2 + 1][0] = r[2]; bh[half * 2 + 1][1] = r[3];
            ldm_x4(r, sbase + S_KL + nrow * SROWB + bkb);
            bl[half * 2][0] = r[0]; bl[half * 2][1] = r[1];
            bl[half * 2 + 1][0] = r[2]; bl[half * 2 + 1][1] = r[3];
        }

        #pragma unroll
        for (int mt = 0; mt < 4; ++mt)
            #pragma unroll
            for (int no = 0; no < 4; ++no)
                mma_bf16(c[mt][no], af[mt], bh[no]);
        #pragma unroll
        for (int mt = 0; mt < 4; ++mt)
            #pragma unroll
            for (int no = 0; no < 4; ++no)
                mma_bf16(c[mt][no], af[mt], bl[no]);

        #pragma unroll
        for (int mt = 0; mt < 4; ++mt)
            ldm_x4(af[mt], sbase + S_QL +
                   (uint32_t)(wm + mt * 16 + a_lrow) * SROWB + kbyte);
        #pragma unroll
        for (int mt = 0; mt < 4; ++mt)
            #pragma unroll
            for (int no = 0; no < 4; ++no)
                mma_bf16(c[mt][no], af[mt], bh[no]);
    }

    // Epilogue: mask + exp + rowsum + store
    const float scale = 1.0f / (float)DD;
    const size_t obase = (size_t)(h * BB + b) * LL * LL;
    float* rs = rowsum + (size_t)p * LL;
    const int erow = lane >> 2;
    const int ecol = (lane & 3) * 2;

    #pragma unroll
    for (int mt = 0; mt < 4; ++mt) {
        #pragma unroll
        for (int r2 = 0; r2 < 2; ++r2) {
            int row = wm + mt * 16 + erow + r2 * 8;
            int q = q0 + row;
            const int* mbase = mask + ((size_t)b * LL + q) * LL;
            float* obase_row = attn + obase + (size_t)q * LL;
            float rsum = 0.f;
            #pragma unroll
            for (int no = 0; no < 4; ++no) {
                int col = k0 + wn + no * 8 + ecol;
                int2 m = *(const int2*)(mbase + col);
                float e0 = m.x ? __expf(c[mt][no][r2 * 2 + 0] * scale) : 0.f;
                float e1 = m.y ? __expf(c[mt][no][r2 * 2 + 1] * scale) : 0.f;
                float2 o; o.x = e0; o.y = e1;
                *(float2*)(obase_row + col) = o;
                rsum += e0 + e1;
            }
            rsum += __shfl_xor_sync(0xffffffffu, rsum, 1);
            rsum += __shfl_xor_sync(0xffffffffu, rsum, 2);
            if ((lane & 3) == 0) atomicAdd(rs + q, rsum);
        }
    }
}

// ---------------------------------------------------------------------------
// AV via HMMA: ctx[128,64] = (P/rowsum) @ V per (b,h) tile; normalized P
// written back to attn during the streaming load. bf16 hi/lo 3-MMA split.
// ---------------------------------------------------------------------------
#define PROWB 80
#define AV_PH 0
#define AV_PL 10240
#define AV_VH 20480
#define AV_VL 25600
#define AV_BUF 30720
#define AV_SMEM (2*AV_BUF)

__global__ __launch_bounds__(256) void av_mma_kernel(
    float* __restrict__ attn, const float* __restrict__ vh,
    const float* __restrict__ rowsum, float* __restrict__ ctx)
{
    extern __shared__ char smem[];
    const uint32_t sbase = smem_u32(smem);
    const int tid = threadIdx.x;
    const int wid = tid >> 5;
    const int lane = tid & 31;
    const int p = blockIdx.y;
    const int b = p / HH;
    const int h = p % HH;
    const int m0 = blockIdx.x * 128;

    float* Pb = attn + (size_t)(h * BB + b) * LL * LL + (size_t)m0 * LL;
    const float* Vb = vh + (size_t)b * LL * DD + h * DKK;

    // P load mapping: row fixed per thread
    const int prow = tid >> 1;
    const int pcseg = (tid & 1) * 16;
    const float inv_r = 1.0f / rowsum[(size_t)p * LL + m0 + prow];
    // V load mapping
    const int vrow = tid >> 3;            // 0..31
    const int vcol = (tid & 7) * 8;       // 0..56

    float rp[16], rv[8];

    auto g_load = [&](int t) {
        float* Pp = Pb + (size_t)prow * LL + t * 32 + pcseg;
        #pragma unroll
        for (int i = 0; i < 4; ++i) {
            float4 v = *(const float4*)(Pp + 4 * i);
            v.x *= inv_r; v.y *= inv_r; v.z *= inv_r; v.w *= inv_r;
            *(float4*)(rp + 4 * i) = v;
            *(float4*)(Pp + 4 * i) = v;   // write back normalized attn
        }
        const float* Vp = Vb + (size_t)(t * 32 + vrow) * DD + vcol;
        #pragma unroll
        for (int i = 0; i < 2; ++i)
            *(float4*)(rv + 4 * i) = *(const float4*)(Vp + 4 * i);
    };
    auto s_store = [&](int buf) {
        char* base = smem + buf * AV_BUF;
        uint32_t po = (uint32_t)prow * PROWB + (uint32_t)pcseg * 2;
        #pragma unroll
        for (int i = 0; i < 8; ++i) {
            uint32_t hi, lo;
            split2(rp[2 * i], rp[2 * i + 1], hi, lo);
            *(uint32_t*)(base + AV_PH + po + 4 * i) = hi;
            *(uint32_t*)(base + AV_PL + po + 4 * i) = lo;
        }
        // V transpose: [n][k], lane-rotated column order to avoid conflicts
        #pragma unroll
        for (int i = 0; i < 8; ++i) {
            int idx = (i + (lane & 7)) & 7;
            float x = rv[idx];
            __nv_bfloat16 hv = __float2bfloat16(x);
            float l = x - __bfloat162float(hv);
            __nv_bfloat16 lv = __float2bfloat16(l);
            uint32_t bo = (uint32_t)(vcol + idx) * PROWB + (uint32_t)vrow * 2;
            *(__nv_bfloat16*)(base + AV_VH + bo) = hv;
            *(__nv_bfloat16*)(base + AV_VL + bo) = lv;
        }
    };

    const int wm = (wid & 3) * 32;
    const int wn = (wid >> 2) * 32;

    float c[2][4][4];
    #pragma unroll
    for (int mt = 0; mt < 2; ++mt)
        #pragma unroll
        for (int no = 0; no < 4; ++no)
            #pragma unroll
            for (int e = 0; e < 4; ++e) c[mt][no][e] = 0.f;

    const uint32_t a_lrow = (uint32_t)(lane & 15);
    const uint32_t a_koff = (uint32_t)(lane >> 4) * 8;
    const uint32_t b_lrow = (uint32_t)((lane >> 4) * 8 + (lane & 7));
    const uint32_t b_koff = (uint32_t)((lane >> 3) & 1) * 8;

    const int NT = LL / 32;
    g_load(0);
    s_store(0);

    for (int t = 0; t < NT; ++t) {
        __syncthreads();
        const uint32_t bb = sbase + (uint32_t)(t & 1) * AV_BUF;
        if (t + 1 < NT) g_load(t + 1);

        #pragma unroll
        for (int ks = 0; ks < 2; ++ks) {
            const uint32_t kbyte = (uint32_t)(ks * 16 + a_koff) * 2;
            uint32_t af[2][4];
            #pragma unroll
            for (int mt = 0; mt < 2; ++mt)
                ldm_x4(af[mt], bb + AV_PH +
                       (uint32_t)(wm + mt * 16 + a_lrow) * PROWB + kbyte);

            const uint32_t bkb = (uint32_t)(ks * 16 + b_koff) * 2;
            uint32_t bhf[4][2], blf[4][2];
            #pragma unroll
            for (int half = 0; half < 2; ++half) {
                uint32_t r[4];
                uint32_t nrow = (uint32_t)(wn + half * 16) + b_lrow;
                ldm_x4(r, bb + AV_VH + nrow * PROWB + bkb);
                bhf[half * 2][0] = r[0]; bhf[half * 2][1] = r[1];
                bhf[half * 2 + 1][0] = r[2]; bhf[half * 2 + 1][1] = r[3];
                ldm_x4(r, bb + AV_VL + nrow * PROWB + bkb);
                blf[half * 2][0] = r[0]; blf[half * 2][1] = r[1];
                blf[half * 2 + 1][0] = r[2]; blf[half * 2 + 1][1] = r[3];
            }

            #pragma unroll
            for (int mt = 0; mt < 2; ++mt)
                #pragma unroll
                for (int no = 0; no < 4; ++no)
                    mma_bf16(c[mt][no], af[mt], bhf[no]);
            #pragma unroll
            for (int mt = 0; mt < 2; ++mt)
                #pragma unroll
                for (int no = 0; no < 4; ++no)
                    mma_bf16(c[mt][no], af[mt], blf[no]);

            #pragma unroll
            for (int mt = 0; mt < 2; ++mt)
                ldm_x4(af[mt], bb + AV_PL +
                       (uint32_t)(wm + mt * 16 + a_lrow) * PROWB + kbyte);
            #pragma unroll
            for (int mt = 0; mt < 2; ++mt)
                #pragma unroll
                for (int no = 0; no < 4; ++no)
                    mma_bf16(c[mt][no], af[mt], bhf[no]);
        }
        if (t + 1 < NT) s_store((t + 1) & 1);
    }

    // Epilogue: store ctx
    const int erow = lane >> 2;
    const int ecol = (lane & 3) * 2;
    #pragma unroll
    for (int mt = 0; mt < 2; ++mt) {
        #pragma unroll
        for (int r2 = 0; r2 < 2; ++r2) {
            int row = wm + mt * 16 + erow + r2 * 8;
            int q = m0 + row;
            float* cp = ctx + ((size_t)b * LL + q) * DD + h * DKK;
            #pragma unroll
            for (int no = 0; no < 4; ++no) {
                int col = wn + no * 8 + ecol;
                float2 o;
                o.x = c[mt][no][r2 * 2 + 0];
                o.y = c[mt][no][r2 * 2 + 1];
                *(float2*)(cp + col) = o;
            }
        }
    }
}

// ---------------------------------------------------------------------------
extern "C" void kernel_launch(void* const* d_in, const int* in_sizes, int n_in,
                              void* d_out, int out_size)
{
    const float* q    = (const float*)d_in[0];
    const float* k    = (const float*)d_in[1];
    const float* v    = (const float*)d_in[2];
    const int*   mask = (const int*)d_in[3];
    const float* Wq   = (const float*)d_in[4];
    const float* bq   = (const float*)d_in[5];
    const float* Wk   = (const float*)d_in[6];
    const float* bk   = (const float*)d_in[7];
    const float* Wv   = (const float*)d_in[8];
    const float* bv   = (const float*)d_in[9];
    const float* Wo   = (const float*)d_in[10];
    const float* bo   = (const float*)d_in[11];

    float* out  = (float*)d_out;
    float* attn = out + (size_t)BB * LL * DD;

    float *qh, *kh, *vh, *ctx, *rowsum;
    cudaGetSymbolAddress((void**)&qh, g_qh);
    cudaGetSymbolAddress((void**)&kh, g_kh);
    cudaGetSymbolAddress((void**)&vh, g_vh);
    cudaGetSymbolAddress((void**)&ctx, g_ctx);
    cudaGetSymbolAddress((void**)&rowsum, g_rowsum);

    const int M = BB * LL;  // 4096

    static int smem_set = 0;
    if (!smem_set) {
        cudaFuncSetAttribute(gemm_mma_kernel,
                             cudaFuncAttributeMaxDynamicSharedMemorySize,
                             GEMM_SMEM);
        cudaFuncSetAttribute(scores_mma_kernel,
                             cudaFuncAttributeMaxDynamicSharedMemorySize,
                             SCORES_SMEM);
        cudaFuncSetAttribute(av_mma_kernel,
                             cudaFuncAttributeMaxDynamicSharedMemorySize,
                             AV_SMEM);
        smem_set = 1;
    }

    zero_kernel<<<(NP * LL + 255) / 256, 256>>>(rowsum, NP * LL);

    dim3 gproj(DD / 128, M / 128);  // (8, 32)
    gemm_mma_kernel<<<gproj, 256, GEMM_SMEM>>>(q, Wq, bq, qh, M, DD, DD);
    gemm_mma_kernel<<<gproj, 256, GEMM_SMEM>>>(k, Wk, bk, kh, M, DD, DD);
    gemm_mma_kernel<<<gproj, 256, GEMM_SMEM>>>(v, Wv, bv, vh, M, DD, DD);

    dim3 gsc(LL / 128, LL / 128, NP);  // (16,16,32)
    scores_mma_kernel<<<gsc, 256, SCORES_SMEM>>>(qh, kh, mask, attn, rowsum);

    dim3 gav(LL / 128, NP);  // (16, 32)
    av_mma_kernel<<<gav, 256, AV_SMEM>>>(attn, vh, rowsum, ctx);

    gemm_mma_kernel<<<gproj, 256, GEMM_SMEM>>>(ctx, Wo, bo, out, M, DD, DD);
}

// round 9
// speedup vs baseline: 1.7425x; 1.1499x over previous
#include <cuda_runtime.h>
#include <cuda_bf16.h>
#include <cstdint>

#define BB 2
#define LL 2048
#define DD 1024
#define HH 16
#define DKK 64
#define NP (BB*HH)

// Scratch (__device__ globals — no runtime allocation)
__device__ float g_qh[(size_t)BB * LL * DD];
__device__ float g_kh[(size_t)BB * LL * DD];
__device__ float g_vh[(size_t)BB * LL * DD];
__device__ float g_rowsum[(size_t)NP * LL];
// bf16 hi/lo staging, reused sequentially (stream-ordered)
__device__ __nv_bfloat16 g_ah[(size_t)BB * LL * DD];
__device__ __nv_bfloat16 g_al[(size_t)BB * LL * DD];
__device__ __nv_bfloat16 g_bh[(size_t)DD * DD];
__device__ __nv_bfloat16 g_bl[(size_t)DD * DD];

// ---- warp-MMA helpers -----------------------------------------------------
__device__ __forceinline__ uint32_t smem_u32(const void* p) {
    uint32_t a;
    asm("{ .reg .u64 t; cvta.to.shared.u64 t, %1; cvt.u32.u64 %0, t; }"
        : "=r"(a) : "l"(p));
    return a;
}
__device__ __forceinline__ void ldm_x4(uint32_t* r, uint32_t addr) {
    asm volatile("ldmatrix.sync.aligned.m8n8.x4.shared.b16 {%0,%1,%2,%3}, [%4];"
                 : "=r"(r[0]), "=r"(r[1]), "=r"(r[2]), "=r"(r[3]) : "r"(addr));
}
__device__ __forceinline__ void mma_bf16(float* c, const uint32_t* a,
                                         const uint32_t* b) {
    asm volatile(
        "mma.sync.aligned.m16n8k16.row.col.f32.bf16.bf16.f32 "
        "{%0,%1,%2,%3}, {%4,%5,%6,%7}, {%8,%9}, {%0,%1,%2,%3};"
        : "+f"(c[0]), "+f"(c[1]), "+f"(c[2]), "+f"(c[3])
        : "r"(a[0]), "r"(a[1]), "r"(a[2]), "r"(a[3]), "r"(b[0]), "r"(b[1]));
}
__device__ __forceinline__ void split2(float x, float y, uint32_t& hi, uint32_t& lo) {
    __nv_bfloat16 hx = __float2bfloat16(x);
    __nv_bfloat16 hy = __float2bfloat16(y);
    float lx = x - __bfloat162float(hx);
    float ly = y - __bfloat162float(hy);
    __nv_bfloat162 hp; hp.x = hx; hp.y = hy;
    __nv_bfloat162 lp = __floats2bfloat162_rn(lx, ly);
    hi = *(uint32_t*)&hp;
    lo = *(uint32_t*)&lp;
}
__device__ __forceinline__ void cpasync16(uint32_t sdst, const void* gsrc) {
    asm volatile("cp.async.ca.shared.global [%0], [%1], 16;"
                 :: "r"(sdst), "l"(gsrc));
}

// ---------------------------------------------------------------------------
__global__ void zero_kernel(float* p, int n) {
    int i = blockIdx.x * blockDim.x + threadIdx.x;
    if (i < n) p[i] = 0.f;
}

// Elementwise fp32 -> bf16 hi/lo (row-major preserved). n4 = elems/4.
__global__ __launch_bounds__(256) void conv_a_kernel(
    const float* __restrict__ A, __nv_bfloat16* __restrict__ Ah,
    __nv_bfloat16* __restrict__ Al, int n4)
{
    int i = blockIdx.x * blockDim.x + threadIdx.x;
    if (i >= n4) return;
    float4 v = *(const float4*)(A + (size_t)i * 4);
    uint32_t h01, l01, h23, l23;
    split2(v.x, v.y, h01, l01);
    split2(v.z, v.w, h23, l23);
    uint32_t* ph = (uint32_t*)Ah + (size_t)i * 2;
    uint32_t* pl = (uint32_t*)Al + (size_t)i * 2;
    ph[0] = h01; ph[1] = h23;
    pl[0] = l01; pl[1] = l23;
}

// Transpose + split: W[K][N] fp32 -> WT_h/WT_l [N][K] bf16. 32x32 tiles.
__global__ __launch_bounds__(256) void conv_wt_kernel(
    const float* __restrict__ W, __nv_bfloat16* __restrict__ Th,
    __nv_bfloat16* __restrict__ Tl, int K, int N)
{
    __shared__ float ts[32][33];
    int k0 = blockIdx.y * 32;
    int n0 = blockIdx.x * 32;
    int tx = threadIdx.x & 31;
    int ty = threadIdx.x >> 5;   // 0..7
    #pragma unroll
    for (int i = 0; i < 4; ++i) {
        int k = ty + i * 8;
        ts[k][tx] = W[(size_t)(k0 + k) * N + n0 + tx];
    }
    __syncthreads();
    #pragma unroll
    for (int i = 0; i < 4; ++i) {
        int n = ty + i * 8;
        float x = ts[tx][n];
        __nv_bfloat16 h = __float2bfloat16(x);
        float l = x - __bfloat162float(h);
        Th[(size_t)(n0 + n) * K + k0 + tx] = h;
        Tl[(size_t)(n0 + n) * K + k0 + tx] = __float2bfloat16(l);
    }
}

// ---------------------------------------------------------------------------
// Pure-bf16 HMMA GEMM with cp.async pipeline.
// C[M,N] = A*W + bias where Ah/Al are [M][K] bf16 and Bh/Bl are W^T [N][K].
// 128x128 tile, BK=32, 8 warps (2x4) each 64x32, 3-MMA hi/lo split.
// smem: XOR-swizzled 64B rows (4x16B chunks, chunk c ^= row&3).
// ---------------------------------------------------------------------------
#define GA_H 0
#define GA_L 8192
#define GB_H 16384
#define GB_L 24576
#define GBUF 32768
#define GEMM_SMEM (2*GBUF)

__global__ __launch_bounds__(256, 2) void gemm_bf16_kernel(
    const __nv_bfloat16* __restrict__ Ah, const __nv_bfloat16* __restrict__ Al,
    const __nv_bfloat16* __restrict__ Bh, const __nv_bfloat16* __restrict__ Bl,
    const float* __restrict__ bias, float* __restrict__ C,
    int M, int N, int K)
{
    extern __shared__ char smem[];
    const uint32_t sbase = smem_u32(smem);
    const int tid  = threadIdx.x;
    const int wid  = tid >> 5;
    const int lane = tid & 31;
    const int m0 = blockIdx.y * 128;
    const int n0 = blockIdx.x * 128;
    const int wm = (wid & 1) * 64;
    const int wn = (wid >> 1) * 32;

    float c[4][4][4];
    #pragma unroll
    for (int mt = 0; mt < 4; ++mt)
        #pragma unroll
        for (int no = 0; no < 4; ++no)
            #pragma unroll
            for (int e = 0; e < 4; ++e) c[mt][no][e] = 0.f;

    // two 16B chunks per thread per array
    const int j0 = tid * 2;
    auto issue = [&](int t) {
        uint32_t sb = sbase + (uint32_t)(t & 1) * GBUF;
        #pragma unroll
        for (int i = 0; i < 2; ++i) {
            int j = j0 + i;
            int r = j >> 2;
            int cch = j & 3;
            uint32_t sw = (uint32_t)r * 64 + (uint32_t)((cch ^ (r & 3)) << 4);
            size_t ga = (size_t)(m0 + r) * K + t * 32 + cch * 8;
            size_t gb = (size_t)(n0 + r) * K + t * 32 + cch * 8;
            cpasync16(sb + GA_H + sw, Ah + ga);
            cpasync16(sb + GA_L + sw, Al + ga);
            cpasync16(sb + GB_H + sw, Bh + gb);
            cpasync16(sb + GB_L + sw, Bl + gb);
        }
        asm volatile("cp.async.commit_group;" ::: "memory");
    };

    const uint32_t a_lrow = (uint32_t)(lane & 15);
    const uint32_t a_cc   = (uint32_t)(lane >> 4);        // chunk half for A
    const uint32_t b_lrow = (uint32_t)((lane >> 4) * 8 + (lane & 7));
    const uint32_t b_cc   = (uint32_t)((lane >> 3) & 1);  // chunk half for B

    const int NT = K / 32;
    issue(0);
    issue(1);

    for (int t = 0; t < NT; ++t) {
        if (t + 1 < NT)
            asm volatile("cp.async.wait_group 1;" ::: "memory");
        else
            asm volatile("cp.async.wait_group 0;" ::: "memory");
        __syncthreads();

        const uint32_t bb = sbase + (uint32_t)(t & 1) * GBUF;

        #pragma unroll
        for (int ks = 0; ks < 2; ++ks) {
            uint32_t af[4][4];
            #pragma unroll
            for (int mt = 0; mt < 4; ++mt) {
                uint32_t row = (uint32_t)(wm + mt * 16) + a_lrow;
                uint32_t cch = (uint32_t)(ks * 2) + a_cc;
                ldm_x4(af[mt], bb + GA_H + row * 64 + ((cch ^ (row & 3)) << 4));
            }
            uint32_t bh[4][2], bl[4][2];
            #pragma unroll
            for (int half = 0; half < 2; ++half) {
                uint32_t r[4];
                uint32_t nrow = (uint32_t)(wn + half * 16) + b_lrow;
                uint32_t cch = (uint32_t)(ks * 2) + b_cc;
                uint32_t sw = nrow * 64 + ((cch ^ (nrow & 3)) << 4);
                ldm_x4(r, bb + GB_H + sw);
                bh[half * 2][0] = r[0]; bh[half * 2][1] = r[1];
                bh[half * 2 + 1][0] = r[2]; bh[half * 2 + 1][1] = r[3];
                ldm_x4(r, bb + GB_L + sw);
                bl[half * 2][0] = r[0]; bl[half * 2][1] = r[1];
                bl[half * 2 + 1][0] = r[2]; bl[half * 2 + 1][1] = r[3];
            }

            #pragma unroll
            for (int mt = 0; mt < 4; ++mt)
                #pragma unroll
                for (int no = 0; no < 4; ++no)
                    mma_bf16(c[mt][no], af[mt], bh[no]);
            #pragma unroll
            for (int mt = 0; mt < 4; ++mt)
                #pragma unroll
                for (int no = 0; no < 4; ++no)
                    mma_bf16(c[mt][no], af[mt], bl[no]);

            #pragma unroll
            for (int mt = 0; mt < 4; ++mt) {
                uint32_t row = (uint32_t)(wm + mt * 16) + a_lrow;
                uint32_t cch = (uint32_t)(ks * 2) + a_cc;
                ldm_x4(af[mt], bb + GA_L + row * 64 + ((cch ^ (row & 3)) << 4));
            }
            #pragma unroll
            for (int mt = 0; mt < 4; ++mt)
                #pragma unroll
                for (int no = 0; no < 4; ++no)
                    mma_bf16(c[mt][no], af[mt], bh[no]);
        }

        if (t + 2 < NT) {
            __syncthreads();
            issue(t + 2);
        }
    }

    const int erow = lane >> 2;
    const int ecol = (lane & 3) * 2;
    #pragma unroll
    for (int mt = 0; mt < 4; ++mt) {
        int r0 = m0 + wm + mt * 16 + erow;
        #pragma unroll
        for (int no = 0; no < 4; ++no) {
            int col = n0 + wn + no * 8 + ecol;
            float2 bv = *(const float2*)(bias + col);
            float2 o;
            o.x = c[mt][no][0] + bv.x;
            o.y = c[mt][no][1] + bv.y;
            *(float2*)(C + (size_t)r0 * N + col) = o;
            o.x = c[mt][no][2] + bv.x;
            o.y = c[mt][no][3] + bv.y;
            *(float2*)(C + (size_t)(r0 + 8) * N + col) = o;
        }
    }
}

// ---------------------------------------------------------------------------
// Scores via HMMA (unchanged R8): S = Qh@Kh^T, epilogue mask+exp+rowsum.
// ---------------------------------------------------------------------------
#define SROWB 144
#define S_QH 0
#define S_QL 18432
#define S_KH 36864
#define S_KL 55296
#define SCORES_SMEM 73728

__global__ __launch_bounds__(256) void scores_mma_kernel(
    const float* __restrict__ qh, const float* __restrict__ kh,
    const int* __restrict__ mask, float* __restrict__ attn,
    float* __restrict__ rowsum)
{
    extern __shared__ char smem[];
    const uint32_t sbase = smem_u32(smem);
    const int tid = threadIdx.x;
    const int wid = tid >> 5;
    const int lane = tid & 31;
    const int p = blockIdx.z;
    const int b = p / HH;
    const int h = p % HH;
    const int q0 = blockIdx.y * 128;
    const int k0 = blockIdx.x * 128;

    {
        int row = tid >> 1;
        int cseg = (tid & 1) * 32;
        const float* Qp = qh + ((size_t)(b * LL + q0 + row)) * DD + h * DKK + cseg;
        const float* Kp = kh + ((size_t)(b * LL + k0 + row)) * DD + h * DKK + cseg;
        char* sm = smem;
        uint32_t ro = (uint32_t)row * SROWB + (uint32_t)cseg * 2;
        #pragma unroll
        for (int i = 0; i < 8; ++i) {
            float4 v = *(const float4*)(Qp + 4 * i);
            uint32_t h01, l01, h23, l23;
            split2(v.x, v.y, h01, l01);
            split2(v.z, v.w, h23, l23);
            *(uint32_t*)(sm + S_QH + ro + 8 * i)     = h01;
            *(uint32_t*)(sm + S_QH + ro + 8 * i + 4) = h23;
            *(uint32_t*)(sm + S_QL + ro + 8 * i)     = l01;
            *(uint32_t*)(sm + S_QL + ro + 8 * i + 4) = l23;
        }
        #pragma unroll
        for (int i = 0; i < 8; ++i) {
            float4 v = *(const float4*)(Kp + 4 * i);
            uint32_t h01, l01, h23, l23;
            split2(v.x, v.y, h01, l01);
            split2(v.z, v.w, h23, l23);
            *(uint32_t*)(sm + S_KH + ro + 8 * i)     = h01;
            *(uint32_t*)(sm + S_KH + ro + 8 * i + 4) = h23;
            *(uint32_t*)(sm + S_KL + ro + 8 * i)     = l01;
            *(uint32_t*)(sm + S_KL + ro + 8 * i + 4) = l23;
        }
    }
    __syncthreads();

    const int wm = (wid & 1) * 64;
    const int wn = (wid >> 1) * 32;

    float c[4][4][4];
    #pragma unroll
    for (int mt = 0; mt < 4; ++mt)
        #pragma unroll
        for (int no = 0; no < 4; ++no)
            #pragma unroll
            for (int e = 0; e < 4; ++e) c[mt][no][e] = 0.f;

    const uint32_t a_lrow = (uint32_t)(lane & 15);
    const uint32_t a_koff = (uint32_t)(lane >> 4) * 8;
    const uint32_t b_lrow = (uint32_t)((lane >> 4) * 8 + (lane & 7));
    const uint32_t b_koff = (uint32_t)((lane >> 3) & 1) * 8;

    #pragma unroll
    for (int ks = 0; ks < 4; ++ks) {
        const uint32_t kbyte = (uint32_t)(ks * 16 + a_koff) * 2;
        uint32_t af[4][4];
        #pragma unroll
        for (int mt = 0; mt < 4; ++mt)
            ldm_x4(af[mt], sbase + S_QH +
                   (uint32_t)(wm + mt * 16 + a_lrow) * SROWB + kbyte);

        const uint32_t bkb = (uint32_t)(ks * 16 + b_koff) * 2;
        uint32_t bh[4][2], bl[4][2];
        #pragma unroll
        for (int half = 0; half < 2; ++half) {
            uint32_t r[4];
            uint32_t nrow = (uint32_t)(wn + half * 16) + b_lrow;
            ldm_x4(r, sbase + S_KH + nrow * SROWB + bkb);
            bh[half * 2][0] = r[0]; bh[half * 2][1] = r[1];
            bh[half * 2 + 1][0] = r[2]; bh[half * 2 + 1][1] = r[3];
            ldm_x4(r, sbase + S_KL + nrow * SROWB + bkb);
            bl[half * 2][0] = r[0]; bl[half * 2][1] = r[1];
            bl[half * 2 + 1][0] = r[2]; bl[half * 2 + 1][1] = r[3];
        }

        #pragma unroll
        for (int mt = 0; mt < 4; ++mt)
            #pragma unroll
            for (int no = 0; no < 4; ++no)
                mma_bf16(c[mt][no], af[mt], bh[no]);
        #pragma unroll
        for (int mt = 0; mt < 4; ++mt)
            #pragma unroll
            for (int no = 0; no < 4; ++no)
                mma_bf16(c[mt][no], af[mt], bl[no]);

        #pragma unroll
        for (int mt = 0; mt < 4; ++mt)
            ldm_x4(af[mt], sbase + S_QL +
                   (uint32_t)(wm + mt * 16 + a_lrow) * SROWB + kbyte);
        #pragma unroll
        for (int mt = 0; mt < 4; ++mt)
            #pragma unroll
            for (int no = 0; no < 4; ++no)
                mma_bf16(c[mt][no], af[mt], bh[no]);
    }

    const float scale = 1.0f / (float)DD;
    const size_t obase = (size_t)(h * BB + b) * LL * LL;
    float* rs = rowsum + (size_t)p * LL;
    const int erow = lane >> 2;
    const int ecol = (lane & 3) * 2;

    #pragma unroll
    for (int mt = 0; mt < 4; ++mt) {
        #pragma unroll
        for (int r2 = 0; r2 < 2; ++r2) {
            int row = wm + mt * 16 + erow + r2 * 8;
            int q = q0 + row;
            const int* mbase = mask + ((size_t)b * LL + q) * LL;
            float* obase_row = attn + obase + (size_t)q * LL;
            float rsum = 0.f;
            #pragma unroll
            for (int no = 0; no < 4; ++no) {
                int col = k0 + wn + no * 8 + ecol;
                int2 m = *(const int2*)(mbase + col);
                float e0 = m.x ? __expf(c[mt][no][r2 * 2 + 0] * scale) : 0.f;
                float e1 = m.y ? __expf(c[mt][no][r2 * 2 + 1] * scale) : 0.f;
                float2 o; o.x = e0; o.y = e1;
                *(float2*)(obase_row + col) = o;
                rsum += e0 + e1;
            }
            rsum += __shfl_xor_sync(0xffffffffu, rsum, 1);
            rsum += __shfl_xor_sync(0xffffffffu, rsum, 2);
            if ((lane & 3) == 0) atomicAdd(rs + q, rsum);
        }
    }
}

// ---------------------------------------------------------------------------
// AV via HMMA: ctx = (P/rowsum)@V; normalized P written back. Epilogue now
// writes ctx directly as bf16 hi/lo (feeds the output GEMM, no fp32 pass).
// ---------------------------------------------------------------------------
#define PROWB 80
#define AV_PH 0
#define AV_PL 10240
#define AV_VH 20480
#define AV_VL 25600
#define AV_BUF 30720
#define AV_SMEM (2*AV_BUF)

__global__ __launch_bounds__(256) void av_mma_kernel(
    float* __restrict__ attn, const float* __restrict__ vh,
    const float* __restrict__ rowsum,
    __nv_bfloat16* __restrict__ ctx_h, __nv_bfloat16* __restrict__ ctx_l)
{
    extern __shared__ char smem[];
    const uint32_t sbase = smem_u32(smem);
    const int tid = threadIdx.x;
    const int wid = tid >> 5;
    const int lane = tid & 31;
    const int p = blockIdx.y;
    const int b = p / HH;
    const int h = p % HH;
    const int m0 = blockIdx.x * 128;

    float* Pb = attn + (size_t)(h * BB + b) * LL * LL + (size_t)m0 * LL;
    const float* Vb = vh + (size_t)b * LL * DD + h * DKK;

    const int prow = tid >> 1;
    const int pcseg = (tid & 1) * 16;
    const float inv_r = 1.0f / rowsum[(size_t)p * LL + m0 + prow];
    const int vrow = tid >> 3;
    const int vcol = (tid & 7) * 8;

    float rp[16], rv[8];

    auto g_load = [&](int t) {
        float* Pp = Pb + (size_t)prow * LL + t * 32 + pcseg;
        #pragma unroll
        for (int i = 0; i < 4; ++i) {
            float4 v = *(const float4*)(Pp + 4 * i);
            v.x *= inv_r; v.y *= inv_r; v.z *= inv_r; v.w *= inv_r;
            *(float4*)(rp + 4 * i) = v;
            *(float4*)(Pp + 4 * i) = v;
        }
        const float* Vp = Vb + (size_t)(t * 32 + vrow) * DD + vcol;
        #pragma unroll
        for (int i = 0; i < 2; ++i)
            *(float4*)(rv + 4 * i) = *(const float4*)(Vp + 4 * i);
    };
    auto s_store = [&](int buf) {
        char* base = smem + buf * AV_BUF;
        uint32_t po = (uint32_t)prow * PROWB + (uint32_t)pcseg * 2;
        #pragma unroll
        for (int i = 0; i < 8; ++i) {
            uint32_t hi, lo;
            split2(rp[2 * i], rp[2 * i + 1], hi, lo);
            *(uint32_t*)(base + AV_PH + po + 4 * i) = hi;
            *(uint32_t*)(base + AV_PL + po + 4 * i) = lo;
        }
        #pragma unroll
        for (int i = 0; i < 8; ++i) {
            int idx = (i + (lane & 7)) & 7;
            float x = rv[idx];
            __nv_bfloat16 hv = __float2bfloat16(x);
            float l = x - __bfloat162float(hv);
            __nv_bfloat16 lv = __float2bfloat16(l);
            uint32_t bo = (uint32_t)(vcol + idx) * PROWB + (uint32_t)vrow * 2;
            *(__nv_bfloat16*)(base + AV_VH + bo) = hv;
            *(__nv_bfloat16*)(base + AV_VL + bo) = lv;
        }
    };

    const int wm = (wid & 3) * 32;
    const int wn = (wid >> 2) * 32;

    float c[2][4][4];
    #pragma unroll
    for (int mt = 0; mt < 2; ++mt)
        #pragma unroll
        for (int no = 0; no < 4; ++no)
            #pragma unroll
            for (int e = 0; e < 4; ++e) c[mt][no][e] = 0.f;

    const uint32_t a_lrow = (uint32_t)(lane & 15);
    const uint32_t a_koff = (uint32_t)(lane >> 4) * 8;
    const uint32_t b_lrow = (uint32_t)((lane >> 4) * 8 + (lane & 7));
    const uint32_t b_koff = (uint32_t)((lane >> 3) & 1) * 8;

    const int NT = LL / 32;
    g_load(0);
    s_store(0);

    for (int t = 0; t < NT; ++t) {
        __syncthreads();
        const uint32_t bb = sbase + (uint32_t)(t & 1) * AV_BUF;
        if (t + 1 < NT) g_load(t + 1);

        #pragma unroll
        for (int ks = 0; ks < 2; ++ks) {
            const uint32_t kbyte = (uint32_t)(ks * 16 + a_koff) * 2;
            uint32_t af[2][4];
            #pragma unroll
            for (int mt = 0; mt < 2; ++mt)
                ldm_x4(af[mt], bb + AV_PH +
                       (uint32_t)(wm + mt * 16 + a_lrow) * PROWB + kbyte);

            const uint32_t bkb = (uint32_t)(ks * 16 + b_koff) * 2;
            uint32_t bhf[4][2], blf[4][2];
            #pragma unroll
            for (int half = 0; half < 2; ++half) {
                uint32_t r[4];
                uint32_t nrow = (uint32_t)(wn + half * 16) + b_lrow;
                ldm_x4(r, bb + AV_VH + nrow * PROWB + bkb);
                bhf[half * 2][0] = r[0]; bhf[half * 2][1] = r[1];
                bhf[half * 2 + 1][0] = r[2]; bhf[half * 2 + 1][1] = r[3];
                ldm_x4(r, bb + AV_VL + nrow * PROWB + bkb);
                blf[half * 2][0] = r[0]; blf[half * 2][1] = r[1];
                blf[half * 2 + 1][0] = r[2]; blf[half * 2 + 1][1] = r[3];
            }

            #pragma unroll
            for (int mt = 0; mt < 2; ++mt)
                #pragma unroll
                for (int no = 0; no < 4; ++no)
                    mma_bf16(c[mt][no], af[mt], bhf[no]);
            #pragma unroll
            for (int mt = 0; mt < 2; ++mt)
                #pragma unroll
                for (int no = 0; no < 4; ++no)
                    mma_bf16(c[mt][no], af[mt], blf[no]);

            #pragma unroll
            for (int mt = 0; mt < 2; ++mt)
                ldm_x4(af[mt], bb + AV_PL +
                       (uint32_t)(wm + mt * 16 + a_lrow) * PROWB + kbyte);
            #pragma unroll
            for (int mt = 0; mt < 2; ++mt)
                #pragma unroll
                for (int no = 0; no < 4; ++no)
                    mma_bf16(c[mt][no], af[mt], bhf[no]);
        }
        if (t + 1 < NT) s_store((t + 1) & 1);
    }

    // Epilogue: write ctx as bf16 hi/lo
    const int erow = lane >> 2;
    const int ecol = (lane & 3) * 2;
    #pragma unroll
    for (int mt = 0; mt < 2; ++mt) {
        #pragma unroll
        for (int r2 = 0; r2 < 2; ++r2) {
            int row = wm + mt * 16 + erow + r2 * 8;
            int q = m0 + row;
            size_t base = ((size_t)b * LL + q) * DD + h * DKK;
            #pragma unroll
            for (int no = 0; no < 4; ++no) {
                int col = wn + no * 8 + ecol;
                uint32_t hi, lo;
                split2(c[mt][no][r2 * 2 + 0], c[mt][no][r2 * 2 + 1], hi, lo);
                *(uint32_t*)(ctx_h + base + col) = hi;
                *(uint32_t*)(ctx_l + base + col) = lo;
            }
        }
    }
}

// ---------------------------------------------------------------------------
extern "C" void kernel_launch(void* const* d_in, const int* in_sizes, int n_in,
                              void* d_out, int out_size)
{
    const float* q    = (const float*)d_in[0];
    const float* k    = (const float*)d_in[1];
    const float* v    = (const float*)d_in[2];
    const int*   mask = (const int*)d_in[3];
    const float* Wq   = (const float*)d_in[4];
    const float* bq   = (const float*)d_in[5];
    const float* Wk   = (const float*)d_in[6];
    const float* bk   = (const float*)d_in[7];
    const float* Wv   = (const float*)d_in[8];
    const float* bv   = (const float*)d_in[9];
    const float* Wo   = (const float*)d_in[10];
    const float* bo   = (const float*)d_in[11];

    float* out  = (float*)d_out;
    float* attn = out + (size_t)BB * LL * DD;

    float *qh, *kh, *vh, *rowsum;
    __nv_bfloat16 *ah, *al, *bh, *bl;
    cudaGetSymbolAddress((void**)&qh, g_qh);
    cudaGetSymbolAddress((void**)&kh, g_kh);
    cudaGetSymbolAddress((void**)&vh, g_vh);
    cudaGetSymbolAddress((void**)&rowsum, g_rowsum);
    cudaGetSymbolAddress((void**)&ah, g_ah);
    cudaGetSymbolAddress((void**)&al, g_al);
    cudaGetSymbolAddress((void**)&bh, g_bh);
    cudaGetSymbolAddress((void**)&bl, g_bl);

    const int M = BB * LL;  // 4096
    const int n4 = M * DD / 4;

    static int smem_set = 0;
    if (!smem_set) {
        cudaFuncSetAttribute(gemm_bf16_kernel,
                             cudaFuncAttributeMaxDynamicSharedMemorySize,
                             GEMM_SMEM);
        cudaFuncSetAttribute(scores_mma_kernel,
                             cudaFuncAttributeMaxDynamicSharedMemorySize,
                             SCORES_SMEM);
        cudaFuncSetAttribute(av_mma_kernel,
                             cudaFuncAttributeMaxDynamicSharedMemorySize,
                             AV_SMEM);
        smem_set = 1;
    }

    zero_kernel<<<(NP * LL + 255) / 256, 256>>>(rowsum, NP * LL);

    dim3 gproj(DD / 128, M / 128);          // (8, 32)
    dim3 gwt(DD / 32, DD / 32);             // (32, 32)
    const int cga = (n4 + 255) / 256;

    // Q projection
    conv_wt_kernel<<<gwt, 256>>>(Wq, bh, bl, DD, DD);
    conv_a_kernel<<<cga, 256>>>(q, ah, al, n4);
    gemm_bf16_kernel<<<gproj, 256, GEMM_SMEM>>>(ah, al, bh, bl, bq, qh, M, DD, DD);
    // K projection
    conv_wt_kernel<<<gwt, 256>>>(Wk, bh, bl, DD, DD);
    conv_a_kernel<<<cga, 256>>>(k, ah, al, n4);
    gemm_bf16_kernel<<<gproj, 256, GEMM_SMEM>>>(ah, al, bh, bl, bk, kh, M, DD, DD);
    // V projection
    conv_wt_kernel<<<gwt, 256>>>(Wv, bh, bl, DD, DD);
    conv_a_kernel<<<cga, 256>>>(v, ah, al, n4);
    gemm_bf16_kernel<<<gproj, 256, GEMM_SMEM>>>(ah, al, bh, bl, bv, vh, M, DD, DD);

    dim3 gsc(LL / 128, LL / 128, NP);       // (16,16,32)
    scores_mma_kernel<<<gsc, 256, SCORES_SMEM>>>(qh, kh, mask, attn, rowsum);

    dim3 gav(LL / 128, NP);                 // (16, 32)
    av_mma_kernel<<<gav, 256, AV_SMEM>>>(attn, vh, rowsum, ah, al);

    // Output projection (ctx already bf16 hi/lo in ah/al)
    conv_wt_kernel<<<gwt, 256>>>(Wo, bh, bl, DD, DD);
    gemm_bf16_kernel<<<gproj, 256, GEMM_SMEM>>>(ah, al, bh, bl, bo, out, M, DD, DD);
}

// round 10
// speedup vs baseline: 1.9826x; 1.1378x over previous
#include <cuda_runtime.h>
#include <cuda_bf16.h>
#include <cstdint>

#define BB 2
#define LL 2048
#define DD 1024
#define HH 16
#define DKK 64
#define NP (BB*HH)

// Scratch (__device__ globals — no runtime allocation)
__device__ float g_qh[(size_t)BB * LL * DD];
__device__ float g_kh[(size_t)BB * LL * DD];
__device__ float g_vh[(size_t)BB * LL * DD];
__device__ float g_rowsum[(size_t)NP * LL];
__device__ __nv_bfloat16 g_ah[(size_t)BB * LL * DD];
__device__ __nv_bfloat16 g_al[(size_t)BB * LL * DD];
__device__ __nv_bfloat16 g_bh[(size_t)DD * DD];
__device__ __nv_bfloat16 g_bl[(size_t)DD * DD];

// ---- warp-MMA helpers -----------------------------------------------------
__device__ __forceinline__ uint32_t smem_u32(const void* p) {
    uint32_t a;
    asm("{ .reg .u64 t; cvta.to.shared.u64 t, %1; cvt.u32.u64 %0, t; }"
        : "=r"(a) : "l"(p));
    return a;
}
__device__ __forceinline__ void ldm_x4(uint32_t* r, uint32_t addr) {
    asm volatile("ldmatrix.sync.aligned.m8n8.x4.shared.b16 {%0,%1,%2,%3}, [%4];"
                 : "=r"(r[0]), "=r"(r[1]), "=r"(r[2]), "=r"(r[3]) : "r"(addr));
}
__device__ __forceinline__ void mma_bf16(float* c, const uint32_t* a,
                                         const uint32_t* b) {
    asm volatile(
        "mma.sync.aligned.m16n8k16.row.col.f32.bf16.bf16.f32 "
        "{%0,%1,%2,%3}, {%4,%5,%6,%7}, {%8,%9}, {%0,%1,%2,%3};"
        : "+f"(c[0]), "+f"(c[1]), "+f"(c[2]), "+f"(c[3])
        : "r"(a[0]), "r"(a[1]), "r"(a[2]), "r"(a[3]), "r"(b[0]), "r"(b[1]));
}
__device__ __forceinline__ void split2(float x, float y, uint32_t& hi, uint32_t& lo) {
    __nv_bfloat16 hx = __float2bfloat16(x);
    __nv_bfloat16 hy = __float2bfloat16(y);
    float lx = x - __bfloat162float(hx);
    float ly = y - __bfloat162float(hy);
    __nv_bfloat162 hp; hp.x = hx; hp.y = hy;
    __nv_bfloat162 lp = __floats2bfloat162_rn(lx, ly);
    hi = *(uint32_t*)&hp;
    lo = *(uint32_t*)&lp;
}
__device__ __forceinline__ uint32_t bfpack(float x, float y) {
    __nv_bfloat162 t = __floats2bfloat162_rn(x, y);
    return *(uint32_t*)&t;
}
__device__ __forceinline__ void cpasync16(uint32_t sdst, const void* gsrc) {
    asm volatile("cp.async.ca.shared.global [%0], [%1], 16;"
                 :: "r"(sdst), "l"(gsrc));
}

// ---------------------------------------------------------------------------
__global__ void zero_kernel(float* p, int n) {
    int i = blockIdx.x * blockDim.x + threadIdx.x;
    if (i < n) p[i] = 0.f;
}

// fp32 -> bf16 hi/lo
__global__ __launch_bounds__(256) void conv_a_kernel(
    const float* __restrict__ A, __nv_bfloat16* __restrict__ Ah,
    __nv_bfloat16* __restrict__ Al, int n4)
{
    int i = blockIdx.x * blockDim.x + threadIdx.x;
    if (i >= n4) return;
    float4 v = *(const float4*)(A + (size_t)i * 4);
    uint32_t h01, l01, h23, l23;
    split2(v.x, v.y, h01, l01);
    split2(v.z, v.w, h23, l23);
    uint32_t* ph = (uint32_t*)Ah + (size_t)i * 2;
    uint32_t* pl = (uint32_t*)Al + (size_t)i * 2;
    ph[0] = h01; ph[1] = h23;
    pl[0] = l01; pl[1] = l23;
}
// fp32 -> bf16 (hi only)
__global__ __launch_bounds__(256) void conv_a_h_kernel(
    const float* __restrict__ A, __nv_bfloat16* __restrict__ Ah, int n4)
{
    int i = blockIdx.x * blockDim.x + threadIdx.x;
    if (i >= n4) return;
    float4 v = *(const float4*)(A + (size_t)i * 4);
    uint32_t* ph = (uint32_t*)Ah + (size_t)i * 2;
    ph[0] = bfpack(v.x, v.y);
    ph[1] = bfpack(v.z, v.w);
}

// Transpose + split: W[K][N] fp32 -> WT hi/lo [N][K] bf16.
template<int SPLIT>
__global__ __launch_bounds__(256) void conv_wt_kernel(
    const float* __restrict__ W, __nv_bfloat16* __restrict__ Th,
    __nv_bfloat16* __restrict__ Tl, int K, int N)
{
    __shared__ float ts[32][33];
    int k0 = blockIdx.y * 32;
    int n0 = blockIdx.x * 32;
    int tx = threadIdx.x & 31;
    int ty = threadIdx.x >> 5;
    #pragma unroll
    for (int i = 0; i < 4; ++i) {
        int k = ty + i * 8;
        ts[k][tx] = W[(size_t)(k0 + k) * N + n0 + tx];
    }
    __syncthreads();
    #pragma unroll
    for (int i = 0; i < 4; ++i) {
        int n = ty + i * 8;
        float x = ts[tx][n];
        __nv_bfloat16 h = __float2bfloat16(x);
        Th[(size_t)(n0 + n) * K + k0 + tx] = h;
        if (SPLIT == 3) {
            float l = x - __bfloat162float(h);
            Tl[(size_t)(n0 + n) * K + k0 + tx] = __float2bfloat16(l);
        }
    }
}

// ---------------------------------------------------------------------------
// bf16 HMMA GEMM, templated on SPLIT (3 = hi/lo 3-MMA, 1 = single bf16).
// C[M,N] = A*W + bias, Ah/Al [M][K], Bh/Bl = W^T [N][K].
// 128x128 tile, BK=32, 8 warps (2x4), cp.async 2-deep, XOR-swizzled 64B rows.
// ---------------------------------------------------------------------------
#define GA_H 0
#define GA_L 8192
#define GB_H 16384
#define GB_L 24576
#define GBUF 32768
#define GEMM_SMEM3 (2*GBUF)
// split1 layout: A at 0, B at 8192, buffer stride 16384
#define G1_B 8192
#define G1BUF 16384
#define GEMM_SMEM1 (2*G1BUF)

template<int SPLIT>
__global__ __launch_bounds__(256, 2) void gemm_bf16_kernel(
    const __nv_bfloat16* __restrict__ Ah, const __nv_bfloat16* __restrict__ Al,
    const __nv_bfloat16* __restrict__ Bh, const __nv_bfloat16* __restrict__ Bl,
    const float* __restrict__ bias, float* __restrict__ C,
    int M, int N, int K)
{
    extern __shared__ char smem[];
    const uint32_t sbase = smem_u32(smem);
    const int tid  = threadIdx.x;
    const int wid  = tid >> 5;
    const int lane = tid & 31;
    const int m0 = blockIdx.y * 128;
    const int n0 = blockIdx.x * 128;
    const int wm = (wid & 1) * 64;
    const int wn = (wid >> 1) * 32;

    const uint32_t BUFSTRIDE = (SPLIT == 3) ? GBUF : G1BUF;
    const uint32_t OFFB      = (SPLIT == 3) ? GB_H : G1_B;
    const uint32_t OFFBL     = GB_L;

    float c[4][4][4];
    #pragma unroll
    for (int mt = 0; mt < 4; ++mt)
        #pragma unroll
        for (int no = 0; no < 4; ++no)
            #pragma unroll
            for (int e = 0; e < 4; ++e) c[mt][no][e] = 0.f;

    const int j0 = tid * 2;
    auto issue = [&](int t) {
        uint32_t sb = sbase + (uint32_t)(t & 1) * BUFSTRIDE;
        #pragma unroll
        for (int i = 0; i < 2; ++i) {
            int j = j0 + i;
            int r = j >> 2;
            int cch = j & 3;
            uint32_t sw = (uint32_t)r * 64 + (uint32_t)((cch ^ (r & 3)) << 4);
            size_t ga = (size_t)(m0 + r) * K + t * 32 + cch * 8;
            size_t gb = (size_t)(n0 + r) * K + t * 32 + cch * 8;
            cpasync16(sb + GA_H + sw, Ah + ga);
            cpasync16(sb + OFFB + sw, Bh + gb);
            if (SPLIT == 3) {
                cpasync16(sb + GA_L + sw, Al + ga);
                cpasync16(sb + OFFBL + sw, Bl + gb);
            }
        }
        asm volatile("cp.async.commit_group;" ::: "memory");
    };

    const uint32_t a_lrow = (uint32_t)(lane & 15);
    const uint32_t a_cc   = (uint32_t)(lane >> 4);
    const uint32_t b_lrow = (uint32_t)((lane >> 4) * 8 + (lane & 7));
    const uint32_t b_cc   = (uint32_t)((lane >> 3) & 1);

    const int NT = K / 32;
    issue(0);
    issue(1);

    for (int t = 0; t < NT; ++t) {
        if (t + 1 < NT)
            asm volatile("cp.async.wait_group 1;" ::: "memory");
        else
            asm volatile("cp.async.wait_group 0;" ::: "memory");
        __syncthreads();

        const uint32_t bb = sbase + (uint32_t)(t & 1) * BUFSTRIDE;

        #pragma unroll
        for (int ks = 0; ks < 2; ++ks) {
            uint32_t af[4][4];
            #pragma unroll
            for (int mt = 0; mt < 4; ++mt) {
                uint32_t row = (uint32_t)(wm + mt * 16) + a_lrow;
                uint32_t cch = (uint32_t)(ks * 2) + a_cc;
                ldm_x4(af[mt], bb + GA_H + row * 64 + ((cch ^ (row & 3)) << 4));
            }
            uint32_t bh[4][2], bl[4][2];
            #pragma unroll
            for (int half = 0; half < 2; ++half) {
                uint32_t r[4];
                uint32_t nrow = (uint32_t)(wn + half * 16) + b_lrow;
                uint32_t cch = (uint32_t)(ks * 2) + b_cc;
                uint32_t sw = nrow * 64 + ((cch ^ (nrow & 3)) << 4);
                ldm_x4(r, bb + OFFB + sw);
                bh[half * 2][0] = r[0]; bh[half * 2][1] = r[1];
                bh[half * 2 + 1][0] = r[2]; bh[half * 2 + 1][1] = r[3];
                if (SPLIT == 3) {
                    ldm_x4(r, bb + OFFBL + sw);
                    bl[half * 2][0] = r[0]; bl[half * 2][1] = r[1];
                    bl[half * 2 + 1][0] = r[2]; bl[half * 2 + 1][1] = r[3];
                }
            }

            #pragma unroll
            for (int mt = 0; mt < 4; ++mt)
                #pragma unroll
                for (int no = 0; no < 4; ++no)
                    mma_bf16(c[mt][no], af[mt], bh[no]);

            if (SPLIT == 3) {
                #pragma unroll
                for (int mt = 0; mt < 4; ++mt)
                    #pragma unroll
                    for (int no = 0; no < 4; ++no)
                        mma_bf16(c[mt][no], af[mt], bl[no]);
                #pragma unroll
                for (int mt = 0; mt < 4; ++mt) {
                    uint32_t row = (uint32_t)(wm + mt * 16) + a_lrow;
                    uint32_t cch = (uint32_t)(ks * 2) + a_cc;
                    ldm_x4(af[mt], bb + GA_L + row * 64 + ((cch ^ (row & 3)) << 4));
                }
                #pragma unroll
                for (int mt = 0; mt < 4; ++mt)
                    #pragma unroll
                    for (int no = 0; no < 4; ++no)
                        mma_bf16(c[mt][no], af[mt], bh[no]);
            }
        }

        if (t + 2 < NT) {
            __syncthreads();
            issue(t + 2);
        }
    }

    const int erow = lane >> 2;
    const int ecol = (lane & 3) * 2;
    #pragma unroll
    for (int mt = 0; mt < 4; ++mt) {
        int r0 = m0 + wm + mt * 16 + erow;
        #pragma unroll
        for (int no = 0; no < 4; ++no) {
            int col = n0 + wn + no * 8 + ecol;
            float2 bv = *(const float2*)(bias + col);
            float2 o;
            o.x = c[mt][no][0] + bv.x;
            o.y = c[mt][no][1] + bv.y;
            *(float2*)(C + (size_t)r0 * N + col) = o;
            o.x = c[mt][no][2] + bv.x;
            o.y = c[mt][no][3] + bv.y;
            *(float2*)(C + (size_t)(r0 + 8) * N + col) = o;
        }
    }
}

// ---------------------------------------------------------------------------
// Scores via single-bf16 HMMA (error suppressed by /1024 scale):
// S = Qh@Kh^T per (b,h) 128x128 tile; epilogue mask+exp+rowsum+store.
// ---------------------------------------------------------------------------
#define SROWB 144
#define S_QH 0
#define S_KH 18432
#define SCORES_SMEM 36864

__global__ __launch_bounds__(256) void scores_mma_kernel(
    const float* __restrict__ qh, const float* __restrict__ kh,
    const int* __restrict__ mask, float* __restrict__ attn,
    float* __restrict__ rowsum)
{
    extern __shared__ char smem[];
    const uint32_t sbase = smem_u32(smem);
    const int tid = threadIdx.x;
    const int wid = tid >> 5;
    const int lane = tid & 31;
    const int p = blockIdx.z;
    const int b = p / HH;
    const int h = p % HH;
    const int q0 = blockIdx.y * 128;
    const int k0 = blockIdx.x * 128;

    {
        int row = tid >> 1;
        int cseg = (tid & 1) * 32;
        const float* Qp = qh + ((size_t)(b * LL + q0 + row)) * DD + h * DKK + cseg;
        const float* Kp = kh + ((size_t)(b * LL + k0 + row)) * DD + h * DKK + cseg;
        char* sm = smem;
        uint32_t ro = (uint32_t)row * SROWB + (uint32_t)cseg * 2;
        #pragma unroll
        for (int i = 0; i < 8; ++i) {
            float4 v = *(const float4*)(Qp + 4 * i);
            *(uint32_t*)(sm + S_QH + ro + 8 * i)     = bfpack(v.x, v.y);
            *(uint32_t*)(sm + S_QH + ro + 8 * i + 4) = bfpack(v.z, v.w);
        }
        #pragma unroll
        for (int i = 0; i < 8; ++i) {
            float4 v = *(const float4*)(Kp + 4 * i);
            *(uint32_t*)(sm + S_KH + ro + 8 * i)     = bfpack(v.x, v.y);
            *(uint32_t*)(sm + S_KH + ro + 8 * i + 4) = bfpack(v.z, v.w);
        }
    }
    __syncthreads();

    const int wm = (wid & 1) * 64;
    const int wn = (wid >> 1) * 32;

    float c[4][4][4];
    #pragma unroll
    for (int mt = 0; mt < 4; ++mt)
        #pragma unroll
        for (int no = 0; no < 4; ++no)
            #pragma unroll
            for (int e = 0; e < 4; ++e) c[mt][no][e] = 0.f;

    const uint32_t a_lrow = (uint32_t)(lane & 15);
    const uint32_t a_koff = (uint32_t)(lane >> 4) * 8;
    const uint32_t b_lrow = (uint32_t)((lane >> 4) * 8 + (lane & 7));
    const uint32_t b_koff = (uint32_t)((lane >> 3) & 1) * 8;

    #pragma unroll
    for (int ks = 0; ks < 4; ++ks) {
        const uint32_t kbyte = (uint32_t)(ks * 16 + a_koff) * 2;
        uint32_t af[4][4];
        #pragma unroll
        for (int mt = 0; mt < 4; ++mt)
            ldm_x4(af[mt], sbase + S_QH +
                   (uint32_t)(wm + mt * 16 + a_lrow) * SROWB + kbyte);

        const uint32_t bkb = (uint32_t)(ks * 16 + b_koff) * 2;
        uint32_t bh[4][2];
        #pragma unroll
        for (int half = 0; half < 2; ++half) {
            uint32_t r[4];
            uint32_t nrow = (uint32_t)(wn + half * 16) + b_lrow;
            ldm_x4(r, sbase + S_KH + nrow * SROWB + bkb);
            bh[half * 2][0] = r[0]; bh[half * 2][1] = r[1];
            bh[half * 2 + 1][0] = r[2]; bh[half * 2 + 1][1] = r[3];
        }

        #pragma unroll
        for (int mt = 0; mt < 4; ++mt)
            #pragma unroll
            for (int no = 0; no < 4; ++no)
                mma_bf16(c[mt][no], af[mt], bh[no]);
    }

    const float scale = 1.0f / (float)DD;
    const size_t obase = (size_t)(h * BB + b) * LL * LL;
    float* rs = rowsum + (size_t)p * LL;
    const int erow = lane >> 2;
    const int ecol = (lane & 3) * 2;

    #pragma unroll
    for (int mt = 0; mt < 4; ++mt) {
        #pragma unroll
        for (int r2 = 0; r2 < 2; ++r2) {
            int row = wm + mt * 16 + erow + r2 * 8;
            int q = q0 + row;
            const int* mbase = mask + ((size_t)b * LL + q) * LL;
            float* obase_row = attn + obase + (size_t)q * LL;
            float rsum = 0.f;
            #pragma unroll
            for (int no = 0; no < 4; ++no) {
                int col = k0 + wn + no * 8 + ecol;
                int2 m = *(const int2*)(mbase + col);
                float e0 = m.x ? __expf(c[mt][no][r2 * 2 + 0] * scale) : 0.f;
                float e1 = m.y ? __expf(c[mt][no][r2 * 2 + 1] * scale) : 0.f;
                float2 o; o.x = e0; o.y = e1;
                *(float2*)(obase_row + col) = o;
                rsum += e0 + e1;
            }
            rsum += __shfl_xor_sync(0xffffffffu, rsum, 1);
            rsum += __shfl_xor_sync(0xffffffffu, rsum, 2);
            if ((lane & 3) == 0) atomicAdd(rs + q, rsum);
        }
    }
}

// ---------------------------------------------------------------------------
// AV via HMMA hi/lo split (errors NOT suppressed here; keep 3-MMA).
// ctx written directly as bf16 hi/lo for the output GEMM.
// ---------------------------------------------------------------------------
#define PROWB 80
#define AV_PH 0
#define AV_PL 10240
#define AV_VH 20480
#define AV_VL 25600
#define AV_BUF 30720
#define AV_SMEM (2*AV_BUF)

__global__ __launch_bounds__(256) void av_mma_kernel(
    float* __restrict__ attn, const float* __restrict__ vh,
    const float* __restrict__ rowsum,
    __nv_bfloat16* __restrict__ ctx_h, __nv_bfloat16* __restrict__ ctx_l)
{
    extern __shared__ char smem[];
    const uint32_t sbase = smem_u32(smem);
    const int tid = threadIdx.x;
    const int wid = tid >> 5;
    const int lane = tid & 31;
    const int p = blockIdx.y;
    const int b = p / HH;
    const int h = p % HH;
    const int m0 = blockIdx.x * 128;

    float* Pb = attn + (size_t)(h * BB + b) * LL * LL + (size_t)m0 * LL;
    const float* Vb = vh + (size_t)b * LL * DD + h * DKK;

    const int prow = tid >> 1;
    const int pcseg = (tid & 1) * 16;
    const float inv_r = 1.0f / rowsum[(size_t)p * LL + m0 + prow];
    const int vrow = tid >> 3;
    const int vcol = (tid & 7) * 8;

    float rp[16], rv[8];

    auto g_load = [&](int t) {
        float* Pp = Pb + (size_t)prow * LL + t * 32 + pcseg;
        #pragma unroll
        for (int i = 0; i < 4; ++i) {
            float4 v = *(const float4*)(Pp + 4 * i);
            v.x *= inv_r; v.y *= inv_r; v.z *= inv_r; v.w *= inv_r;
            *(float4*)(rp + 4 * i) = v;
            *(float4*)(Pp + 4 * i) = v;
        }
        const float* Vp = Vb + (size_t)(t * 32 + vrow) * DD + vcol;
        #pragma unroll
        for (int i = 0; i < 2; ++i)
            *(float4*)(rv + 4 * i) = *(const float4*)(Vp + 4 * i);
    };
    auto s_store = [&](int buf) {
        char* base = smem + buf * AV_BUF;
        uint32_t po = (uint32_t)prow * PROWB + (uint32_t)pcseg * 2;
        #pragma unroll
        for (int i = 0; i < 8; ++i) {
            uint32_t hi, lo;
            split2(rp[2 * i], rp[2 * i + 1], hi, lo);
            *(uint32_t*)(base + AV_PH + po + 4 * i) = hi;
            *(uint32_t*)(base + AV_PL + po + 4 * i) = lo;
        }
        #pragma unroll
        for (int i = 0; i < 8; ++i) {
            int idx = (i + (lane & 7)) & 7;
            float x = rv[idx];
            __nv_bfloat16 hv = __float2bfloat16(x);
            float l = x - __bfloat162float(hv);
            __nv_bfloat16 lv = __float2bfloat16(l);
            uint32_t bo = (uint32_t)(vcol + idx) * PROWB + (uint32_t)vrow * 2;
            *(__nv_bfloat16*)(base + AV_VH + bo) = hv;
            *(__nv_bfloat16*)(base + AV_VL + bo) = lv;
        }
    };

    const int wm = (wid & 3) * 32;
    const int wn = (wid >> 2) * 32;

    float c[2][4][4];
    #pragma unroll
    for (int mt = 0; mt < 2; ++mt)
        #pragma unroll
        for (int no = 0; no < 4; ++no)
            #pragma unroll
            for (int e = 0; e < 4; ++e) c[mt][no][e] = 0.f;

    const uint32_t a_lrow = (uint32_t)(lane & 15);
    const uint32_t a_koff = (uint32_t)(lane >> 4) * 8;
    const uint32_t b_lrow = (uint32_t)((lane >> 4) * 8 + (lane & 7));
    const uint32_t b_koff = (uint32_t)((lane >> 3) & 1) * 8;

    const int NT = LL / 32;
    g_load(0);
    s_store(0);

    for (int t = 0; t < NT; ++t) {
        __syncthreads();
        const uint32_t bb = sbase + (uint32_t)(t & 1) * AV_BUF;
        if (t + 1 < NT) g_load(t + 1);

        #pragma unroll
        for (int ks = 0; ks < 2; ++ks) {
            const uint32_t kbyte = (uint32_t)(ks * 16 + a_koff) * 2;
            uint32_t af[2][4];
            #pragma unroll
            for (int mt = 0; mt < 2; ++mt)
                ldm_x4(af[mt], bb + AV_PH +
                       (uint32_t)(wm + mt * 16 + a_lrow) * PROWB + kbyte);

            const uint32_t bkb = (uint32_t)(ks * 16 + b_koff) * 2;
            uint32_t bhf[4][2], blf[4][2];
            #pragma unroll
            for (int half = 0; half < 2; ++half) {
                uint32_t r[4];
                uint32_t nrow = (uint32_t)(wn + half * 16) + b_lrow;
                ldm_x4(r, bb + AV_VH + nrow * PROWB + bkb);
                bhf[half * 2][0] = r[0]; bhf[half * 2][1] = r[1];
                bhf[half * 2 + 1][0] = r[2]; bhf[half * 2 + 1][1] = r[3];
                ldm_x4(r, bb + AV_VL + nrow * PROWB + bkb);
                blf[half * 2][0] = r[0]; blf[half * 2][1] = r[1];
                blf[half * 2 + 1][0] = r[2]; blf[half * 2 + 1][1] = r[3];
            }

            #pragma unroll
            for (int mt = 0; mt < 2; ++mt)
                #pragma unroll
                for (int no = 0; no < 4; ++no)
                    mma_bf16(c[mt][no], af[mt], bhf[no]);
            #pragma unroll
            for (int mt = 0; mt < 2; ++mt)
                #pragma unroll
                for (int no = 0; no < 4; ++no)
                    mma_bf16(c[mt][no], af[mt], blf[no]);

            #pragma unroll
            for (int mt = 0; mt < 2; ++mt)
                ldm_x4(af[mt], bb + AV_PL +
                       (uint32_t)(wm + mt * 16 + a_lrow) * PROWB + kbyte);
            #pragma unroll
            for (int mt = 0; mt < 2; ++mt)
                #pragma unroll
                for (int no = 0; no < 4; ++no)
                    mma_bf16(c[mt][no], af[mt], bhf[no]);
        }
        if (t + 1 < NT) s_store((t + 1) & 1);
    }

    const int erow = lane >> 2;
    const int ecol = (lane & 3) * 2;
    #pragma unroll
    for (int mt = 0; mt < 2; ++mt) {
        #pragma unroll
        for (int r2 = 0; r2 < 2; ++r2) {
            int row = wm + mt * 16 + erow + r2 * 8;
            int q = m0 + row;
            size_t base = ((size_t)b * LL + q) * DD + h * DKK;
            #pragma unroll
            for (int no = 0; no < 4; ++no) {
                int col = wn + no * 8 + ecol;
                uint32_t hi, lo;
                split2(c[mt][no][r2 * 2 + 0], c[mt][no][r2 * 2 + 1], hi, lo);
                *(uint32_t*)(ctx_h + base + col) = hi;
                *(uint32_t*)(ctx_l + base + col) = lo;
            }
        }
    }
}

// ---------------------------------------------------------------------------
extern "C" void kernel_launch(void* const* d_in, const int* in_sizes, int n_in,
                              void* d_out, int out_size)
{
    const float* q    = (const float*)d_in[0];
    const float* k    = (const float*)d_in[1];
    const float* v    = (const float*)d_in[2];
    const int*   mask = (const int*)d_in[3];
    const float* Wq   = (const float*)d_in[4];
    const float* bq   = (const float*)d_in[5];
    const float* Wk   = (const float*)d_in[6];
    const float* bk   = (const float*)d_in[7];
    const float* Wv   = (const float*)d_in[8];
    const float* bv   = (const float*)d_in[9];
    const float* Wo   = (const float*)d_in[10];
    const float* bo   = (const float*)d_in[11];

    float* out  = (float*)d_out;
    float* attn = out + (size_t)BB * LL * DD;

    float *qh, *kh, *vh, *rowsum;
    __nv_bfloat16 *ah, *al, *bh, *bl;
    cudaGetSymbolAddress((void**)&qh, g_qh);
    cudaGetSymbolAddress((void**)&kh, g_kh);
    cudaGetSymbolAddress((void**)&vh, g_vh);
    cudaGetSymbolAddress((void**)&rowsum, g_rowsum);
    cudaGetSymbolAddress((void**)&ah, g_ah);
    cudaGetSymbolAddress((void**)&al, g_al);
    cudaGetSymbolAddress((void**)&bh, g_bh);
    cudaGetSymbolAddress((void**)&bl, g_bl);

    const int M = BB * LL;  // 4096
    const int n4 = M * DD / 4;

    static int smem_set = 0;
    if (!smem_set) {
        cudaFuncSetAttribute(gemm_bf16_kernel<3>,
                             cudaFuncAttributeMaxDynamicSharedMemorySize,
                             GEMM_SMEM3);
        cudaFuncSetAttribute(gemm_bf16_kernel<1>,
                             cudaFuncAttributeMaxDynamicSharedMemorySize,
                             GEMM_SMEM1);
        cudaFuncSetAttribute(scores_mma_kernel,
                             cudaFuncAttributeMaxDynamicSharedMemorySize,
                             SCORES_SMEM);
        cudaFuncSetAttribute(av_mma_kernel,
                             cudaFuncAttributeMaxDynamicSharedMemorySize,
                             AV_SMEM);
        smem_set = 1;
    }

    zero_kernel<<<(NP * LL + 255) / 256, 256>>>(rowsum, NP * LL);

    dim3 gproj(DD / 128, M / 128);          // (8, 32)
    dim3 gwt(DD / 32, DD / 32);             // (32, 32)
    const int cga = (n4 + 255) / 256;

    // Q projection (single-bf16: score errors suppressed by /D)
    conv_wt_kernel<1><<<gwt, 256>>>(Wq, bh, bl, DD, DD);
    conv_a_h_kernel<<<cga, 256>>>(q, ah, n4);
    gemm_bf16_kernel<1><<<gproj, 256, GEMM_SMEM1>>>(ah, al, bh, bl, bq, qh, M, DD, DD);
    // K projection (single-bf16)
    conv_wt_kernel<1><<<gwt, 256>>>(Wk, bh, bl, DD, DD);
    conv_a_h_kernel<<<cga, 256>>>(k, ah, n4);
    gemm_bf16_kernel<1><<<gproj, 256, GEMM_SMEM1>>>(ah, al, bh, bl, bk, kh, M, DD, DD);
    // V projection (full split)
    conv_wt_kernel<3><<<gwt, 256>>>(Wv, bh, bl, DD, DD);
    conv_a_kernel<<<cga, 256>>>(v, ah, al, n4);
    gemm_bf16_kernel<3><<<gproj, 256, GEMM_SMEM3>>>(ah, al, bh, bl, bv, vh, M, DD, DD);

    dim3 gsc(LL / 128, LL / 128, NP);       // (16,16,32)
    scores_mma_kernel<<<gsc, 256, SCORES_SMEM>>>(qh, kh, mask, attn, rowsum);

    dim3 gav(LL / 128, NP);                 // (16, 32)
    av_mma_kernel<<<gav, 256, AV_SMEM>>>(attn, vh, rowsum, ah, al);

    // Output projection (ctx bf16 hi/lo in ah/al; full split)
    conv_wt_kernel<3><<<gwt, 256>>>(Wo, bh, bl, DD, DD);
    gemm_bf16_kernel<3><<<gproj, 256, GEMM_SMEM3>>>(ah, al, bh, bl, bo, out, M, DD, DD);
}

// round 12
// speedup vs baseline: 2.1342x; 1.0765x over previous
#include <cuda_runtime.h>
#include <cuda_bf16.h>
#include <cstdint>

#define BB 2
#define LL 2048
#define DD 1024
#define HH 16
#define DKK 64
#define NP (BB*HH)

// Scratch (__device__ globals — no runtime allocation)
__device__ float g_rowsum[(size_t)NP * LL];
__device__ __nv_bfloat16 g_ah[(size_t)BB * LL * DD];   // input act hi / ctx hi
__device__ __nv_bfloat16 g_al[(size_t)BB * LL * DD];   // input act lo / ctx lo
__device__ __nv_bfloat16 g_bh[(size_t)DD * DD];        // W^T hi
__device__ __nv_bfloat16 g_bl[(size_t)DD * DD];        // W^T lo
__device__ __nv_bfloat16 g_qhb[(size_t)BB * LL * DD];  // Q-proj out bf16
__device__ __nv_bfloat16 g_khb[(size_t)BB * LL * DD];  // K-proj out bf16
__device__ __nv_bfloat16 g_vhh[(size_t)BB * LL * DD];  // V-proj out hi
__device__ __nv_bfloat16 g_vhl[(size_t)BB * LL * DD];  // V-proj out lo

// ---- helpers --------------------------------------------------------------
__device__ __forceinline__ uint32_t smem_u32(const void* p) {
    uint32_t a;
    asm("{ .reg .u64 t; cvta.to.shared.u64 t, %1; cvt.u32.u64 %0, t; }"
        : "=r"(a) : "l"(p));
    return a;
}
__device__ __forceinline__ void ldm_x4(uint32_t* r, uint32_t addr) {
    asm volatile("ldmatrix.sync.aligned.m8n8.x4.shared.b16 {%0,%1,%2,%3}, [%4];"
                 : "=r"(r[0]), "=r"(r[1]), "=r"(r[2]), "=r"(r[3]) : "r"(addr));
}
__device__ __forceinline__ void ldm_x4_t(uint32_t* r, uint32_t addr) {
    asm volatile("ldmatrix.sync.aligned.m8n8.x4.trans.shared.b16 {%0,%1,%2,%3}, [%4];"
                 : "=r"(r[0]), "=r"(r[1]), "=r"(r[2]), "=r"(r[3]) : "r"(addr));
}
__device__ __forceinline__ void mma_bf16(float* c, const uint32_t* a,
                                         const uint32_t* b) {
    asm volatile(
        "mma.sync.aligned.m16n8k16.row.col.f32.bf16.bf16.f32 "
        "{%0,%1,%2,%3}, {%4,%5,%6,%7}, {%8,%9}, {%0,%1,%2,%3};"
        : "+f"(c[0]), "+f"(c[1]), "+f"(c[2]), "+f"(c[3])
        : "r"(a[0]), "r"(a[1]), "r"(a[2]), "r"(a[3]), "r"(b[0]), "r"(b[1]));
}
__device__ __forceinline__ void split2(float x, float y, uint32_t& hi, uint32_t& lo) {
    __nv_bfloat16 hx = __float2bfloat16(x);
    __nv_bfloat16 hy = __float2bfloat16(y);
    float lx = x - __bfloat162float(hx);
    float ly = y - __bfloat162float(hy);
    __nv_bfloat162 hp; hp.x = hx; hp.y = hy;
    __nv_bfloat162 lp = __floats2bfloat162_rn(lx, ly);
    hi = *(uint32_t*)&hp;
    lo = *(uint32_t*)&lp;
}
__device__ __forceinline__ uint32_t bfpack(float x, float y) {
    __nv_bfloat162 t = __floats2bfloat162_rn(x, y);
    return *(uint32_t*)&t;
}
__device__ __forceinline__ void cpasync16(uint32_t sdst, const void* gsrc) {
    asm volatile("cp.async.ca.shared.global [%0], [%1], 16;"
                 :: "r"(sdst), "l"(gsrc));
}

// ---------------------------------------------------------------------------
__global__ void zero_kernel(float* p, int n) {
    int i = blockIdx.x * blockDim.x + threadIdx.x;
    if (i < n) p[i] = 0.f;
}
__global__ __launch_bounds__(256) void conv_a_kernel(
    const float* __restrict__ A, __nv_bfloat16* __restrict__ Ah,
    __nv_bfloat16* __restrict__ Al, int n4)
{
    int i = blockIdx.x * blockDim.x + threadIdx.x;
    if (i >= n4) return;
    float4 v = *(const float4*)(A + (size_t)i * 4);
    uint32_t h01, l01, h23, l23;
    split2(v.x, v.y, h01, l01);
    split2(v.z, v.w, h23, l23);
    uint32_t* ph = (uint32_t*)Ah + (size_t)i * 2;
    uint32_t* pl = (uint32_t*)Al + (size_t)i * 2;
    ph[0] = h01; ph[1] = h23;
    pl[0] = l01; pl[1] = l23;
}
__global__ __launch_bounds__(256) void conv_a_h_kernel(
    const float* __restrict__ A, __nv_bfloat16* __restrict__ Ah, int n4)
{
    int i = blockIdx.x * blockDim.x + threadIdx.x;
    if (i >= n4) return;
    float4 v = *(const float4*)(A + (size_t)i * 4);
    uint32_t* ph = (uint32_t*)Ah + (size_t)i * 2;
    ph[0] = bfpack(v.x, v.y);
    ph[1] = bfpack(v.z, v.w);
}
template<int SPLIT>
__global__ __launch_bounds__(256) void conv_wt_kernel(
    const float* __restrict__ W, __nv_bfloat16* __restrict__ Th,
    __nv_bfloat16* __restrict__ Tl, int K, int N)
{
    __shared__ float ts[32][33];
    int k0 = blockIdx.y * 32;
    int n0 = blockIdx.x * 32;
    int tx = threadIdx.x & 31;
    int ty = threadIdx.x >> 5;
    #pragma unroll
    for (int i = 0; i < 4; ++i) {
        int k = ty + i * 8;
        ts[k][tx] = W[(size_t)(k0 + k) * N + n0 + tx];
    }
    __syncthreads();
    #pragma unroll
    for (int i = 0; i < 4; ++i) {
        int n = ty + i * 8;
        float x = ts[tx][n];
        __nv_bfloat16 h = __float2bfloat16(x);
        Th[(size_t)(n0 + n) * K + k0 + tx] = h;
        if (SPLIT == 3) {
            float l = x - __bfloat162float(h);
            Tl[(size_t)(n0 + n) * K + k0 + tx] = __float2bfloat16(l);
        }
    }
}

// ---------------------------------------------------------------------------
// bf16 HMMA GEMM. SPLIT: 3 = hi/lo 3-MMA, 1 = single. OUT: 0 = fp32,
// 1 = bf16 single, 2 = bf16 hi/lo.
// ---------------------------------------------------------------------------
#define GA_H 0
#define GA_L 8192
#define GB_H 16384
#define GB_L 24576
#define GBUF 32768
#define GEMM_SMEM3 (2*GBUF)
#define G1_B 8192
#define G1BUF 16384
#define GEMM_SMEM1 (2*G1BUF)

template<int SPLIT, int OUT>
__global__ __launch_bounds__(256, 2) void gemm_bf16_kernel(
    const __nv_bfloat16* __restrict__ Ah, const __nv_bfloat16* __restrict__ Al,
    const __nv_bfloat16* __restrict__ Bh, const __nv_bfloat16* __restrict__ Bl,
    const float* __restrict__ bias, float* __restrict__ C,
    __nv_bfloat16* __restrict__ Ch, __nv_bfloat16* __restrict__ Cl,
    int M, int N, int K)
{
    extern __shared__ char smem[];
    const uint32_t sbase = smem_u32(smem);
    const int tid  = threadIdx.x;
    const int wid  = tid >> 5;
    const int lane = tid & 31;
    const int m0 = blockIdx.y * 128;
    const int n0 = blockIdx.x * 128;
    const int wm = (wid & 1) * 64;
    const int wn = (wid >> 1) * 32;

    const uint32_t BUFSTRIDE = (SPLIT == 3) ? GBUF : G1BUF;
    const uint32_t OFFB      = (SPLIT == 3) ? GB_H : G1_B;

    float c[4][4][4];
    #pragma unroll
    for (int mt = 0; mt < 4; ++mt)
        #pragma unroll
        for (int no = 0; no < 4; ++no)
            #pragma unroll
            for (int e = 0; e < 4; ++e) c[mt][no][e] = 0.f;

    const int j0 = tid * 2;
    auto issue = [&](int t) {
        uint32_t sb = sbase + (uint32_t)(t & 1) * BUFSTRIDE;
        #pragma unroll
        for (int i = 0; i < 2; ++i) {
            int j = j0 + i;
            int r = j >> 2;
            int cch = j & 3;
            uint32_t sw = (uint32_t)r * 64 + (uint32_t)((cch ^ (r & 3)) << 4);
            size_t ga = (size_t)(m0 + r) * K + t * 32 + cch * 8;
            size_t gb = (size_t)(n0 + r) * K + t * 32 + cch * 8;
            cpasync16(sb + GA_H + sw, Ah + ga);
            cpasync16(sb + OFFB + sw, Bh + gb);
            if (SPLIT == 3) {
                cpasync16(sb + GA_L + sw, Al + ga);
                cpasync16(sb + GB_L + sw, Bl + gb);
            }
        }
        asm volatile("cp.async.commit_group;" ::: "memory");
    };

    const uint32_t a_lrow = (uint32_t)(lane & 15);
    const uint32_t a_cc   = (uint32_t)(lane >> 4);
    const uint32_t b_lrow = (uint32_t)((lane >> 4) * 8 + (lane & 7));
    const uint32_t b_cc   = (uint32_t)((lane >> 3) & 1);

    const int NT = K / 32;
    issue(0);
    issue(1);

    for (int t = 0; t < NT; ++t) {
        if (t + 1 < NT)
            asm volatile("cp.async.wait_group 1;" ::: "memory");
        else
            asm volatile("cp.async.wait_group 0;" ::: "memory");
        __syncthreads();

        const uint32_t bb = sbase + (uint32_t)(t & 1) * BUFSTRIDE;

        #pragma unroll
        for (int ks = 0; ks < 2; ++ks) {
            uint32_t af[4][4];
            #pragma unroll
            for (int mt = 0; mt < 4; ++mt) {
                uint32_t row = (uint32_t)(wm + mt * 16) + a_lrow;
                uint32_t cch = (uint32_t)(ks * 2) + a_cc;
                ldm_x4(af[mt], bb + GA_H + row * 64 + ((cch ^ (row & 3)) << 4));
            }
            uint32_t bh[4][2], bl[4][2];
            #pragma unroll
            for (int half = 0; half < 2; ++half) {
                uint32_t r[4];
                uint32_t nrow = (uint32_t)(wn + half * 16) + b_lrow;
                uint32_t cch = (uint32_t)(ks * 2) + b_cc;
                uint32_t sw = nrow * 64 + ((cch ^ (nrow & 3)) << 4);
                ldm_x4(r, bb + OFFB + sw);
                bh[half * 2][0] = r[0]; bh[half * 2][1] = r[1];
                bh[half * 2 + 1][0] = r[2]; bh[half * 2 + 1][1] = r[3];
                if (SPLIT == 3) {
                    ldm_x4(r, bb + GB_L + sw);
                    bl[half * 2][0] = r[0]; bl[half * 2][1] = r[1];
                    bl[half * 2 + 1][0] = r[2]; bl[half * 2 + 1][1] = r[3];
                }
            }

            #pragma unroll
            for (int mt = 0; mt < 4; ++mt)
                #pragma unroll
                for (int no = 0; no < 4; ++no)
                    mma_bf16(c[mt][no], af[mt], bh[no]);

            if (SPLIT == 3) {
                #pragma unroll
                for (int mt = 0; mt < 4; ++mt)
                    #pragma unroll
                    for (int no = 0; no < 4; ++no)
                        mma_bf16(c[mt][no], af[mt], bl[no]);
                #pragma unroll
                for (int mt = 0; mt < 4; ++mt) {
                    uint32_t row = (uint32_t)(wm + mt * 16) + a_lrow;
                    uint32_t cch = (uint32_t)(ks * 2) + a_cc;
                    ldm_x4(af[mt], bb + GA_L + row * 64 + ((cch ^ (row & 3)) << 4));
                }
                #pragma unroll
                for (int mt = 0; mt < 4; ++mt)
                    #pragma unroll
                    for (int no = 0; no < 4; ++no)
                        mma_bf16(c[mt][no], af[mt], bh[no]);
            }
        }

        if (t + 2 < NT) {
            __syncthreads();
            issue(t + 2);
        }
    }

    const int erow = lane >> 2;
    const int ecol = (lane & 3) * 2;
    #pragma unroll
    for (int mt = 0; mt < 4; ++mt) {
        int r0 = m0 + wm + mt * 16 + erow;
        #pragma unroll
        for (int no = 0; no < 4; ++no) {
            int col = n0 + wn + no * 8 + ecol;
            float2 bv = *(const float2*)(bias + col);
            float o0 = c[mt][no][0] + bv.x;
            float o1 = c[mt][no][1] + bv.y;
            float o2 = c[mt][no][2] + bv.x;
            float o3 = c[mt][no][3] + bv.y;
            if (OUT == 0) {
                float2 o;
                o.x = o0; o.y = o1;
                *(float2*)(C + (size_t)r0 * N + col) = o;
                o.x = o2; o.y = o3;
                *(float2*)(C + (size_t)(r0 + 8) * N + col) = o;
            } else if (OUT == 1) {
                *(uint32_t*)(Ch + (size_t)r0 * N + col) = bfpack(o0, o1);
                *(uint32_t*)(Ch + (size_t)(r0 + 8) * N + col) = bfpack(o2, o3);
            } else {
                uint32_t hi, lo;
                split2(o0, o1, hi, lo);
                *(uint32_t*)(Ch + (size_t)r0 * N + col) = hi;
                *(uint32_t*)(Cl + (size_t)r0 * N + col) = lo;
                split2(o2, o3, hi, lo);
                *(uint32_t*)(Ch + (size_t)(r0 + 8) * N + col) = hi;
                *(uint32_t*)(Cl + (size_t)(r0 + 8) * N + col) = lo;
            }
        }
    }
}

// ---------------------------------------------------------------------------
// Scores: single-bf16 HMMA from preconverted qhb/khb via cp.async.
// smem: 128-row x 128B tiles, XOR swizzle over 8x16B chunks.
// ---------------------------------------------------------------------------
#define SC_Q 0
#define SC_K 16384
#define SCORES_SMEM 32768

__global__ __launch_bounds__(256, 2) void scores_mma_kernel(
    const __nv_bfloat16* __restrict__ qhb, const __nv_bfloat16* __restrict__ khb,
    const int* __restrict__ mask, float* __restrict__ attn,
    float* __restrict__ rowsum)
{
    extern __shared__ char smem[];
    const uint32_t sbase = smem_u32(smem);
    const int tid = threadIdx.x;
    const int wid = tid >> 5;
    const int lane = tid & 31;
    const int p = blockIdx.z;
    const int b = p / HH;
    const int h = p % HH;
    const int q0 = blockIdx.y * 128;
    const int k0 = blockIdx.x * 128;

    {
        const __nv_bfloat16* Qg = qhb + (size_t)(b * LL + q0) * DD + h * DKK;
        const __nv_bfloat16* Kg = khb + (size_t)(b * LL + k0) * DD + h * DKK;
        int j0 = tid * 4;
        #pragma unroll
        for (int i = 0; i < 4; ++i) {
            int j = j0 + i;
            int r = j >> 3;
            int cch = j & 7;
            uint32_t sw = (uint32_t)r * 128 + (uint32_t)((cch ^ (r & 7)) << 4);
            cpasync16(sbase + SC_Q + sw, Qg + (size_t)r * DD + cch * 8);
            cpasync16(sbase + SC_K + sw, Kg + (size_t)r * DD + cch * 8);
        }
        asm volatile("cp.async.commit_group;" ::: "memory");
        asm volatile("cp.async.wait_group 0;" ::: "memory");
    }
    __syncthreads();

    const int wm = (wid & 1) * 64;
    const int wn = (wid >> 1) * 32;

    float c[4][4][4];
    #pragma unroll
    for (int mt = 0; mt < 4; ++mt)
        #pragma unroll
        for (int no = 0; no < 4; ++no)
            #pragma unroll
            for (int e = 0; e < 4; ++e) c[mt][no][e] = 0.f;

    const uint32_t a_lrow = (uint32_t)(lane & 15);
    const uint32_t a_cc   = (uint32_t)(lane >> 4);
    const uint32_t b_lrow = (uint32_t)((lane >> 4) * 8 + (lane & 7));
    const uint32_t b_cc   = (uint32_t)((lane >> 3) & 1);

    #pragma unroll
    for (int ks = 0; ks < 4; ++ks) {
        uint32_t af[4][4];
        #pragma unroll
        for (int mt = 0; mt < 4; ++mt) {
            uint32_t row = (uint32_t)(wm + mt * 16) + a_lrow;
            uint32_t cch = (uint32_t)(ks * 2) + a_cc;
            ldm_x4(af[mt], sbase + SC_Q + row * 128 + ((cch ^ (row & 7)) << 4));
        }
        uint32_t bh[4][2];
        #pragma unroll
        for (int half = 0; half < 2; ++half) {
            uint32_t r[4];
            uint32_t nrow = (uint32_t)(wn + half * 16) + b_lrow;
            uint32_t cch = (uint32_t)(ks * 2) + b_cc;
            ldm_x4(r, sbase + SC_K + nrow * 128 + ((cch ^ (nrow & 7)) << 4));
            bh[half * 2][0] = r[0]; bh[half * 2][1] = r[1];
            bh[half * 2 + 1][0] = r[2]; bh[half * 2 + 1][1] = r[3];
        }
        #pragma unroll
        for (int mt = 0; mt < 4; ++mt)
            #pragma unroll
            for (int no = 0; no < 4; ++no)
                mma_bf16(c[mt][no], af[mt], bh[no]);
    }

    const float scale = 1.0f / (float)DD;
    const size_t obase = (size_t)(h * BB + b) * LL * LL;
    float* rs = rowsum + (size_t)p * LL;
    const int erow = lane >> 2;
    const int ecol = (lane & 3) * 2;

    #pragma unroll
    for (int mt = 0; mt < 4; ++mt) {
        #pragma unroll
        for (int r2 = 0; r2 < 2; ++r2) {
            int row = wm + mt * 16 + erow + r2 * 8;
            int q = q0 + row;
            const int* mbase = mask + ((size_t)b * LL + q) * LL;
            float* obase_row = attn + obase + (size_t)q * LL;
            float rsum = 0.f;
            #pragma unroll
            for (int no = 0; no < 4; ++no) {
                int col = k0 + wn + no * 8 + ecol;
                int2 m = *(const int2*)(mbase + col);
                float e0 = m.x ? __expf(c[mt][no][r2 * 2 + 0] * scale) : 0.f;
                float e1 = m.y ? __expf(c[mt][no][r2 * 2 + 1] * scale) : 0.f;
                float2 o; o.x = e0; o.y = e1;
                *(float2*)(obase_row + col) = o;
                rsum += e0 + e1;
            }
            rsum += __shfl_xor_sync(0xffffffffu, rsum, 1);
            rsum += __shfl_xor_sync(0xffffffffu, rsum, 2);
            if ((lane & 3) == 0) atomicAdd(rs + q, rsum);
        }
    }
}

// ---------------------------------------------------------------------------
// AV: ctx = (P/rowsum)@V, normalized P written back. P fp32 from attn,
// split hi/lo in regs; V bf16 hi/lo via cp.async + trans-ldmatrix.
// ---------------------------------------------------------------------------
#define PROWB 80
#define AV_PH 0
#define AV_PL 10240
#define AVV_H 20480
#define AVV_L 24576
#define AV_BUF 28672
#define AV_SMEM (2*AV_BUF)

__global__ __launch_bounds__(256) void av_mma_kernel(
    float* __restrict__ attn,
    const __nv_bfloat16* __restrict__ vhh, const __nv_bfloat16* __restrict__ vhl,
    const float* __restrict__ rowsum,
    __nv_bfloat16* __restrict__ ctx_h, __nv_bfloat16* __restrict__ ctx_l)
{
    extern __shared__ char smem[];
    const uint32_t sbase = smem_u32(smem);
    const int tid = threadIdx.x;
    const int wid = tid >> 5;
    const int lane = tid & 31;
    const int p = blockIdx.y;
    const int b = p / HH;
    const int h = p % HH;
    const int m0 = blockIdx.x * 128;

    float* Pb = attn + (size_t)(h * BB + b) * LL * LL + (size_t)m0 * LL;
    const __nv_bfloat16* Vh = vhh + (size_t)b * LL * DD + h * DKK;
    const __nv_bfloat16* Vl = vhl + (size_t)b * LL * DD + h * DKK;

    const int prow = tid >> 1;
    const int pcseg = (tid & 1) * 16;
    const float inv_r = 1.0f / rowsum[(size_t)p * LL + m0 + prow];
    const int v_r = tid >> 3;     // 0..31
    const int v_c = tid & 7;      // 0..7

    float rp[16];

    auto issueV = [&](int t) {
        uint32_t sb = sbase + (uint32_t)(t & 1) * AV_BUF;
        uint32_t sw = (uint32_t)v_r * 128 + (uint32_t)((v_c ^ (v_r & 7)) << 4);
        size_t g = (size_t)(t * 32 + v_r) * DD + v_c * 8;
        cpasync16(sb + AVV_H + sw, Vh + g);
        cpasync16(sb + AVV_L + sw, Vl + g);
        asm volatile("cp.async.commit_group;" ::: "memory");
    };
    auto g_loadP = [&](int t) {
        float* Pp = Pb + (size_t)prow * LL + t * 32 + pcseg;
        #pragma unroll
        for (int i = 0; i < 4; ++i) {
            float4 v = *(const float4*)(Pp + 4 * i);
            v.x *= inv_r; v.y *= inv_r; v.z *= inv_r; v.w *= inv_r;
            *(float4*)(rp + 4 * i) = v;
            *(float4*)(Pp + 4 * i) = v;
        }
    };
    auto s_storeP = [&](int buf) {
        char* base = smem + buf * AV_BUF;
        uint32_t po = (uint32_t)prow * PROWB + (uint32_t)pcseg * 2;
        #pragma unroll
        for (int i = 0; i < 8; ++i) {
            uint32_t hi, lo;
            split2(rp[2 * i], rp[2 * i + 1], hi, lo);
            *(uint32_t*)(base + AV_PH + po + 4 * i) = hi;
            *(uint32_t*)(base + AV_PL + po + 4 * i) = lo;
        }
    };

    const int wm = (wid & 3) * 32;
    const int wn = (wid >> 2) * 32;

    float c[2][4][4];
    #pragma unroll
    for (int mt = 0; mt < 2; ++mt)
        #pragma unroll
        for (int no = 0; no < 4; ++no)
            #pragma unroll
            for (int e = 0; e < 4; ++e) c[mt][no][e] = 0.f;

    const uint32_t a_lrow = (uint32_t)(lane & 15);
    const uint32_t a_koff = (uint32_t)(lane >> 4) * 8;
    // trans-ldmatrix lane mapping for V ([k][n] tiles)
    const int vm = lane >> 3;                 // matrix id 0..3
    const int v_krow_off = (vm & 1) * 8 + (lane & 7);
    const int v_nc_off = (vm >> 1);           // n-chunk offset (0 or 1)

    const int NT = LL / 32;
    issueV(0);
    g_loadP(0);
    s_storeP(0);

    for (int t = 0; t < NT; ++t) {
        asm volatile("cp.async.wait_group 0;" ::: "memory");
        __syncthreads();
        const uint32_t bb = sbase + (uint32_t)(t & 1) * AV_BUF;
        if (t + 1 < NT) {
            issueV(t + 1);
            g_loadP(t + 1);
        }

        #pragma unroll
        for (int ks = 0; ks < 2; ++ks) {
            const uint32_t kbyte = (uint32_t)(ks * 16 + a_koff) * 2;
            uint32_t af[2][4];
            #pragma unroll
            for (int mt = 0; mt < 2; ++mt)
                ldm_x4(af[mt], bb + AV_PH +
                       (uint32_t)(wm + mt * 16 + a_lrow) * PROWB + kbyte);

            uint32_t bhf[4][2], blf[4][2];
            #pragma unroll
            for (int half = 0; half < 2; ++half) {
                uint32_t r[4];
                uint32_t k_row = (uint32_t)(ks * 16 + v_krow_off);
                uint32_t cch = (uint32_t)((wn + half * 16) >> 3) + v_nc_off;
                uint32_t sw = k_row * 128 + ((cch ^ (k_row & 7)) << 4);
                ldm_x4_t(r, bb + AVV_H + sw);
                bhf[half * 2][0] = r[0]; bhf[half * 2][1] = r[1];
                bhf[half * 2 + 1][0] = r[2]; bhf[half * 2 + 1][1] = r[3];
                ldm_x4_t(r, bb + AVV_L + sw);
                blf[half * 2][0] = r[0]; blf[half * 2][1] = r[1];
                blf[half * 2 + 1][0] = r[2]; blf[half * 2 + 1][1] = r[3];
            }

            #pragma unroll
            for (int mt = 0; mt < 2; ++mt)
                #pragma unroll
                for (int no = 0; no < 4; ++no)
                    mma_bf16(c[mt][no], af[mt], bhf[no]);
            #pragma unroll
            for (int mt = 0; mt < 2; ++mt)
                #pragma unroll
                for (int no = 0; no < 4; ++no)
                    mma_bf16(c[mt][no], af[mt], blf[no]);

            #pragma unroll
            for (int mt = 0; mt < 2; ++mt)
                ldm_x4(af[mt], bb + AV_PL +
                       (uint32_t)(wm + mt * 16 + a_lrow) * PROWB + kbyte);
            #pragma unroll
            for (int mt = 0; mt < 2; ++mt)
                #pragma unroll
                for (int no = 0; no < 4; ++no)
                    mma_bf16(c[mt][no], af[mt], bhf[no]);
        }
        if (t + 1 < NT) s_storeP((t + 1) & 1);
    }

    const int erow = lane >> 2;
    const int ecol = (lane & 3) * 2;
    #pragma unroll
    for (int mt = 0; mt < 2; ++mt) {
        #pragma unroll
        for (int r2 = 0; r2 < 2; ++r2) {
            int row = wm + mt * 16 + erow + r2 * 8;
            int q = m0 + row;
            size_t base = ((size_t)b * LL + q) * DD + h * DKK;
            #pragma unroll
            for (int no = 0; no < 4; ++no) {
                int col = wn + no * 8 + ecol;
                uint32_t hi, lo;
                split2(c[mt][no][r2 * 2 + 0], c[mt][no][r2 * 2 + 1], hi, lo);
                *(uint32_t*)(ctx_h + base + col) = hi;
                *(uint32_t*)(ctx_l + base + col) = lo;
            }
        }
    }
}

// ---------------------------------------------------------------------------
extern "C" void kernel_launch(void* const* d_in, const int* in_sizes, int n_in,
                              void* d_out, int out_size)
{
    const float* q    = (const float*)d_in[0];
    const float* k    = (const float*)d_in[1];
    const float* v    = (const float*)d_in[2];
    const int*   mask = (const int*)d_in[3];
    const float* Wq   = (const float*)d_in[4];
    const float* bq   = (const float*)d_in[5];
    const float* Wk   = (const float*)d_in[6];
    const float* bk   = (const float*)d_in[7];
    const float* Wv   = (const float*)d_in[8];
    const float* bv   = (const float*)d_in[9];
    const float* Wo   = (const float*)d_in[10];
    const float* bo   = (const float*)d_in[11];

    float* out  = (float*)d_out;
    float* attn = out + (size_t)BB * LL * DD;

    float* rowsum;
    __nv_bfloat16 *ah, *al, *bh, *bl, *qhb, *khb, *vhh, *vhl;
    cudaGetSymbolAddress((void**)&rowsum, g_rowsum);
    cudaGetSymbolAddress((void**)&ah, g_ah);
    cudaGetSymbolAddress((void**)&al, g_al);
    cudaGetSymbolAddress((void**)&bh, g_bh);
    cudaGetSymbolAddress((void**)&bl, g_bl);
    cudaGetSymbolAddress((void**)&qhb, g_qhb);
    cudaGetSymbolAddress((void**)&khb, g_khb);
    cudaGetSymbolAddress((void**)&vhh, g_vhh);
    cudaGetSymbolAddress((void**)&vhl, g_vhl);

    const int M = BB * LL;  // 4096
    const int n4 = M * DD / 4;

    static int smem_set = 0;
    if (!smem_set) {
        cudaFuncSetAttribute(gemm_bf16_kernel<1,1>,
                             cudaFuncAttributeMaxDynamicSharedMemorySize, GEMM_SMEM1);
        cudaFuncSetAttribute(gemm_bf16_kernel<3,2>,
                             cudaFuncAttributeMaxDynamicSharedMemorySize, GEMM_SMEM3);
        cudaFuncSetAttribute(gemm_bf16_kernel<3,0>,
                             cudaFuncAttributeMaxDynamicSharedMemorySize, GEMM_SMEM3);
        cudaFuncSetAttribute(scores_mma_kernel,
                             cudaFuncAttributeMaxDynamicSharedMemorySize, SCORES_SMEM);
        cudaFuncSetAttribute(av_mma_kernel,
                             cudaFuncAttributeMaxDynamicSharedMemorySize, AV_SMEM);
        smem_set = 1;
    }

    zero_kernel<<<(NP * LL + 255) / 256, 256>>>(rowsum, NP * LL);

    dim3 gproj(DD / 128, M / 128);
    dim3 gwt(DD / 32, DD / 32);
    const int cga = (n4 + 255) / 256;

    // Q projection -> bf16
    conv_wt_kernel<1><<<gwt, 256>>>(Wq, bh, bl, DD, DD);
    conv_a_h_kernel<<<cga, 256>>>(q, ah, n4);
    gemm_bf16_kernel<1,1><<<gproj, 256, GEMM_SMEM1>>>(ah, al, bh, bl, bq,
                                                      nullptr, qhb, nullptr, M, DD, DD);
    // K projection -> bf16
    conv_wt_kernel<1><<<gwt, 256>>>(Wk, bh, bl, DD, DD);
    conv_a_h_kernel<<<cga, 256>>>(k, ah, n4);
    gemm_bf16_kernel<1,1><<<gproj, 256, GEMM_SMEM1>>>(ah, al, bh, bl, bk,
                                                      nullptr, khb, nullptr, M, DD, DD);
    // V projection -> bf16 hi/lo
    conv_wt_kernel<3><<<gwt, 256>>>(Wv, bh, bl, DD, DD);
    conv_a_kernel<<<cga, 256>>>(v, ah, al, n4);
    gemm_bf16_kernel<3,2><<<gproj, 256, GEMM_SMEM3>>>(ah, al, bh, bl, bv,
                                                      nullptr, vhh, vhl, M, DD, DD);

    dim3 gsc(LL / 128, LL / 128, NP);
    scores_mma_kernel<<<gsc, 256, SCORES_SMEM>>>(qhb, khb, mask, attn, rowsum);

    dim3 gav(LL / 128, NP);
    av_mma_kernel<<<gav, 256, AV_SMEM>>>(attn, vhh, vhl, rowsum, ah, al);

    // Output projection (ctx bf16 hi/lo in ah/al)
    conv_wt_kernel<3><<<gwt, 256>>>(Wo, bh, bl, DD, DD);
    gemm_bf16_kernel<3,0><<<gproj, 256, GEMM_SMEM3>>>(ah, al, bh, bl, bo,
                                                      out, nullptr, nullptr, M, DD, DD);
}

// round 13
// speedup vs baseline: 2.2814x; 1.0689x over previous
#include <cuda_runtime.h>
#include <cuda_bf16.h>
#include <cstdint>

#define BB 2
#define LL 2048
#define DD 1024
#define HH 16
#define DKK 64
#define NP (BB*HH)

// Scratch (__device__ globals — no runtime allocation)
__device__ __nv_bfloat16 g_ah[(size_t)BB * LL * DD];   // input act hi / ctx hi
__device__ __nv_bfloat16 g_al[(size_t)BB * LL * DD];   // input act lo / ctx lo
__device__ __nv_bfloat16 g_bh[(size_t)DD * DD];        // W^T hi
__device__ __nv_bfloat16 g_bl[(size_t)DD * DD];        // W^T lo
__device__ __nv_bfloat16 g_qhb[(size_t)BB * LL * DD];  // Q-proj out bf16
__device__ __nv_bfloat16 g_khb[(size_t)BB * LL * DD];  // K-proj out bf16
__device__ __nv_bfloat16 g_vhh[(size_t)BB * LL * DD];  // V-proj out hi
__device__ __nv_bfloat16 g_vhl[(size_t)BB * LL * DD];  // V-proj out lo

// ---- helpers --------------------------------------------------------------
__device__ __forceinline__ uint32_t smem_u32(const void* p) {
    uint32_t a;
    asm("{ .reg .u64 t; cvta.to.shared.u64 t, %1; cvt.u32.u64 %0, t; }"
        : "=r"(a) : "l"(p));
    return a;
}
__device__ __forceinline__ void ldm_x4(uint32_t* r, uint32_t addr) {
    asm volatile("ldmatrix.sync.aligned.m8n8.x4.shared.b16 {%0,%1,%2,%3}, [%4];"
                 : "=r"(r[0]), "=r"(r[1]), "=r"(r[2]), "=r"(r[3]) : "r"(addr));
}
__device__ __forceinline__ void ldm_x4_t(uint32_t* r, uint32_t addr) {
    asm volatile("ldmatrix.sync.aligned.m8n8.x4.trans.shared.b16 {%0,%1,%2,%3}, [%4];"
                 : "=r"(r[0]), "=r"(r[1]), "=r"(r[2]), "=r"(r[3]) : "r"(addr));
}
__device__ __forceinline__ void mma_bf16(float* c, const uint32_t* a,
                                         const uint32_t* b) {
    asm volatile(
        "mma.sync.aligned.m16n8k16.row.col.f32.bf16.bf16.f32 "
        "{%0,%1,%2,%3}, {%4,%5,%6,%7}, {%8,%9}, {%0,%1,%2,%3};"
        : "+f"(c[0]), "+f"(c[1]), "+f"(c[2]), "+f"(c[3])
        : "r"(a[0]), "r"(a[1]), "r"(a[2]), "r"(a[3]), "r"(b[0]), "r"(b[1]));
}
__device__ __forceinline__ void split2(float x, float y, uint32_t& hi, uint32_t& lo) {
    __nv_bfloat16 hx = __float2bfloat16(x);
    __nv_bfloat16 hy = __float2bfloat16(y);
    float lx = x - __bfloat162float(hx);
    float ly = y - __bfloat162float(hy);
    __nv_bfloat162 hp; hp.x = hx; hp.y = hy;
    __nv_bfloat162 lp = __floats2bfloat162_rn(lx, ly);
    hi = *(uint32_t*)&hp;
    lo = *(uint32_t*)&lp;
}
__device__ __forceinline__ uint32_t bfpack(float x, float y) {
    __nv_bfloat162 t = __floats2bfloat162_rn(x, y);
    return *(uint32_t*)&t;
}
__device__ __forceinline__ void cpasync16(uint32_t sdst, const void* gsrc) {
    asm volatile("cp.async.ca.shared.global [%0], [%1], 16;"
                 :: "r"(sdst), "l"(gsrc));
}

// ---------------------------------------------------------------------------
__global__ __launch_bounds__(256) void conv_a_kernel(
    const float* __restrict__ A, __nv_bfloat16* __restrict__ Ah,
    __nv_bfloat16* __restrict__ Al, int n4)
{
    int i = blockIdx.x * blockDim.x + threadIdx.x;
    if (i >= n4) return;
    float4 v = *(const float4*)(A + (size_t)i * 4);
    uint32_t h01, l01, h23, l23;
    split2(v.x, v.y, h01, l01);
    split2(v.z, v.w, h23, l23);
    uint32_t* ph = (uint32_t*)Ah + (size_t)i * 2;
    uint32_t* pl = (uint32_t*)Al + (size_t)i * 2;
    ph[0] = h01; ph[1] = h23;
    pl[0] = l01; pl[1] = l23;
}
__global__ __launch_bounds__(256) void conv_a_h_kernel(
    const float* __restrict__ A, __nv_bfloat16* __restrict__ Ah, int n4)
{
    int i = blockIdx.x * blockDim.x + threadIdx.x;
    if (i >= n4) return;
    float4 v = *(const float4*)(A + (size_t)i * 4);
    uint32_t* ph = (uint32_t*)Ah + (size_t)i * 2;
    ph[0] = bfpack(v.x, v.y);
    ph[1] = bfpack(v.z, v.w);
}
template<int SPLIT>
__global__ __launch_bounds__(256) void conv_wt_kernel(
    const float* __restrict__ W, __nv_bfloat16* __restrict__ Th,
    __nv_bfloat16* __restrict__ Tl, int K, int N)
{
    __shared__ float ts[32][33];
    int k0 = blockIdx.y * 32;
    int n0 = blockIdx.x * 32;
    int tx = threadIdx.x & 31;
    int ty = threadIdx.x >> 5;
    #pragma unroll
    for (int i = 0; i < 4; ++i) {
        int k = ty + i * 8;
        ts[k][tx] = W[(size_t)(k0 + k) * N + n0 + tx];
    }
    __syncthreads();
    #pragma unroll
    for (int i = 0; i < 4; ++i) {
        int n = ty + i * 8;
        float x = ts[tx][n];
        __nv_bfloat16 h = __float2bfloat16(x);
        Th[(size_t)(n0 + n) * K + k0 + tx] = h;
        if (SPLIT == 3) {
            float l = x - __bfloat162float(h);
            Tl[(size_t)(n0 + n) * K + k0 + tx] = __float2bfloat16(l);
        }
    }
}

// ---------------------------------------------------------------------------
// bf16 HMMA GEMM, 3-stage cp.async ring (one __syncthreads per iter).
// SPLIT: 3 = hi/lo 3-MMA, 1 = single. OUT: 0 = fp32, 1 = bf16, 2 = bf16 hi/lo.
// ---------------------------------------------------------------------------
#define GA_H 0
#define GA_L 8192
#define GB_H 16384
#define GB_L 24576
#define GBUF 32768
#define GEMM_SMEM3 (3*GBUF)
#define G1_B 8192
#define G1BUF 16384
#define GEMM_SMEM1 (3*G1BUF)

template<int SPLIT, int OUT>
__global__ __launch_bounds__(256, 2) void gemm_bf16_kernel(
    const __nv_bfloat16* __restrict__ Ah, const __nv_bfloat16* __restrict__ Al,
    const __nv_bfloat16* __restrict__ Bh, const __nv_bfloat16* __restrict__ Bl,
    const float* __restrict__ bias, float* __restrict__ C,
    __nv_bfloat16* __restrict__ Ch, __nv_bfloat16* __restrict__ Cl,
    int M, int N, int K)
{
    extern __shared__ char smem[];
    const uint32_t sbase = smem_u32(smem);
    const int tid  = threadIdx.x;
    const int wid  = tid >> 5;
    const int lane = tid & 31;
    const int m0 = blockIdx.y * 128;
    const int n0 = blockIdx.x * 128;
    const int wm = (wid & 1) * 64;
    const int wn = (wid >> 1) * 32;

    const uint32_t BUFSTRIDE = (SPLIT == 3) ? GBUF : G1BUF;
    const uint32_t OFFB      = (SPLIT == 3) ? GB_H : G1_B;

    float c[4][4][4];
    #pragma unroll
    for (int mt = 0; mt < 4; ++mt)
        #pragma unroll
        for (int no = 0; no < 4; ++no)
            #pragma unroll
            for (int e = 0; e < 4; ++e) c[mt][no][e] = 0.f;

    const int j0 = tid * 2;
    auto issue = [&](int t) {
        uint32_t sb = sbase + (uint32_t)(t % 3) * BUFSTRIDE;
        #pragma unroll
        for (int i = 0; i < 2; ++i) {
            int j = j0 + i;
            int r = j >> 2;
            int cch = j & 3;
            uint32_t sw = (uint32_t)r * 64 + (uint32_t)((cch ^ (r & 3)) << 4);
            size_t ga = (size_t)(m0 + r) * K + t * 32 + cch * 8;
            size_t gb = (size_t)(n0 + r) * K + t * 32 + cch * 8;
            cpasync16(sb + GA_H + sw, Ah + ga);
            cpasync16(sb + OFFB + sw, Bh + gb);
            if (SPLIT == 3) {
                cpasync16(sb + GA_L + sw, Al + ga);
                cpasync16(sb + GB_L + sw, Bl + gb);
            }
        }
        asm volatile("cp.async.commit_group;" ::: "memory");
    };

    const uint32_t a_lrow = (uint32_t)(lane & 15);
    const uint32_t a_cc   = (uint32_t)(lane >> 4);
    const uint32_t b_lrow = (uint32_t)((lane >> 4) * 8 + (lane & 7));
    const uint32_t b_cc   = (uint32_t)((lane >> 3) & 1);

    const int NT = K / 32;
    issue(0);
    issue(1);

    for (int t = 0; t < NT; ++t) {
        if (t + 1 < NT)
            asm volatile("cp.async.wait_group 1;" ::: "memory");
        else
            asm volatile("cp.async.wait_group 0;" ::: "memory");
        __syncthreads();
        if (t + 2 < NT) issue(t + 2);

        const uint32_t bb = sbase + (uint32_t)(t % 3) * BUFSTRIDE;

        #pragma unroll
        for (int ks = 0; ks < 2; ++ks) {
            uint32_t af[4][4];
            #pragma unroll
            for (int mt = 0; mt < 4; ++mt) {
                uint32_t row = (uint32_t)(wm + mt * 16) + a_lrow;
                uint32_t cch = (uint32_t)(ks * 2) + a_cc;
                ldm_x4(af[mt], bb + GA_H + row * 64 + ((cch ^ (row & 3)) << 4));
            }
            uint32_t bh[4][2], bl[4][2];
            #pragma unroll
            for (int half = 0; half < 2; ++half) {
                uint32_t r[4];
                uint32_t nrow = (uint32_t)(wn + half * 16) + b_lrow;
                uint32_t cch = (uint32_t)(ks * 2) + b_cc;
                uint32_t sw = nrow * 64 + ((cch ^ (nrow & 3)) << 4);
                ldm_x4(r, bb + OFFB + sw);
                bh[half * 2][0] = r[0]; bh[half * 2][1] = r[1];
                bh[half * 2 + 1][0] = r[2]; bh[half * 2 + 1][1] = r[3];
                if (SPLIT == 3) {
                    ldm_x4(r, bb + GB_L + sw);
                    bl[half * 2][0] = r[0]; bl[half * 2][1] = r[1];
                    bl[half * 2 + 1][0] = r[2]; bl[half * 2 + 1][1] = r[3];
                }
            }

            #pragma unroll
            for (int mt = 0; mt < 4; ++mt)
                #pragma unroll
                for (int no = 0; no < 4; ++no)
                    mma_bf16(c[mt][no], af[mt], bh[no]);

            if (SPLIT == 3) {
                #pragma unroll
                for (int mt = 0; mt < 4; ++mt)
                    #pragma unroll
                    for (int no = 0; no < 4; ++no)
                        mma_bf16(c[mt][no], af[mt], bl[no]);
                #pragma unroll
                for (int mt = 0; mt < 4; ++mt) {
                    uint32_t row = (uint32_t)(wm + mt * 16) + a_lrow;
                    uint32_t cch = (uint32_t)(ks * 2) + a_cc;
                    ldm_x4(af[mt], bb + GA_L + row * 64 + ((cch ^ (row & 3)) << 4));
                }
                #pragma unroll
                for (int mt = 0; mt < 4; ++mt)
                    #pragma unroll
                    for (int no = 0; no < 4; ++no)
                        mma_bf16(c[mt][no], af[mt], bh[no]);
            }
        }
    }

    const int erow = lane >> 2;
    const int ecol = (lane & 3) * 2;
    #pragma unroll
    for (int mt = 0; mt < 4; ++mt) {
        int r0 = m0 + wm + mt * 16 + erow;
        #pragma unroll
        for (int no = 0; no < 4; ++no) {
            int col = n0 + wn + no * 8 + ecol;
            float2 bv = *(const float2*)(bias + col);
            float o0 = c[mt][no][0] + bv.x;
            float o1 = c[mt][no][1] + bv.y;
            float o2 = c[mt][no][2] + bv.x;
            float o3 = c[mt][no][3] + bv.y;
            if (OUT == 0) {
                float2 o;
                o.x = o0; o.y = o1;
                *(float2*)(C + (size_t)r0 * N + col) = o;
                o.x = o2; o.y = o3;
                *(float2*)(C + (size_t)(r0 + 8) * N + col) = o;
            } else if (OUT == 1) {
                *(uint32_t*)(Ch + (size_t)r0 * N + col) = bfpack(o0, o1);
                *(uint32_t*)(Ch + (size_t)(r0 + 8) * N + col) = bfpack(o2, o3);
            } else {
                uint32_t hi, lo;
                split2(o0, o1, hi, lo);
                *(uint32_t*)(Ch + (size_t)r0 * N + col) = hi;
                *(uint32_t*)(Cl + (size_t)r0 * N + col) = lo;
                split2(o2, o3, hi, lo);
                *(uint32_t*)(Ch + (size_t)(r0 + 8) * N + col) = hi;
                *(uint32_t*)(Cl + (size_t)(r0 + 8) * N + col) = lo;
            }
        }
    }
}

// ---------------------------------------------------------------------------
// Fused attention: one CTA per (pair, 128-row q-strip).
// Phase 1: loop k-tiles, S = Q@K^T (bf16), e = mask?exp(s/D):0 -> attn
//          (unnormalized), rowsum in CTA-local smem (no global atomics).
// Phase 2: re-read own e strip (L2-hot), normalize + write back, AV MMA
//          (P hi/lo x V hi/lo, 3-MMA), ctx out as bf16 hi/lo.
// ---------------------------------------------------------------------------
#define FK_Q 0
#define FK_K 16384
#define FUSED_SMEM 65536
// phase 2 overlay (after full drain + barrier)
#define P2_PH 0
#define P2_PL 10240
#define P2_VH 20480
#define P2_VL 24576
#define P2_BUF 28672
#define PROWB 80

__global__ __launch_bounds__(256, 2) void attn_fused_kernel(
    const __nv_bfloat16* __restrict__ qhb, const __nv_bfloat16* __restrict__ khb,
    const int* __restrict__ mask,
    const __nv_bfloat16* __restrict__ vhh, const __nv_bfloat16* __restrict__ vhl,
    float* __restrict__ attn,
    __nv_bfloat16* __restrict__ ctx_h, __nv_bfloat16* __restrict__ ctx_l)
{
    extern __shared__ char smem[];
    __shared__ float srow[128];
    const uint32_t sbase = smem_u32(smem);
    const int tid = threadIdx.x;
    const int wid = tid >> 5;
    const int lane = tid & 31;
    const int p = blockIdx.y;
    const int b = p / HH;
    const int h = p % HH;
    const int q0 = blockIdx.x * 128;

    if (tid < 128) srow[tid] = 0.f;

    // Q tile once (group 0)
    {
        const __nv_bfloat16* Qg = qhb + (size_t)(b * LL + q0) * DD + h * DKK;
        #pragma unroll
        for (int i = 0; i < 4; ++i) {
            int j = tid * 4 + i;
            int r = j >> 3;
            int cch = j & 7;
            uint32_t sw = (uint32_t)r * 128 + (uint32_t)((cch ^ (r & 7)) << 4);
            cpasync16(sbase + FK_Q + sw, Qg + (size_t)r * DD + cch * 8);
        }
        asm volatile("cp.async.commit_group;" ::: "memory");
    }
    auto issueK = [&](int t) {
        uint32_t sb = sbase + FK_K + (uint32_t)(t % 3) * 16384;
        const __nv_bfloat16* Kg = khb + (size_t)(b * LL + t * 128) * DD + h * DKK;
        #pragma unroll
        for (int i = 0; i < 4; ++i) {
            int j = tid * 4 + i;
            int r = j >> 3;
            int cch = j & 7;
            uint32_t sw = (uint32_t)r * 128 + (uint32_t)((cch ^ (r & 7)) << 4);
            cpasync16(sb + sw, Kg + (size_t)r * DD + cch * 8);
        }
        asm volatile("cp.async.commit_group;" ::: "memory");
    };
    issueK(0);
    issueK(1);

    const int wm = (wid & 1) * 64;
    const int wn = (wid >> 1) * 32;
    const uint32_t a_lrow = (uint32_t)(lane & 15);
    const uint32_t a_cc   = (uint32_t)(lane >> 4);
    const uint32_t b_lrow = (uint32_t)((lane >> 4) * 8 + (lane & 7));
    const uint32_t b_cc   = (uint32_t)((lane >> 3) & 1);
    const int erow = lane >> 2;
    const int ecol = (lane & 3) * 2;
    const float scale = 1.0f / (float)DD;
    const size_t obase = (size_t)(h * BB + b) * LL * LL;

    const int NKT = LL / 128;  // 16

    for (int kt = 0; kt < NKT; ++kt) {
        if (kt + 1 < NKT)
            asm volatile("cp.async.wait_group 1;" ::: "memory");
        else
            asm volatile("cp.async.wait_group 0;" ::: "memory");
        __syncthreads();
        if (kt + 2 < NKT) issueK(kt + 2);

        const uint32_t kb = sbase + FK_K + (uint32_t)(kt % 3) * 16384;

        float c[4][4][4];
        #pragma unroll
        for (int mt = 0; mt < 4; ++mt)
            #pragma unroll
            for (int no = 0; no < 4; ++no)
                #pragma unroll
                for (int e = 0; e < 4; ++e) c[mt][no][e] = 0.f;

        #pragma unroll
        for (int ks = 0; ks < 4; ++ks) {
            uint32_t af[4][4];
            #pragma unroll
            for (int mt = 0; mt < 4; ++mt) {
                uint32_t row = (uint32_t)(wm + mt * 16) + a_lrow;
                uint32_t cch = (uint32_t)(ks * 2) + a_cc;
                ldm_x4(af[mt], sbase + FK_Q + row * 128 + ((cch ^ (row & 7)) << 4));
            }
            uint32_t bh[4][2];
            #pragma unroll
            for (int half = 0; half < 2; ++half) {
                uint32_t r[4];
                uint32_t nrow = (uint32_t)(wn + half * 16) + b_lrow;
                uint32_t cch = (uint32_t)(ks * 2) + b_cc;
                ldm_x4(r, kb + nrow * 128 + ((cch ^ (nrow & 7)) << 4));
                bh[half * 2][0] = r[0]; bh[half * 2][1] = r[1];
                bh[half * 2 + 1][0] = r[2]; bh[half * 2 + 1][1] = r[3];
            }
            #pragma unroll
            for (int mt = 0; mt < 4; ++mt)
                #pragma unroll
                for (int no = 0; no < 4; ++no)
                    mma_bf16(c[mt][no], af[mt], bh[no]);
        }

        // epilogue: mask + exp + write e + smem rowsum
        const int k0 = kt * 128;
        #pragma unroll
        for (int mt = 0; mt < 4; ++mt) {
            #pragma unroll
            for (int r2 = 0; r2 < 2; ++r2) {
                int row = wm + mt * 16 + erow + r2 * 8;
                int q = q0 + row;
                const int* mbase = mask + ((size_t)b * LL + q) * LL;
                float* orow = attn + obase + (size_t)q * LL;
                float rsum = 0.f;
                #pragma unroll
                for (int no = 0; no < 4; ++no) {
                    int col = k0 + wn + no * 8 + ecol;
                    int2 m = *(const int2*)(mbase + col);
                    float e0 = m.x ? __expf(c[mt][no][r2 * 2 + 0] * scale) : 0.f;
                    float e1 = m.y ? __expf(c[mt][no][r2 * 2 + 1] * scale) : 0.f;
                    float2 o; o.x = e0; o.y = e1;
                    *(float2*)(orow + col) = o;
                    rsum += e0 + e1;
                }
                rsum += __shfl_xor_sync(0xffffffffu, rsum, 1);
                rsum += __shfl_xor_sync(0xffffffffu, rsum, 2);
                if ((lane & 3) == 0) atomicAdd(&srow[row], rsum);
            }
        }
    }

    // phase boundary
    asm volatile("cp.async.wait_group 0;" ::: "memory");
    __syncthreads();

    // ---------------- Phase 2: normalize + AV ----------------
    float* Pb = attn + obase + (size_t)q0 * LL;
    const __nv_bfloat16* Vh = vhh + (size_t)b * LL * DD + h * DKK;
    const __nv_bfloat16* Vl = vhl + (size_t)b * LL * DD + h * DKK;

    const int prow = tid >> 1;
    const int pcseg = (tid & 1) * 16;
    const float inv_r = 1.0f / srow[prow];
    const int v_r = tid >> 3;
    const int v_c = tid & 7;

    float rp[16];

    auto issueV = [&](int t) {
        uint32_t sb = sbase + (uint32_t)(t & 1) * P2_BUF;
        uint32_t sw = (uint32_t)v_r * 128 + (uint32_t)((v_c ^ (v_r & 7)) << 4);
        size_t g = (size_t)(t * 32 + v_r) * DD + v_c * 8;
        cpasync16(sb + P2_VH + sw, Vh + g);
        cpasync16(sb + P2_VL + sw, Vl + g);
        asm volatile("cp.async.commit_group;" ::: "memory");
    };
    auto g_loadP = [&](int t) {
        float* Pp = Pb + (size_t)prow * LL + t * 32 + pcseg;
        #pragma unroll
        for (int i = 0; i < 4; ++i) {
            float4 v = *(const float4*)(Pp + 4 * i);
            v.x *= inv_r; v.y *= inv_r; v.z *= inv_r; v.w *= inv_r;
            *(float4*)(rp + 4 * i) = v;
            *(float4*)(Pp + 4 * i) = v;
        }
    };
    auto s_storeP = [&](int buf) {
        char* base = smem + buf * P2_BUF;
        uint32_t po = (uint32_t)prow * PROWB + (uint32_t)pcseg * 2;
        #pragma unroll
        for (int i = 0; i < 8; ++i) {
            uint32_t hi, lo;
            split2(rp[2 * i], rp[2 * i + 1], hi, lo);
            *(uint32_t*)(base + P2_PH + po + 4 * i) = hi;
            *(uint32_t*)(base + P2_PL + po + 4 * i) = lo;
        }
    };

    const int wm2 = (wid & 3) * 32;
    const int wn2 = (wid >> 2) * 32;

    float c2[2][4][4];
    #pragma unroll
    for (int mt = 0; mt < 2; ++mt)
        #pragma unroll
        for (int no = 0; no < 4; ++no)
            #pragma unroll
            for (int e = 0; e < 4; ++e) c2[mt][no][e] = 0.f;

    const uint32_t a2_lrow = (uint32_t)(lane & 15);
    const uint32_t a2_koff = (uint32_t)(lane >> 4) * 8;
    const int vm = lane >> 3;
    const int v_krow_off = (vm & 1) * 8 + (lane & 7);
    const int v_nc_off = (vm >> 1);

    const int NT2 = LL / 32;
    issueV(0);
    g_loadP(0);
    s_storeP(0);

    for (int t = 0; t < NT2; ++t) {
        asm volatile("cp.async.wait_group 0;" ::: "memory");
        __syncthreads();
        const uint32_t bb = sbase + (uint32_t)(t & 1) * P2_BUF;
        if (t + 1 < NT2) {
            issueV(t + 1);
            g_loadP(t + 1);
        }

        #pragma unroll
        for (int ks = 0; ks < 2; ++ks) {
            const uint32_t kbyte = (uint32_t)(ks * 16 + a2_koff) * 2;
            uint32_t af[2][4];
            #pragma unroll
            for (int mt = 0; mt < 2; ++mt)
                ldm_x4(af[mt], bb + P2_PH +
                       (uint32_t)(wm2 + mt * 16 + a2_lrow) * PROWB + kbyte);

            uint32_t bhf[4][2], blf[4][2];
            #pragma unroll
            for (int half = 0; half < 2; ++half) {
                uint32_t r[4];
                uint32_t k_row = (uint32_t)(ks * 16 + v_krow_off);
                uint32_t cch = (uint32_t)((wn2 + half * 16) >> 3) + v_nc_off;
                uint32_t sw = k_row * 128 + ((cch ^ (k_row & 7)) << 4);
                ldm_x4_t(r, bb + P2_VH + sw);
                bhf[half * 2][0] = r[0]; bhf[half * 2][1] = r[1];
                bhf[half * 2 + 1][0] = r[2]; bhf[half * 2 + 1][1] = r[3];
                ldm_x4_t(r, bb + P2_VL + sw);
                blf[half * 2][0] = r[0]; blf[half * 2][1] = r[1];
                blf[half * 2 + 1][0] = r[2]; blf[half * 2 + 1][1] = r[3];
            }

            #pragma unroll
            for (int mt = 0; mt < 2; ++mt)
                #pragma unroll
                for (int no = 0; no < 4; ++no)
                    mma_bf16(c2[mt][no], af[mt], bhf[no]);
            #pragma unroll
            for (int mt = 0; mt < 2; ++mt)
                #pragma unroll
                for (int no = 0; no < 4; ++no)
                    mma_bf16(c2[mt][no], af[mt], blf[no]);

            #pragma unroll
            for (int mt = 0; mt < 2; ++mt)
                ldm_x4(af[mt], bb + P2_PL +
                       (uint32_t)(wm2 + mt * 16 + a2_lrow) * PROWB + kbyte);
            #pragma unroll
            for (int mt = 0; mt < 2; ++mt)
                #pragma unroll
                for (int no = 0; no < 4; ++no)
                    mma_bf16(c2[mt][no], af[mt], bhf[no]);
        }
        if (t + 1 < NT2) s_storeP((t + 1) & 1);
    }

    // ctx epilogue (bf16 hi/lo)
    #pragma unroll
    for (int mt = 0; mt < 2; ++mt) {
        #pragma unroll
        for (int r2 = 0; r2 < 2; ++r2) {
            int row = wm2 + mt * 16 + erow + r2 * 8;
            int q = q0 + row;
            size_t base = ((size_t)b * LL + q) * DD + h * DKK;
            #pragma unroll
            for (int no = 0; no < 4; ++no) {
                int col = wn2 + no * 8 + ecol;
                uint32_t hi, lo;
                split2(c2[mt][no][r2 * 2 + 0], c2[mt][no][r2 * 2 + 1], hi, lo);
                *(uint32_t*)(ctx_h + base + col) = hi;
                *(uint32_t*)(ctx_l + base + col) = lo;
            }
        }
    }
}

// ---------------------------------------------------------------------------
extern "C" void kernel_launch(void* const* d_in, const int* in_sizes, int n_in,
                              void* d_out, int out_size)
{
    const float* q    = (const float*)d_in[0];
    const float* k    = (const float*)d_in[1];
    const float* v    = (const float*)d_in[2];
    const int*   mask = (const int*)d_in[3];
    const float* Wq   = (const float*)d_in[4];
    const float* bq   = (const float*)d_in[5];
    const float* Wk   = (const float*)d_in[6];
    const float* bk   = (const float*)d_in[7];
    const float* Wv   = (const float*)d_in[8];
    const float* bv   = (const float*)d_in[9];
    const float* Wo   = (const float*)d_in[10];
    const float* bo   = (const float*)d_in[11];

    float* out  = (float*)d_out;
    float* attn = out + (size_t)BB * LL * DD;

    __nv_bfloat16 *ah, *al, *bh, *bl, *qhb, *khb, *vhh, *vhl;
    cudaGetSymbolAddress((void**)&ah, g_ah);
    cudaGetSymbolAddress((void**)&al, g_al);
    cudaGetSymbolAddress((void**)&bh, g_bh);
    cudaGetSymbolAddress((void**)&bl, g_bl);
    cudaGetSymbolAddress((void**)&qhb, g_qhb);
    cudaGetSymbolAddress((void**)&khb, g_khb);
    cudaGetSymbolAddress((void**)&vhh, g_vhh);
    cudaGetSymbolAddress((void**)&vhl, g_vhl);

    const int M = BB * LL;  // 4096
    const int n4 = M * DD / 4;

    static int smem_set = 0;
    if (!smem_set) {
        cudaFuncSetAttribute(gemm_bf16_kernel<1,1>,
                             cudaFuncAttributeMaxDynamicSharedMemorySize, GEMM_SMEM1);
        cudaFuncSetAttribute(gemm_bf16_kernel<3,2>,
                             cudaFuncAttributeMaxDynamicSharedMemorySize, GEMM_SMEM3);
        cudaFuncSetAttribute(gemm_bf16_kernel<3,0>,
                             cudaFuncAttributeMaxDynamicSharedMemorySize, GEMM_SMEM3);
        cudaFuncSetAttribute(attn_fused_kernel,
                             cudaFuncAttributeMaxDynamicSharedMemorySize, FUSED_SMEM);
        smem_set = 1;
    }

    dim3 gproj(DD / 128, M / 128);
    dim3 gwt(DD / 32, DD / 32);
    const int cga = (n4 + 255) / 256;

    // Q projection -> bf16
    conv_wt_kernel<1><<<gwt, 256>>>(Wq, bh, bl, DD, DD);
    conv_a_h_kernel<<<cga, 256>>>(q, ah, n4);
    gemm_bf16_kernel<1,1><<<gproj, 256, GEMM_SMEM1>>>(ah, al, bh, bl, bq,
                                                      nullptr, qhb, nullptr, M, DD, DD);
    // K projection -> bf16
    conv_wt_kernel<1><<<gwt, 256>>>(Wk, bh, bl, DD, DD);
    conv_a_h_kernel<<<cga, 256>>>(k, ah, n4);
    gemm_bf16_kernel<1,1><<<gproj, 256, GEMM_SMEM1>>>(ah, al, bh, bl, bk,
                                                      nullptr, khb, nullptr, M, DD, DD);
    // V projection -> bf16 hi/lo
    conv_wt_kernel<3><<<gwt, 256>>>(Wv, bh, bl, DD, DD);
    conv_a_kernel<<<cga, 256>>>(v, ah, al, n4);
    gemm_bf16_kernel<3,2><<<gproj, 256, GEMM_SMEM3>>>(ah, al, bh, bl, bv,
                                                      nullptr, vhh, vhl, M, DD, DD);

    // Fused scores + softmax + AV
    dim3 gf(LL / 128, NP);  // (16, 32)
    attn_fused_kernel<<<gf, 256, FUSED_SMEM>>>(qhb, khb, mask, vhh, vhl,
                                               attn, ah, al);

    // Output projection (ctx bf16 hi/lo in ah/al)
    conv_wt_kernel<3><<<gwt, 256>>>(Wo, bh, bl, DD, DD);
    gemm_bf16_kernel<3,0><<<gproj, 256, GEMM_SMEM3>>>(ah, al, bh, bl, bo,
                                                      out, nullptr, nullptr, M, DD, DD);
}